// round 2
// baseline (speedup 1.0000x reference)
#include <cuda_runtime.h>
#include <cuda_bf16.h>
#include <math.h>

// ---------------- problem constants ----------------
#define Vv 32000
#define Ee 512
#define Ff 2048
#define Dd 256
#define Nn 2048
#define Ll 2
#define Bb 8
#define Tt 256
#define HM 4
#define TOPK 8
#define HA 8
#define HD 64   // Dd/HM
#define DH 64   // Ee/HA
#define IFc 1028 // 4*Dd + HM
#define Mrows (Bb*Tt)  // 2048

// ---------------- scratch (static device memory; no allocs allowed) ----------------
__device__ float g_x[Mrows*Ee];
__device__ float g_h[Mrows*Ee];
__device__ float g_q[Mrows*Ee];
__device__ float g_k[Mrows*Ee];
__device__ float g_v[Mrows*Ee];
__device__ float g_attno[Mrows*Ee];
__device__ float g_hf[Mrows*Ee];
__device__ float g_ffn[Mrows*Ff];
__device__ float g_iface[Mrows*IFc];
__device__ float g_mem[Bb*Nn*Dd];
__device__ float g_sumsq[Bb*Nn*HM];
__device__ float g_rvhist[Mrows*Dd];
__device__ float g_rv[Bb*Dd];
__device__ float g_i[Bb*IFc];
__device__ float g_keys[Bb*2*HM*HD];
__device__ float g_sim[2*Bb*HM*Nn];

// ---------------- embedding ----------------
__global__ void k_embed(const int* __restrict__ seq, const float* __restrict__ emb,
                        const float* __restrict__ pos) {
    int stride = gridDim.x * blockDim.x;
    for (int idx = blockIdx.x*blockDim.x + threadIdx.x; idx < Mrows*Ee; idx += stride) {
        int e  = idx % Ee;
        int bt = idx / Ee;
        int t  = bt % Tt;
        g_x[idx] = emb[(size_t)seq[bt]*Ee + e] + pos[t*Ee + e];
    }
}

// ---------------- layernorm (row = one block, E=512, 256 threads) ----------------
__global__ void k_ln(const float* __restrict__ in, float* __restrict__ outp,
                     const float* __restrict__ g, const float* __restrict__ b) {
    int row = blockIdx.x;
    int tid = threadIdx.x;
    const float* x = in + (size_t)row*Ee;
    __shared__ float red[256];
    float v0 = x[tid], v1 = x[tid+256];
    red[tid] = v0 + v1;
    __syncthreads();
    for (int s = 128; s > 0; s >>= 1) { if (tid < s) red[tid] += red[tid+s]; __syncthreads(); }
    float mean = red[0] * (1.f/Ee);
    __syncthreads();
    float d0 = v0 - mean, d1 = v1 - mean;
    red[tid] = d0*d0 + d1*d1;
    __syncthreads();
    for (int s = 128; s > 0; s >>= 1) { if (tid < s) red[tid] += red[tid+s]; __syncthreads(); }
    float inv = rsqrtf(red[0] * (1.f/Ee) + 1e-5f);
    outp[(size_t)row*Ee + tid]       = d0*inv*g[tid]     + b[tid];
    outp[(size_t)row*Ee + tid + 256] = d1*inv*g[tid+256] + b[tid+256];
}

// ---------------- GEMM: C = A(MxK) @ W(KxNc) [+bias] [gelu] [+res] ----------------
// BM=BN=128, BK=8, 256 threads, 8x8 register tile. K%8==0, M%128==0 guaranteed.
__global__ void k_gemm(const float* __restrict__ A, const float* __restrict__ W,
                       const float* __restrict__ bias, const float* __restrict__ res,
                       float* __restrict__ C, int M, int K, int Nc, int act) {
    __shared__ float As[8][128];
    __shared__ float Bs[8][128];
    int bm = blockIdx.y * 128, bn = blockIdx.x * 128;
    int tid = threadIdx.x;
    int tx = tid % 16, ty = tid / 16;
    float acc[8][8];
#pragma unroll
    for (int i = 0; i < 8; i++)
#pragma unroll
        for (int j = 0; j < 8; j++) acc[i][j] = 0.f;

    int arow = tid >> 1;            // 0..127
    int acol = (tid & 1) * 4;       // 0 or 4
    int brow = tid >> 5;            // 0..7
    int bcol = (tid & 31) * 4;      // 0..124

    for (int k0 = 0; k0 < K; k0 += 8) {
        float4 av = *(const float4*)&A[(size_t)(bm + arow)*K + k0 + acol];
        As[acol+0][arow] = av.x; As[acol+1][arow] = av.y;
        As[acol+2][arow] = av.z; As[acol+3][arow] = av.w;
        float4 bv;
        if (bn + bcol + 4 <= Nc) bv = *(const float4*)&W[(size_t)(k0 + brow)*Nc + bn + bcol];
        else { bv.x = bv.y = bv.z = bv.w = 0.f; }
        *(float4*)&Bs[brow][bcol] = bv;
        __syncthreads();
#pragma unroll
        for (int kk = 0; kk < 8; kk++) {
            float4 a0 = *(const float4*)&As[kk][ty*8];
            float4 a1 = *(const float4*)&As[kk][ty*8+4];
            float4 b0 = *(const float4*)&Bs[kk][tx*8];
            float4 b1 = *(const float4*)&Bs[kk][tx*8+4];
            float ar[8] = {a0.x,a0.y,a0.z,a0.w,a1.x,a1.y,a1.z,a1.w};
            float br[8] = {b0.x,b0.y,b0.z,b0.w,b1.x,b1.y,b1.z,b1.w};
#pragma unroll
            for (int i = 0; i < 8; i++)
#pragma unroll
                for (int j = 0; j < 8; j++) acc[i][j] += ar[i]*br[j];
        }
        __syncthreads();
    }
#pragma unroll
    for (int i = 0; i < 8; i++) {
        int row = bm + ty*8 + i;
#pragma unroll
        for (int j = 0; j < 8; j++) {
            int col = bn + tx*8 + j;
            if (col < Nc) {
                float v = acc[i][j];
                if (bias) v += bias[col];
                if (act == 1) { // tanh-gelu (JAX default approximate=True)
                    float xx = v;
                    float tt = tanhf(0.7978845608028654f * (xx + 0.044715f*xx*xx*xx));
                    v = 0.5f * xx * (1.f + tt);
                }
                if (res) v += res[(size_t)row*Nc + col];
                C[(size_t)row*Nc + col] = v;
            }
        }
    }
}

// ---------------- attention: one block per (b,h,t) ----------------
__global__ void k_attn() {
    int t = blockIdx.x, hh = blockIdx.y, b = blockIdx.z;
    int tid = threadIdx.x;
    __shared__ float sq[64];
    __shared__ float ss[256];
    __shared__ float red[256];
    const float* qrow = g_q + ((size_t)(b*Tt + t))*Ee + hh*DH;
    if (tid < 64) sq[tid] = qrow[tid];
    __syncthreads();
    float lmax = -3.4e38f;
    for (int j = tid; j <= t; j += 256) {
        const float* krow = g_k + ((size_t)(b*Tt + j))*Ee + hh*DH;
        float d = 0.f;
#pragma unroll
        for (int e = 0; e < 64; e++) d += sq[e]*krow[e];
        d *= 0.125f; // 1/sqrt(64)
        ss[j] = d;
        lmax = fmaxf(lmax, d);
    }
    red[tid] = lmax;
    __syncthreads();
    for (int s = 128; s > 0; s >>= 1) { if (tid < s) red[tid] = fmaxf(red[tid], red[tid+s]); __syncthreads(); }
    float mx = red[0];
    __syncthreads();
    float lsum = 0.f;
    for (int j = tid; j <= t; j += 256) { float p = expf(ss[j]-mx); ss[j] = p; lsum += p; }
    red[tid] = lsum;
    __syncthreads();
    for (int s = 128; s > 0; s >>= 1) { if (tid < s) red[tid] += red[tid+s]; __syncthreads(); }
    float inv = 1.f / red[0];
    __syncthreads();
    if (tid < 64) {
        float acc = 0.f;
        for (int j = 0; j <= t; j++)
            acc += ss[j] * g_v[((size_t)(b*Tt + j))*Ee + hh*DH + tid];
        g_attno[((size_t)(b*Tt + t))*Ee + hh*DH + tid] = acc * inv;
    }
}

// ---------------- scan init: broadcast mem, compute sumsq, zero rv ----------------
__global__ void k_scan_init(const float* __restrict__ mem_init) {
    int stride = gridDim.x*blockDim.x;
    int tid0 = blockIdx.x*blockDim.x + threadIdx.x;
    for (int idx = tid0; idx < Bb*Nn*Dd; idx += stride)
        g_mem[idx] = mem_init[idx % (Nn*Dd)];
    for (int idx = tid0; idx < Bb*Nn*HM; idx += stride) {
        int h = idx % HM;
        int n = (idx / HM) % Nn;
        const float* r = mem_init + (size_t)n*Dd + h*HD;
        float s = 0.f;
#pragma unroll
        for (int d = 0; d < HD; d++) s += r[d]*r[d];
        g_sumsq[idx] = s;
    }
    for (int idx = tid0; idx < Bb*Dd; idx += stride) g_rv[idx] = 0.f;
}

// ---------------- per-step: i = iface[t] + rv @ W_if_r + b_if; normalize keys; record rv hist ----
// grid (17, B), 64 threads
__global__ void k_iface(const float* __restrict__ iface, const float* __restrict__ W_if_r,
                        const float* __restrict__ b_if, int t) {
    int chunk = blockIdx.x, b = blockIdx.y;
    int lane = threadIdx.x;
    int col = chunk*64 + lane;
    __shared__ float srv[Dd];
    // load rv to shared
    for (int d = lane; d < Dd; d += 64) srv[d] = g_rv[b*Dd + d];
    __syncthreads();
    float acc = 0.f;
    if (col < IFc) {
        acc = iface[((size_t)(b*Tt + t))*IFc + col] + b_if[col];
#pragma unroll 4
        for (int d = 0; d < Dd; d++) acc += srv[d] * W_if_r[(size_t)d*IFc + col];
        g_i[b*IFc + col] = acc;
    }
    if (chunk < 8) { // key chunks: 0..3 read key heads, 4..7 write key heads
        __shared__ float sv[64];
        sv[lane] = acc*acc;
        __syncthreads();
        for (int s = 32; s > 0; s >>= 1) { if (lane < s) sv[lane] += sv[lane+s]; __syncthreads(); }
        float inv = rsqrtf(sv[0] + 1e-8f);
        int rw = (chunk >> 2);
        int head = chunk & 3;
        g_keys[((b*2 + rw)*HM + head)*HD + lane] = acc * inv;
    }
    if (chunk < 4) { // rv history = carry rv at step t
        g_rvhist[((size_t)(b*Tt + t))*Dd + col] = srv[col];
    }
}

// ---------------- per-step: sim[b,h,n] for read & write keys. grid (8 nchunks, 32 bh) ----
__global__ void k_sim() {
    int bh = blockIdx.y;
    int b = bh / HM, h = bh % HM;
    int chunk = blockIdx.x;
    int tid = threadIdx.x;
    __shared__ float kr[64], kw[64];
    if (tid < 64)        kr[tid]    = g_keys[((b*2 + 0)*HM + h)*HD + tid];
    else if (tid < 128)  kw[tid-64] = g_keys[((b*2 + 1)*HM + h)*HD + tid - 64];
    __syncthreads();
    int warp = tid >> 5, lane = tid & 31;
    int n0 = chunk*256 + warp*32;
    for (int n = n0; n < n0 + 32; n++) {
        const float* mrow = g_mem + ((size_t)(b*Nn + n))*Dd + h*HD;
        float m0 = mrow[lane], m1 = mrow[lane + 32];
        float dr = m0*kr[lane] + m1*kr[lane+32];
        float dw = m0*kw[lane] + m1*kw[lane+32];
        for (int s = 16; s > 0; s >>= 1) {
            dr += __shfl_down_sync(0xffffffffu, dr, s);
            dw += __shfl_down_sync(0xffffffffu, dw, s);
        }
        if (lane == 0) {
            float inv = rsqrtf(g_sumsq[(b*Nn + n)*HM + h] + 1e-8f);
            g_sim[(size_t)bh*Nn + n]               = dr * inv;
            g_sim[(size_t)(Bb*HM + bh)*Nn + n]     = dw * inv;
        }
    }
}

__device__ __forceinline__ float sigmoidf_(float x) { return 1.f/(1.f + expf(-x)); }

// ---------------- per-step: topk+softmax (read&write), rv gather, sparse mem update ----
// grid 32 (=B*HM) blocks, 256 threads
__global__ void k_step(const float* __restrict__ beta_read_p, const float* __restrict__ beta_write_p) {
    int bh = blockIdx.x;
    int b = bh / HM, h = bh % HM;
    int tid = threadIdx.x;
    __shared__ float ssim[Nn];
    __shared__ float rmax[256]; __shared__ int rmaxi[256];
    __shared__ float topv[TOPK]; __shared__ int topi[TOPK];
    __shared__ int listn;
    __shared__ float lw[40]; __shared__ int li[40];
    __shared__ float ssum;
    __shared__ float red64[64];

    for (int rw = 0; rw < 2; rw++) {
        float beta = (rw == 0) ? *beta_read_p : *beta_write_p;
        beta = log1pf(expf(beta));
        beta = fminf(fmaxf(beta, 1.f), 20.f);
        const float* simsrc = g_sim + ((size_t)(rw*Bb*HM + bh))*Nn;
        for (int n = tid; n < Nn; n += 256) ssim[n] = simsrc[n];
        if (tid == 0) listn = 0;
        __syncthreads();
        // iterative top-8
        for (int k = 0; k < TOPK; k++) {
            float bv = -3.4e38f; int bi = 0;
            for (int n = tid; n < Nn; n += 256) if (ssim[n] > bv) { bv = ssim[n]; bi = n; }
            rmax[tid] = bv; rmaxi[tid] = bi;
            __syncthreads();
            for (int s = 128; s > 0; s >>= 1) {
                if (tid < s && rmax[tid+s] > rmax[tid]) { rmax[tid] = rmax[tid+s]; rmaxi[tid] = rmaxi[tid+s]; }
                __syncthreads();
            }
            if (tid == 0) { topv[k] = rmax[0]; topi[k] = rmaxi[0]; ssim[rmaxi[0]] = -3.4e38f; }
            __syncthreads();
        }
        float smax = topv[0], kth = topv[TOPK-1];
        // build survivor list (top-8 plus exact ties with kth)
        if (tid < TOPK) {
            int p = atomicAdd(&listn, 1);
            if (p < 40) { li[p] = topi[tid]; lw[p] = expf(beta*(topv[tid]-smax)); }
        }
        for (int n = tid; n < Nn; n += 256) {
            if (ssim[n] >= kth) {
                int p = atomicAdd(&listn, 1);
                if (p < 40) { li[p] = n; lw[p] = expf(beta*(ssim[n]-smax)); }
            }
        }
        __syncthreads();
        int ln = listn < 40 ? listn : 40;
        if (tid == 0) { float s = 0.f; for (int j = 0; j < ln; j++) s += lw[j]; ssum = s; }
        __syncthreads();
        if (rw == 0) {
            // rv_new[b, h*64+d] = sum_j w_j * mem[b, idx_j, h, d]   (pre-update mem)
            if (tid < 64) {
                float acc = 0.f;
                for (int j = 0; j < ln; j++)
                    acc += (lw[j]/ssum) * g_mem[((size_t)(b*Nn + li[j]))*Dd + h*HD + tid];
                g_rv[b*Dd + h*HD + tid] = acc;
            }
            __syncthreads();
        } else {
            float gh = sigmoidf_(g_i[b*IFc + 4*Dd + h]);
            for (int j = 0; j < ln; j++) {
                int n = li[j];
                float w = lw[j]/ssum;
                if (tid < 64) {
                    size_t mi = ((size_t)(b*Nn + n))*Dd + h*HD + tid;
                    float m   = g_mem[mi];
                    float er  = sigmoidf_(g_i[b*IFc + 3*Dd + h*HD + tid]);
                    float val = g_i[b*IFc + 2*Dd + h*HD + tid];
                    float nm = m*(1.f - w*er) + w*(gh*val);
                    g_mem[mi] = nm;
                    red64[tid] = nm*nm;
                }
                __syncthreads();
                if (tid == 0) {
                    float s = 0.f;
                    for (int d = 0; d < 64; d++) s += red64[d];
                    g_sumsq[(b*Nn + n)*HM + h] = s;
                }
                __syncthreads();
            }
        }
        __syncthreads();
    }
}

// helpers for device-symbol addresses resolved at launch time
static float* addr_of(const void* symbol) {
    void* p = nullptr;
    cudaGetSymbolAddress(&p, symbol);
    return (float*)p;
}

extern "C" void kernel_launch(void* const* d_in, const int* in_sizes, int n_in,
                              void* d_out, int out_size) {
    const int*   input_seq = (const int*)  d_in[0];
    const float* emb       = (const float*)d_in[1];
    const float* pos       = (const float*)d_in[2];
    const float* ln1_g     = (const float*)d_in[3];
    const float* ln1_b     = (const float*)d_in[4];
    const float* ln2_g     = (const float*)d_in[5];
    const float* ln2_b     = (const float*)d_in[6];
    const float* Wq        = (const float*)d_in[7];
    const float* Wk        = (const float*)d_in[8];
    const float* Wv        = (const float*)d_in[9];
    const float* Wo        = (const float*)d_in[10];
    const float* W1        = (const float*)d_in[11];
    const float* b1        = (const float*)d_in[12];
    const float* W2        = (const float*)d_in[13];
    const float* b2        = (const float*)d_in[14];
    const float* lnf_g     = (const float*)d_in[15];
    const float* lnf_b     = (const float*)d_in[16];
    const float* W_if_h    = (const float*)d_in[17];
    const float* W_if_r    = (const float*)d_in[18];
    const float* b_if      = (const float*)d_in[19];
    const float* W_lg_h    = (const float*)d_in[20];
    const float* W_lg_r    = (const float*)d_in[21];
    const float* b_lg      = (const float*)d_in[22];
    const float* beta_read = (const float*)d_in[23];
    const float* beta_write= (const float*)d_in[24];
    const float* mem_init  = (const float*)d_in[25];
    float* out = (float*)d_out;

    static float* p_x = nullptr, *p_h, *p_q, *p_k, *p_v, *p_attno, *p_hf, *p_ffn, *p_iface, *p_rvhist;
    if (!p_x) {
        p_x      = addr_of(g_x);      p_h     = addr_of(g_h);
        p_q      = addr_of(g_q);      p_k     = addr_of(g_k);
        p_v      = addr_of(g_v);      p_attno = addr_of(g_attno);
        p_hf     = addr_of(g_hf);     p_ffn   = addr_of(g_ffn);
        p_iface  = addr_of(g_iface);  p_rvhist= addr_of(g_rvhist);
    }

    // ---- embedding ----
    k_embed<<<2048, 256>>>(input_seq, emb, pos);

    // ---- transformer layers ----
    dim3 gE((Ee + 127)/128, Mrows/128);     // (4, 16)
    dim3 gF((Ff + 127)/128, Mrows/128);     // (16, 16)
    for (int l = 0; l < Ll; l++) {
        k_ln<<<Mrows, 256>>>(p_x, p_h, ln1_g + l*Ee, ln1_b + l*Ee);
        k_gemm<<<gE, 256>>>(p_h, Wq + (size_t)l*Ee*Ee, nullptr, nullptr, p_q, Mrows, Ee, Ee, 0);
        k_gemm<<<gE, 256>>>(p_h, Wk + (size_t)l*Ee*Ee, nullptr, nullptr, p_k, Mrows, Ee, Ee, 0);
        k_gemm<<<gE, 256>>>(p_h, Wv + (size_t)l*Ee*Ee, nullptr, nullptr, p_v, Mrows, Ee, Ee, 0);
        k_attn<<<dim3(Tt, HA, Bb), 256>>>();
        k_gemm<<<gE, 256>>>(p_attno, Wo + (size_t)l*Ee*Ee, nullptr, p_x, p_x, Mrows, Ee, Ee, 0);
        k_ln<<<Mrows, 256>>>(p_x, p_h, ln2_g + l*Ee, ln2_b + l*Ee);
        k_gemm<<<gF, 256>>>(p_h, W1 + (size_t)l*Ee*Ff, b1 + l*Ff, nullptr, p_ffn, Mrows, Ee, Ff, 1);
        k_gemm<<<gE, 256>>>(p_ffn, W2 + (size_t)l*Ff*Ee, b2 + l*Ee, p_x, p_x, Mrows, Ff, Ee, 0);
    }

    // ---- final LN, iface projection, log_h ----
    k_ln<<<Mrows, 256>>>(p_x, p_hf, lnf_g, lnf_b);
    k_gemm<<<dim3((IFc + 127)/128, Mrows/128), 256>>>(p_hf, W_if_h, nullptr, nullptr, p_iface,
                                                      Mrows, Ee, IFc, 0);
    k_gemm<<<dim3((Vv + 127)/128, Mrows/128), 256>>>(p_hf, W_lg_h, b_lg, nullptr, out,
                                                     Mrows, Ee, Vv, 0);

    // ---- memory scan ----
    k_scan_init<<<2048, 256>>>(mem_init);
    for (int t = 0; t < Tt; t++) {
        k_iface<<<dim3(17, Bb), 64>>>(p_iface, W_if_r, b_if, t);
        k_sim<<<dim3(8, Bb*HM), 256>>>();
        k_step<<<Bb*HM, 256>>>(beta_read, beta_write);
    }

    // ---- log_r: RVhist @ W_lg_r accumulated into out ----
    k_gemm<<<dim3((Vv + 127)/128, Mrows/128), 256>>>(p_rvhist, W_lg_r, nullptr, out, out,
                                                     Mrows, Dd, Vv, 0);
}

// round 3
// speedup vs baseline: 1.1196x; 1.1196x over previous
#include <cuda_runtime.h>
#include <cuda_bf16.h>
#include <math.h>

// ---------------- problem constants ----------------
#define Vv 32000
#define Ee 512
#define Ff 2048
#define Dd 256
#define Nn 2048
#define Ll 2
#define Bb 8
#define Tt 256
#define HM 4
#define TOPK 8
#define HA 8
#define HD 64
#define DH 64
#define IFc 1028
#define Mrows (Bb*Tt)
#define GRIDB 128

// ---------------- scratch ----------------
__device__ float g_x[Mrows*Ee];
__device__ float g_h[Mrows*Ee];
__device__ float g_q[Mrows*Ee];
__device__ float g_k[Mrows*Ee];
__device__ float g_v[Mrows*Ee];
__device__ float g_attno[Mrows*Ee];
__device__ float g_hf[Mrows*Ee];
__device__ float g_ffn[Mrows*Ff];
__device__ float g_iface[Mrows*IFc];
__device__ float g_mem[Bb*Nn*Dd];
__device__ float g_sumsq[Bb*Nn*HM];
__device__ float g_rvhist[Mrows*Dd];
__device__ float g_rv[Bb*Dd];
__device__ float g_ibuf[2][Bb*IFc];
__device__ float g_sim[2*Bb*HM*Nn];
__device__ unsigned g_cnt;
__device__ unsigned g_gen;

// ---------------- embedding ----------------
__global__ void k_embed(const int* __restrict__ seq, const float* __restrict__ emb,
                        const float* __restrict__ pos) {
    int stride = gridDim.x * blockDim.x;
    for (int idx = blockIdx.x*blockDim.x + threadIdx.x; idx < Mrows*Ee; idx += stride) {
        int e  = idx % Ee;
        int bt = idx / Ee;
        int t  = bt % Tt;
        g_x[idx] = emb[(size_t)seq[bt]*Ee + e] + pos[t*Ee + e];
    }
}

// ---------------- layernorm ----------------
__global__ void k_ln(const float* __restrict__ in, float* __restrict__ outp,
                     const float* __restrict__ g, const float* __restrict__ b) {
    int row = blockIdx.x;
    int tid = threadIdx.x;
    const float* x = in + (size_t)row*Ee;
    __shared__ float red[256];
    float v0 = x[tid], v1 = x[tid+256];
    red[tid] = v0 + v1;
    __syncthreads();
    for (int s = 128; s > 0; s >>= 1) { if (tid < s) red[tid] += red[tid+s]; __syncthreads(); }
    float mean = red[0] * (1.f/Ee);
    __syncthreads();
    float d0 = v0 - mean, d1 = v1 - mean;
    red[tid] = d0*d0 + d1*d1;
    __syncthreads();
    for (int s = 128; s > 0; s >>= 1) { if (tid < s) red[tid] += red[tid+s]; __syncthreads(); }
    float inv = rsqrtf(red[0] * (1.f/Ee) + 1e-5f);
    outp[(size_t)row*Ee + tid]       = d0*inv*g[tid]     + b[tid];
    outp[(size_t)row*Ee + tid + 256] = d1*inv*g[tid+256] + b[tid+256];
}

__device__ __forceinline__ float geluf_(float xx) {
    float tt = tanhf(0.7978845608028654f * (xx + 0.044715f*xx*xx*xx));
    return 0.5f * xx * (1.f + tt);
}

// ---------------- GEMM: BM x 128 tile, BK=16, double-buffered ----------------
template<int BM, int TM>
__global__ void __launch_bounds__(256) k_gemm(const float* __restrict__ A, const float* __restrict__ W,
                       const float* __restrict__ bias, const float* __restrict__ res,
                       float* __restrict__ C, int M, int K, int N, int act) {
    __shared__ float As[2][16][BM];
    __shared__ float Bs[2][16][128];
    const int tid = threadIdx.x;
    const int bm = blockIdx.y * BM, bn = blockIdx.x * 128;
    const int tx = tid & 15, ty = tid >> 4;
    constexpr int AV = BM/64;
    float4 aR[AV], bR[2];
    float acc[TM][8];
#pragma unroll
    for (int i = 0; i < TM; i++)
#pragma unroll
        for (int j = 0; j < 8; j++) acc[i][j] = 0.f;

    auto ldg = [&](int k0) {
#pragma unroll
        for (int v = 0; v < AV; v++) {
            int i = tid + v*256;
            int row = i >> 2, cg = i & 3;
            aR[v] = *(const float4*)(A + (size_t)(bm+row)*K + k0 + cg*4);
        }
#pragma unroll
        for (int v = 0; v < 2; v++) {
            int i = tid + v*256;
            int row = i >> 5, cg = i & 31;
            int col = bn + cg*4;
            if (col < N) bR[v] = *(const float4*)(W + (size_t)(k0+row)*N + col);
            else { bR[v].x = bR[v].y = bR[v].z = bR[v].w = 0.f; }
        }
    };
    auto sts = [&](int buf) {
#pragma unroll
        for (int v = 0; v < AV; v++) {
            int i = tid + v*256;
            int row = i >> 2, cg = i & 3;
            As[buf][cg*4+0][row] = aR[v].x; As[buf][cg*4+1][row] = aR[v].y;
            As[buf][cg*4+2][row] = aR[v].z; As[buf][cg*4+3][row] = aR[v].w;
        }
#pragma unroll
        for (int v = 0; v < 2; v++) {
            int i = tid + v*256;
            int row = i >> 5, cg = i & 31;
            *(float4*)&Bs[buf][row][cg*4] = bR[v];
        }
    };
    auto comp = [&](int buf) {
#pragma unroll
        for (int kk = 0; kk < 16; kk++) {
            float a[TM], bfr[8];
#pragma unroll
            for (int v = 0; v < TM/4; v++)
                *(float4*)&a[v*4] = *(const float4*)&As[buf][kk][ty*TM + v*4];
            *(float4*)&bfr[0] = *(const float4*)&Bs[buf][kk][tx*8];
            *(float4*)&bfr[4] = *(const float4*)&Bs[buf][kk][tx*8+4];
#pragma unroll
            for (int i = 0; i < TM; i++)
#pragma unroll
                for (int j = 0; j < 8; j++) acc[i][j] += a[i]*bfr[j];
        }
    };

    ldg(0); sts(0); __syncthreads();
    int cur = 0;
    for (int k0 = 16; k0 < K; k0 += 16) {
        ldg(k0);
        comp(cur);
        sts(cur^1);
        __syncthreads();
        cur ^= 1;
    }
    comp(cur);

#pragma unroll
    for (int i = 0; i < TM; i++) {
        int row = bm + ty*TM + i;
#pragma unroll
        for (int jv = 0; jv < 2; jv++) {
            int col = bn + tx*8 + jv*4;
            if (col < N) {
                float4 v4;
                v4.x = acc[i][jv*4+0]; v4.y = acc[i][jv*4+1];
                v4.z = acc[i][jv*4+2]; v4.w = acc[i][jv*4+3];
                if (bias) { v4.x += bias[col]; v4.y += bias[col+1]; v4.z += bias[col+2]; v4.w += bias[col+3]; }
                if (act == 1) { v4.x = geluf_(v4.x); v4.y = geluf_(v4.y); v4.z = geluf_(v4.z); v4.w = geluf_(v4.w); }
                if (res) {
                    float4 r4 = *(const float4*)&res[(size_t)row*N + col];
                    v4.x += r4.x; v4.y += r4.y; v4.z += r4.z; v4.w += r4.w;
                }
                *(float4*)&C[(size_t)row*N + col] = v4;
            }
        }
    }
}

// ---------------- dual-source logits GEMM: out = A1@W1 + A2@W2 + bias ----------------
__global__ void __launch_bounds__(256) k_gemm_dual(const float* __restrict__ A1, const float* __restrict__ Wg,
                            const float* __restrict__ A2, const float* __restrict__ Wr,
                            const float* __restrict__ bias, float* __restrict__ C, int N) {
    constexpr int BM = 128, TM = 8, K1 = 512, KT = 768;
    __shared__ float As[2][16][BM];
    __shared__ float Bs[2][16][128];
    const int tid = threadIdx.x;
    const int bm = blockIdx.y * BM, bn = blockIdx.x * 128;
    const int tx = tid & 15, ty = tid >> 4;
    float4 aR[2], bR[2];
    float acc[TM][8];
#pragma unroll
    for (int i = 0; i < TM; i++)
#pragma unroll
        for (int j = 0; j < 8; j++) acc[i][j] = 0.f;

    auto ldg = [&](int k0) {
        const float* Ap; const float* Wp; int Kp, kr;
        if (k0 < K1) { Ap = A1; Wp = Wg; Kp = 512; kr = k0; }
        else         { Ap = A2; Wp = Wr; Kp = 256; kr = k0 - K1; }
#pragma unroll
        for (int v = 0; v < 2; v++) {
            int i = tid + v*256;
            int row = i >> 2, cg = i & 3;
            aR[v] = *(const float4*)(Ap + (size_t)(bm+row)*Kp + kr + cg*4);
        }
#pragma unroll
        for (int v = 0; v < 2; v++) {
            int i = tid + v*256;
            int row = i >> 5, cg = i & 31;
            int col = bn + cg*4;
            if (col < N) bR[v] = *(const float4*)(Wp + (size_t)(kr+row)*N + col);
            else { bR[v].x = bR[v].y = bR[v].z = bR[v].w = 0.f; }
        }
    };
    auto sts = [&](int buf) {
#pragma unroll
        for (int v = 0; v < 2; v++) {
            int i = tid + v*256;
            int row = i >> 2, cg = i & 3;
            As[buf][cg*4+0][row] = aR[v].x; As[buf][cg*4+1][row] = aR[v].y;
            As[buf][cg*4+2][row] = aR[v].z; As[buf][cg*4+3][row] = aR[v].w;
        }
#pragma unroll
        for (int v = 0; v < 2; v++) {
            int i = tid + v*256;
            int row = i >> 5, cg = i & 31;
            *(float4*)&Bs[buf][row][cg*4] = bR[v];
        }
    };
    auto comp = [&](int buf) {
#pragma unroll
        for (int kk = 0; kk < 16; kk++) {
            float a[TM], bfr[8];
            *(float4*)&a[0] = *(const float4*)&As[buf][kk][ty*TM];
            *(float4*)&a[4] = *(const float4*)&As[buf][kk][ty*TM+4];
            *(float4*)&bfr[0] = *(const float4*)&Bs[buf][kk][tx*8];
            *(float4*)&bfr[4] = *(const float4*)&Bs[buf][kk][tx*8+4];
#pragma unroll
            for (int i = 0; i < TM; i++)
#pragma unroll
                for (int j = 0; j < 8; j++) acc[i][j] += a[i]*bfr[j];
        }
    };

    ldg(0); sts(0); __syncthreads();
    int cur = 0;
    for (int k0 = 16; k0 < KT; k0 += 16) {
        ldg(k0);
        comp(cur);
        sts(cur^1);
        __syncthreads();
        cur ^= 1;
    }
    comp(cur);

#pragma unroll
    for (int i = 0; i < TM; i++) {
        int row = bm + ty*TM + i;
#pragma unroll
        for (int jv = 0; jv < 2; jv++) {
            int col = bn + tx*8 + jv*4;
            if (col < N) {
                float4 v4;
                v4.x = acc[i][jv*4+0] + bias[col];
                v4.y = acc[i][jv*4+1] + bias[col+1];
                v4.z = acc[i][jv*4+2] + bias[col+2];
                v4.w = acc[i][jv*4+3] + bias[col+3];
                *(float4*)&C[(size_t)row*N + col] = v4;
            }
        }
    }
}

// ---------------- attention ----------------
__global__ void k_attn() {
    int t = blockIdx.x, hh = blockIdx.y, b = blockIdx.z;
    int tid = threadIdx.x;
    __shared__ float sq[64];
    __shared__ float ss[256];
    __shared__ float red[256];
    const float* qrow = g_q + ((size_t)(b*Tt + t))*Ee + hh*DH;
    if (tid < 64) sq[tid] = qrow[tid];
    __syncthreads();
    float lmax = -3.4e38f;
    for (int j = tid; j <= t; j += 256) {
        const float* krow = g_k + ((size_t)(b*Tt + j))*Ee + hh*DH;
        float d = 0.f;
#pragma unroll
        for (int e = 0; e < 64; e++) d += sq[e]*krow[e];
        d *= 0.125f;
        ss[j] = d;
        lmax = fmaxf(lmax, d);
    }
    red[tid] = lmax;
    __syncthreads();
    for (int s = 128; s > 0; s >>= 1) { if (tid < s) red[tid] = fmaxf(red[tid], red[tid+s]); __syncthreads(); }
    float mx = red[0];
    __syncthreads();
    float lsum = 0.f;
    for (int j = tid; j <= t; j += 256) { float p = expf(ss[j]-mx); ss[j] = p; lsum += p; }
    red[tid] = lsum;
    __syncthreads();
    for (int s = 128; s > 0; s >>= 1) { if (tid < s) red[tid] += red[tid+s]; __syncthreads(); }
    float inv = 1.f / red[0];
    __syncthreads();
    if (tid < 64) {
        float acc = 0.f;
        for (int j = 0; j <= t; j++)
            acc += ss[j] * g_v[((size_t)(b*Tt + j))*Ee + hh*DH + tid];
        g_attno[((size_t)(b*Tt + t))*Ee + hh*DH + tid] = acc * inv;
    }
}

// ---------------- scan init ----------------
__global__ void k_scan_init(const float* __restrict__ mem_init, const float* __restrict__ iface,
                            const float* __restrict__ b_if) {
    int stride = gridDim.x*blockDim.x;
    int tid0 = blockIdx.x*blockDim.x + threadIdx.x;
    for (int idx = tid0; idx < Bb*Nn*Dd; idx += stride)
        g_mem[idx] = mem_init[idx % (Nn*Dd)];
    for (int idx = tid0; idx < Bb*Nn*HM; idx += stride) {
        int h = idx % HM;
        int n = (idx / HM) % Nn;
        const float* r = mem_init + (size_t)n*Dd + h*HD;
        float s = 0.f;
#pragma unroll
        for (int d = 0; d < HD; d++) s += r[d]*r[d];
        g_sumsq[idx] = s;
    }
    for (int idx = tid0; idx < Bb*IFc; idx += stride) {
        int b = idx / IFc, c = idx - b*IFc;
        g_ibuf[0][idx] = iface[((size_t)(b*Tt))*IFc + c] + b_if[c];
    }
    for (int idx = tid0; idx < Bb*Dd; idx += stride) {
        g_rv[idx] = 0.f;
        int b = idx / Dd, d = idx % Dd;
        g_rvhist[((size_t)(b*Tt))*Dd + d] = 0.f;
    }
    if (tid0 == 0) { g_cnt = 0u; g_gen = 0u; }
}

// ---------------- software grid barrier (all GRIDB blocks resident) ----------------
__device__ __forceinline__ void gridbar() {
    __syncthreads();
    if (threadIdx.x == 0) {
        __threadfence();
        unsigned gen = atomicAdd(&g_gen, 0u);
        if (atomicAdd(&g_cnt, 1u) == GRIDB - 1u) {
            g_cnt = 0u;
            __threadfence();
            atomicExch(&g_gen, gen + 1u);
        } else {
            while (atomicAdd(&g_gen, 0u) == gen) { }
        }
    }
    __syncthreads();
}

__device__ __forceinline__ float sigmoidf_(float x) { return 1.f/(1.f + expf(-x)); }

// ---------------- persistent scan kernel: entire 256-step recurrence ----------------
__global__ void __launch_bounds__(256, 1) k_scan(const float* __restrict__ iface,
                                                 const float* __restrict__ W_if_r,
                                                 const float* __restrict__ b_if,
                                                 const float* __restrict__ brp,
                                                 const float* __restrict__ bwp) {
    const int blk = blockIdx.x, tid = threadIdx.x;
    const int warp = tid >> 5, lane = tid & 31;
    __shared__ float ssim[Nn];
    __shared__ float skr[64], skw[64];
    __shared__ float kq[128];
    __shared__ float rv8[8]; __shared__ int ri8[8];
    __shared__ float lw[48]; __shared__ int li[48];
    __shared__ int s_cnt; __shared__ int s_win;
    __shared__ float s_scal[4];

    float beta_r, beta_w;
    {
        float b0 = *brp; b0 = log1pf(expf(b0)); beta_r = fminf(fmaxf(b0, 1.f), 20.f);
        float b1 = *bwp; b1 = log1pf(expf(b1)); beta_w = fminf(fmaxf(b1, 1.f), 20.f);
    }
    const int s_bh = blk >> 2, s_sub = blk & 3;
    const int s_b = s_bh >> 2, s_h = s_bh & 3;
    const int c_b = blk >> 2, c_h = blk & 3;   // valid when blk < 32

    for (int t = 0; t < Tt; t++) {
        const float* ib = g_ibuf[t & 1];
        // ---------- phase SIM (all 128 blocks) ----------
        {
            if (tid < 128) {
                int rw = tid >> 6, d = tid & 63;
                float kx = ib[s_b*IFc + rw*Dd + s_h*64 + d];
                if (rw) skw[d] = kx; else skr[d] = kx;
                kq[tid] = kx*kx;
            }
            __syncthreads();
            if (tid < 2) {
                float s = 0.f;
                for (int d2 = 0; d2 < 64; d2++) s += kq[tid*64 + d2];
                s_scal[tid] = rsqrtf(s + 1e-8f);
            }
            __syncthreads();
            if (tid < 128) {
                int rw = tid >> 6, d = tid & 63;
                if (rw) skw[d] *= s_scal[1]; else skr[d] *= s_scal[0];
            }
            __syncthreads();
            int n0 = s_sub*512 + warp*64;
            for (int r = 0; r < 64; r++) {
                int n = n0 + r;
                const float* mrow = g_mem + ((size_t)(s_b*Nn + n))*Dd + s_h*64;
                float m0 = mrow[lane], m1 = mrow[lane + 32];
                float dr = m0*skr[lane] + m1*skr[lane+32];
                float dw = m0*skw[lane] + m1*skw[lane+32];
#pragma unroll
                for (int off = 16; off > 0; off >>= 1) {
                    dr += __shfl_down_sync(0xffffffffu, dr, off);
                    dw += __shfl_down_sync(0xffffffffu, dw, off);
                }
                if (lane == 0) {
                    float inv = rsqrtf(g_sumsq[(s_b*Nn + n)*HM + s_h] + 1e-8f);
                    g_sim[(size_t)s_bh*Nn + n]        = dr * inv;
                    g_sim[(size_t)(32 + s_bh)*Nn + n] = dw * inv;
                }
            }
        }
        gridbar();
        // ---------- phase C (blocks 0..31: topk, rv, mem update) ----------
        if (blk < 32) {
            for (int rw = 0; rw < 2; rw++) {
                float beta = rw ? beta_w : beta_r;
                const float* s0 = g_sim + ((size_t)(rw*32 + blk))*Nn;
                float v[8];
#pragma unroll
                for (int j2 = 0; j2 < 8; j2++) { v[j2] = s0[tid + 256*j2]; ssim[tid + 256*j2] = v[j2]; }
                if (tid == 0) s_cnt = 0;
                __syncthreads();
                for (int k = 0; k < TOPK; k++) {
                    float bv = -3.4e38f; int bi = 0;
#pragma unroll
                    for (int j2 = 0; j2 < 8; j2++) if (v[j2] > bv) { bv = v[j2]; bi = tid + 256*j2; }
#pragma unroll
                    for (int off = 16; off > 0; off >>= 1) {
                        float ov = __shfl_down_sync(0xffffffffu, bv, off);
                        int   oi = __shfl_down_sync(0xffffffffu, bi, off);
                        if (ov > bv) { bv = ov; bi = oi; }
                    }
                    if (lane == 0) { rv8[warp] = bv; ri8[warp] = bi; }
                    __syncthreads();
                    if (tid == 0) {
                        float mv = rv8[0]; int mi = ri8[0];
                        for (int w2 = 1; w2 < 8; w2++) if (rv8[w2] > mv) { mv = rv8[w2]; mi = ri8[w2]; }
                        if (k == 0)       s_scal[0] = mv;
                        if (k == TOPK-1)  s_scal[1] = mv;
                        s_win = mi;
                    }
                    __syncthreads();
                    int wn = s_win;
                    if ((wn & 255) == tid) v[wn >> 8] = -3.4e38f;
                }
                float smax = s_scal[0], kth = s_scal[1];
#pragma unroll
                for (int j2 = 0; j2 < 8; j2++) {
                    int n = tid + 256*j2;
                    float sv = ssim[n];
                    if (sv >= kth) {
                        int p = atomicAdd(&s_cnt, 1);
                        if (p < 48) { li[p] = n; lw[p] = expf(beta*(sv - smax)); }
                    }
                }
                __syncthreads();
                int ln = s_cnt < 48 ? s_cnt : 48;
                if (tid == 0) {
                    for (int a2 = 1; a2 < ln; a2++) {  // sort by index -> deterministic sums
                        int key = li[a2]; float kw2 = lw[a2]; int c2 = a2 - 1;
                        while (c2 >= 0 && li[c2] > key) { li[c2+1] = li[c2]; lw[c2+1] = lw[c2]; c2--; }
                        li[c2+1] = key; lw[c2+1] = kw2;
                    }
                    float s = 0.f;
                    for (int j = 0; j < ln; j++) s += lw[j];
                    s_scal[2] = 1.f / s;
                }
                __syncthreads();
                float invs = s_scal[2];
                if (rw == 0) {
                    if (tid < 64) {
                        float acc = 0.f;
                        for (int j = 0; j < ln; j++)
                            acc += (lw[j]*invs) * g_mem[((size_t)(c_b*Nn + li[j]))*Dd + c_h*64 + tid];
                        g_rv[c_b*Dd + c_h*64 + tid] = acc;
                        if (t + 1 < Tt) g_rvhist[((size_t)(c_b*Tt + t + 1))*Dd + c_h*64 + tid] = acc;
                    }
                    __syncthreads();
                } else {
                    float gh   = sigmoidf_(ib[c_b*IFc + 4*Dd + c_h]);
                    float er0  = sigmoidf_(ib[c_b*IFc + 3*Dd + c_h*64 + lane]);
                    float er1  = sigmoidf_(ib[c_b*IFc + 3*Dd + c_h*64 + lane + 32]);
                    float val0 = ib[c_b*IFc + 2*Dd + c_h*64 + lane];
                    float val1 = ib[c_b*IFc + 2*Dd + c_h*64 + lane + 32];
                    for (int j = warp; j < ln; j += 8) {
                        int n = li[j]; float w = lw[j]*invs;
                        size_t base = ((size_t)(c_b*Nn + n))*Dd + c_h*64;
                        float m0 = g_mem[base + lane], m1 = g_mem[base + lane + 32];
                        float nm0 = m0*(1.f - w*er0) + w*(gh*val0);
                        float nm1 = m1*(1.f - w*er1) + w*(gh*val1);
                        g_mem[base + lane] = nm0;
                        g_mem[base + lane + 32] = nm1;
                        float ss2 = nm0*nm0 + nm1*nm1;
#pragma unroll
                        for (int off = 16; off > 0; off >>= 1) ss2 += __shfl_down_sync(0xffffffffu, ss2, off);
                        if (lane == 0) g_sumsq[(c_b*Nn + n)*HM + c_h] = ss2;
                    }
                    __syncthreads();
                }
            }
        }
        gridbar();
        // ---------- phase A: iface for t+1 (deterministic full dot per thread) ----------
        if (t + 1 < Tt) {
            for (int idx = blk*256 + tid; idx < Bb*IFc; idx += GRIDB*256) {
                int b2 = idx / IFc, c = idx - b2*IFc;
                float acc = iface[((size_t)(b2*Tt + t + 1))*IFc + c] + b_if[c];
                const float* rvp = g_rv + b2*Dd;
                const float* wp = W_if_r + c;
#pragma unroll 4
                for (int d = 0; d < Dd; d++) acc += rvp[d] * wp[(size_t)d*IFc];
                g_ibuf[(t + 1) & 1][idx] = acc;
            }
        }
        gridbar();
    }
}

static float* addr_of(const void* symbol) {
    void* p = nullptr;
    cudaGetSymbolAddress(&p, symbol);
    return (float*)p;
}

extern "C" void kernel_launch(void* const* d_in, const int* in_sizes, int n_in,
                              void* d_out, int out_size) {
    const int*   input_seq = (const int*)  d_in[0];
    const float* emb       = (const float*)d_in[1];
    const float* pos       = (const float*)d_in[2];
    const float* ln1_g     = (const float*)d_in[3];
    const float* ln1_b     = (const float*)d_in[4];
    const float* ln2_g     = (const float*)d_in[5];
    const float* ln2_b     = (const float*)d_in[6];
    const float* Wq        = (const float*)d_in[7];
    const float* Wk        = (const float*)d_in[8];
    const float* Wv        = (const float*)d_in[9];
    const float* Wo        = (const float*)d_in[10];
    const float* W1        = (const float*)d_in[11];
    const float* b1        = (const float*)d_in[12];
    const float* W2        = (const float*)d_in[13];
    const float* b2        = (const float*)d_in[14];
    const float* lnf_g     = (const float*)d_in[15];
    const float* lnf_b     = (const float*)d_in[16];
    const float* W_if_h    = (const float*)d_in[17];
    const float* W_if_r    = (const float*)d_in[18];
    const float* b_if      = (const float*)d_in[19];
    const float* W_lg_h    = (const float*)d_in[20];
    const float* W_lg_r    = (const float*)d_in[21];
    const float* b_lg      = (const float*)d_in[22];
    const float* beta_read = (const float*)d_in[23];
    const float* beta_write= (const float*)d_in[24];
    const float* mem_init  = (const float*)d_in[25];
    float* out = (float*)d_out;

    static float* p_x = nullptr, *p_h, *p_q, *p_k, *p_v, *p_attno, *p_hf, *p_ffn, *p_iface, *p_rvhist;
    if (!p_x) {
        p_x      = addr_of(g_x);      p_h     = addr_of(g_h);
        p_q      = addr_of(g_q);      p_k     = addr_of(g_k);
        p_v      = addr_of(g_v);      p_attno = addr_of(g_attno);
        p_hf     = addr_of(g_hf);     p_ffn   = addr_of(g_ffn);
        p_iface  = addr_of(g_iface);  p_rvhist= addr_of(g_rvhist);
    }

    k_embed<<<2048, 256>>>(input_seq, emb, pos);

    dim3 gE(4, 32);      // N=512  with BM=64  -> 128 blocks
    dim3 gF(16, 16);     // N=2048 with BM=128 -> 256 blocks
    for (int l = 0; l < Ll; l++) {
        k_ln<<<Mrows, 256>>>(p_x, p_h, ln1_g + l*Ee, ln1_b + l*Ee);
        k_gemm<64,4><<<gE, 256>>>(p_h, Wq + (size_t)l*Ee*Ee, nullptr, nullptr, p_q, Mrows, Ee, Ee, 0);
        k_gemm<64,4><<<gE, 256>>>(p_h, Wk + (size_t)l*Ee*Ee, nullptr, nullptr, p_k, Mrows, Ee, Ee, 0);
        k_gemm<64,4><<<gE, 256>>>(p_h, Wv + (size_t)l*Ee*Ee, nullptr, nullptr, p_v, Mrows, Ee, Ee, 0);
        k_attn<<<dim3(Tt, HA, Bb), 256>>>();
        k_gemm<64,4><<<gE, 256>>>(p_attno, Wo + (size_t)l*Ee*Ee, nullptr, p_x, p_x, Mrows, Ee, Ee, 0);
        k_ln<<<Mrows, 256>>>(p_x, p_h, ln2_g + l*Ee, ln2_b + l*Ee);
        k_gemm<128,8><<<gF, 256>>>(p_h, W1 + (size_t)l*Ee*Ff, b1 + l*Ff, nullptr, p_ffn, Mrows, Ee, Ff, 1);
        k_gemm<64,4><<<gE, 256>>>(p_ffn, W2 + (size_t)l*Ff*Ee, b2 + l*Ee, p_x, p_x, Mrows, Ff, Ee, 0);
    }

    k_ln<<<Mrows, 256>>>(p_x, p_hf, lnf_g, lnf_b);
    k_gemm<128,8><<<dim3(9, 16), 256>>>(p_hf, W_if_h, nullptr, nullptr, p_iface, Mrows, Ee, IFc, 0);

    // ---- memory scan (single persistent kernel) ----
    k_scan_init<<<2048, 256>>>(mem_init, p_iface, b_if);
    k_scan<<<GRIDB, 256>>>(p_iface, W_if_r, b_if, beta_read, beta_write);

    // ---- logits: out = h_f @ W_lg_h + rvhist @ W_lg_r + b_lg (one fused GEMM) ----
    k_gemm_dual<<<dim3(250, 16), 256>>>(p_hf, W_lg_h, p_rvhist, W_lg_r, b_lg, out, Vv);
}

// round 5
// speedup vs baseline: 1.2354x; 1.1034x over previous
#include <cuda_runtime.h>
#include <cuda_bf16.h>
#include <math.h>
#include <stdint.h>

// ---------------- problem constants ----------------
#define Vv 32000
#define Ee 512
#define Ff 2048
#define Dd 256
#define Nn 2048
#define Ll 2
#define Bb 8
#define Tt 256
#define HM 4
#define TOPK 8
#define HA 8
#define HD 64
#define DH 64
#define IFc 1028
#define Mrows (Bb*Tt)
#define GRIDB 128
#define KTOT 768          // 512 (h_f) + 256 (rvhist)
#define NCHUNK 72         // 3 segments * 768/32

// ---------------- scratch ----------------
__device__ float g_x[Mrows*Ee];
__device__ float g_h[Mrows*Ee];
__device__ float g_q[Mrows*Ee];
__device__ float g_k[Mrows*Ee];
__device__ float g_v[Mrows*Ee];
__device__ float g_attno[Mrows*Ee];
__device__ float g_hf[Mrows*Ee];
__device__ float g_ffn[Mrows*Ff];
__device__ float g_iface[Mrows*IFc];
__device__ float g_mem[Bb*Nn*Dd];
__device__ float g_sumsq[Bb*Nn*HM];
__device__ float g_rvhist[Mrows*Dd];
__device__ float g_rv[Bb*Dd];
__device__ float g_ibuf[2][Bb*IFc];
__device__ float g_sim[2*Bb*HM*Nn];
__device__ float g_wifrT[IFc*Dd];
__device__ __nv_bfloat16 g_Whi[(size_t)Vv*KTOT];     // [n][k]
__device__ __nv_bfloat16 g_Wlo[(size_t)Vv*KTOT];     // [n][k]
__device__ __nv_bfloat16 g_Ab[(size_t)Mrows*2*KTOT]; // [m][hi(768) | lo(768)]
__device__ unsigned g_cnt;
__device__ unsigned g_gen;

// ---------------- embedding ----------------
__global__ void k_embed(const int* __restrict__ seq, const float* __restrict__ emb,
                        const float* __restrict__ pos) {
    int stride = gridDim.x * blockDim.x;
    for (int idx = blockIdx.x*blockDim.x + threadIdx.x; idx < Mrows*Ee; idx += stride) {
        int e  = idx % Ee;
        int bt = idx / Ee;
        int t  = bt % Tt;
        g_x[idx] = emb[(size_t)seq[bt]*Ee + e] + pos[t*Ee + e];
    }
}

// ---------------- layernorm ----------------
__global__ void k_ln(const float* __restrict__ in, float* __restrict__ outp,
                     const float* __restrict__ g, const float* __restrict__ b) {
    int row = blockIdx.x;
    int tid = threadIdx.x;
    const float* x = in + (size_t)row*Ee;
    __shared__ float red[256];
    float v0 = x[tid], v1 = x[tid+256];
    red[tid] = v0 + v1;
    __syncthreads();
    for (int s = 128; s > 0; s >>= 1) { if (tid < s) red[tid] += red[tid+s]; __syncthreads(); }
    float mean = red[0] * (1.f/Ee);
    __syncthreads();
    float d0 = v0 - mean, d1 = v1 - mean;
    red[tid] = d0*d0 + d1*d1;
    __syncthreads();
    for (int s = 128; s > 0; s >>= 1) { if (tid < s) red[tid] += red[tid+s]; __syncthreads(); }
    float inv = rsqrtf(red[0] * (1.f/Ee) + 1e-5f);
    outp[(size_t)row*Ee + tid]       = d0*inv*g[tid]     + b[tid];
    outp[(size_t)row*Ee + tid + 256] = d1*inv*g[tid+256] + b[tid+256];
}

__device__ __forceinline__ float geluf_(float xx) {
    float tt = tanhf(0.7978845608028654f * (xx + 0.044715f*xx*xx*xx));
    return 0.5f * xx * (1.f + tt);
}

// ---------------- SIMT GEMM (transformer-sized) ----------------
template<int BM, int TM>
__global__ void __launch_bounds__(256) k_gemm(const float* __restrict__ A, const float* __restrict__ W,
                       const float* __restrict__ bias, const float* __restrict__ res,
                       float* __restrict__ C, int M, int K, int N, int act) {
    __shared__ float As[2][16][BM];
    __shared__ float Bs[2][16][128];
    const int tid = threadIdx.x;
    const int bm = blockIdx.y * BM, bn = blockIdx.x * 128;
    const int tx = tid & 15, ty = tid >> 4;
    constexpr int AV = BM/64;
    float4 aR[AV], bR[2];
    float acc[TM][8];
#pragma unroll
    for (int i = 0; i < TM; i++)
#pragma unroll
        for (int j = 0; j < 8; j++) acc[i][j] = 0.f;

    auto ldg = [&](int k0) {
#pragma unroll
        for (int v = 0; v < AV; v++) {
            int i = tid + v*256;
            int row = i >> 2, cg = i & 3;
            aR[v] = *(const float4*)(A + (size_t)(bm+row)*K + k0 + cg*4);
        }
#pragma unroll
        for (int v = 0; v < 2; v++) {
            int i = tid + v*256;
            int row = i >> 5, cg = i & 31;
            int col = bn + cg*4;
            if (col < N) bR[v] = *(const float4*)(W + (size_t)(k0+row)*N + col);
            else { bR[v].x = bR[v].y = bR[v].z = bR[v].w = 0.f; }
        }
    };
    auto sts = [&](int buf) {
#pragma unroll
        for (int v = 0; v < AV; v++) {
            int i = tid + v*256;
            int row = i >> 2, cg = i & 3;
            As[buf][cg*4+0][row] = aR[v].x; As[buf][cg*4+1][row] = aR[v].y;
            As[buf][cg*4+2][row] = aR[v].z; As[buf][cg*4+3][row] = aR[v].w;
        }
#pragma unroll
        for (int v = 0; v < 2; v++) {
            int i = tid + v*256;
            int row = i >> 5, cg = i & 31;
            *(float4*)&Bs[buf][row][cg*4] = bR[v];
        }
    };
    auto comp = [&](int buf) {
#pragma unroll
        for (int kk = 0; kk < 16; kk++) {
            float a[TM], bfr[8];
#pragma unroll
            for (int v = 0; v < TM/4; v++)
                *(float4*)&a[v*4] = *(const float4*)&As[buf][kk][ty*TM + v*4];
            *(float4*)&bfr[0] = *(const float4*)&Bs[buf][kk][tx*8];
            *(float4*)&bfr[4] = *(const float4*)&Bs[buf][kk][tx*8+4];
#pragma unroll
            for (int i = 0; i < TM; i++)
#pragma unroll
                for (int j = 0; j < 8; j++) acc[i][j] += a[i]*bfr[j];
        }
    };

    ldg(0); sts(0); __syncthreads();
    int cur = 0;
    for (int k0 = 16; k0 < K; k0 += 16) {
        ldg(k0);
        comp(cur);
        sts(cur^1);
        __syncthreads();
        cur ^= 1;
    }
    comp(cur);

#pragma unroll
    for (int i = 0; i < TM; i++) {
        int row = bm + ty*TM + i;
#pragma unroll
        for (int jv = 0; jv < 2; jv++) {
            int col = bn + tx*8 + jv*4;
            if (col < N) {
                float4 v4;
                v4.x = acc[i][jv*4+0]; v4.y = acc[i][jv*4+1];
                v4.z = acc[i][jv*4+2]; v4.w = acc[i][jv*4+3];
                if (bias) { v4.x += bias[col]; v4.y += bias[col+1]; v4.z += bias[col+2]; v4.w += bias[col+3]; }
                if (act == 1) { v4.x = geluf_(v4.x); v4.y = geluf_(v4.y); v4.z = geluf_(v4.z); v4.w = geluf_(v4.w); }
                if (res) {
                    float4 r4 = *(const float4*)&res[(size_t)row*N + col];
                    v4.x += r4.x; v4.y += r4.y; v4.z += r4.z; v4.w += r4.w;
                }
                *(float4*)&C[(size_t)row*N + col] = v4;
            }
        }
    }
}

// ---------------- attention ----------------
__global__ void k_attn() {
    int t = blockIdx.x, hh = blockIdx.y, b = blockIdx.z;
    int tid = threadIdx.x;
    __shared__ float sq[64];
    __shared__ float ss[256];
    __shared__ float red[256];
    const float* qrow = g_q + ((size_t)(b*Tt + t))*Ee + hh*DH;
    if (tid < 64) sq[tid] = qrow[tid];
    __syncthreads();
    float lmax = -3.4e38f;
    for (int j = tid; j <= t; j += 256) {
        const float* krow = g_k + ((size_t)(b*Tt + j))*Ee + hh*DH;
        float d = 0.f;
#pragma unroll
        for (int e = 0; e < 64; e++) d += sq[e]*krow[e];
        d *= 0.125f;
        ss[j] = d;
        lmax = fmaxf(lmax, d);
    }
    red[tid] = lmax;
    __syncthreads();
    for (int s = 128; s > 0; s >>= 1) { if (tid < s) red[tid] = fmaxf(red[tid], red[tid+s]); __syncthreads(); }
    float mx = red[0];
    __syncthreads();
    float lsum = 0.f;
    for (int j = tid; j <= t; j += 256) { float p = expf(ss[j]-mx); ss[j] = p; lsum += p; }
    red[tid] = lsum;
    __syncthreads();
    for (int s = 128; s > 0; s >>= 1) { if (tid < s) red[tid] += red[tid+s]; __syncthreads(); }
    float inv = 1.f / red[0];
    __syncthreads();
    if (tid < 64) {
        float acc = 0.f;
        for (int j = 0; j <= t; j++)
            acc += ss[j] * g_v[((size_t)(b*Tt + j))*Ee + hh*DH + tid];
        g_attno[((size_t)(b*Tt + t))*Ee + hh*DH + tid] = acc * inv;
    }
}

// ---------------- W_lg split + transpose ----------------
__global__ void k_convW(const float* __restrict__ Wh, const float* __restrict__ Wr) {
    __shared__ float tile[32][33];
    int nt = blockIdx.x*32, kt = blockIdx.y*32;
    int tx = threadIdx.x, ty = threadIdx.y;   // 32 x 8
#pragma unroll
    for (int r = 0; r < 32; r += 8) {
        int k = kt + ty + r, n = nt + tx;
        float v = (k < 512) ? Wh[(size_t)k*Vv + n] : Wr[(size_t)(k-512)*Vv + n];
        tile[ty+r][tx] = v;
    }
    __syncthreads();
#pragma unroll
    for (int r = 0; r < 32; r += 8) {
        int n = nt + ty + r, k = kt + tx;
        float v = tile[tx][ty+r];
        __nv_bfloat16 hi = __float2bfloat16(v);
        __nv_bfloat16 lo = __float2bfloat16(v - __bfloat162float(hi));
        g_Whi[(size_t)n*KTOT + k] = hi;
        g_Wlo[(size_t)n*KTOT + k] = lo;
    }
}

// ---------------- A split ----------------
__global__ void k_convA() {
    int stride = gridDim.x*blockDim.x;
    for (int idx = blockIdx.x*blockDim.x + threadIdx.x; idx < Mrows*KTOT; idx += stride) {
        int m = idx / KTOT, k = idx - m*KTOT;
        float v = (k < 512) ? g_hf[(size_t)m*Ee + k] : g_rvhist[(size_t)m*Dd + (k-512)];
        __nv_bfloat16 hi = __float2bfloat16(v);
        __nv_bfloat16 lo = __float2bfloat16(v - __bfloat162float(hi));
        g_Ab[(size_t)m*(2*KTOT) + k]        = hi;
        g_Ab[(size_t)m*(2*KTOT) + KTOT + k] = lo;
    }
}

// ---------------- transpose W_if_r ----------------
__global__ void k_twifr(const float* __restrict__ W) {
    __shared__ float tile[32][33];
    int ct = blockIdx.x*32, dt = blockIdx.y*32;
    int tx = threadIdx.x, ty = threadIdx.y;
#pragma unroll
    for (int r = 0; r < 32; r += 8) {
        int d = dt + ty + r, c = ct + tx;
        tile[ty+r][tx] = (c < IFc) ? W[(size_t)d*IFc + c] : 0.f;
    }
    __syncthreads();
#pragma unroll
    for (int r = 0; r < 32; r += 8) {
        int c = ct + ty + r, d = dt + tx;
        if (c < IFc) g_wifrT[(size_t)c*Dd + d] = tile[tx][ty+r];
    }
}

// ---------------- bf16 mma.sync helper (plain-target PTX, sm_80+) ----------------
__device__ __forceinline__ void mma16816(float* c, const uint32_t* a, const uint32_t* b) {
    asm volatile(
        "mma.sync.aligned.m16n8k16.row.col.f32.bf16.bf16.f32 "
        "{%0,%1,%2,%3}, {%4,%5,%6,%7}, {%8,%9}, {%0,%1,%2,%3};"
        : "+f"(c[0]), "+f"(c[1]), "+f"(c[2]), "+f"(c[3])
        : "r"(a[0]), "r"(a[1]), "r"(a[2]), "r"(a[3]), "r"(b[0]), "r"(b[1]));
}

// ---------------- HMMA logits GEMM: out[2048 x 32000] = bf16x3(A,W) + bias ----------------
// block tile 128x128, BK=32, 8 warps (2 m x 4 n), warp tile 64x32.
__global__ void __launch_bounds__(256) k_lgemm(const float* __restrict__ bias, float* __restrict__ C) {
    __shared__ __nv_bfloat16 As[2][128][40];
    __shared__ __nv_bfloat16 Bs[2][128][40];
    const int tid = threadIdx.x, wid = tid >> 5, lane = tid & 31;
    const int m0 = blockIdx.y * 128, n0 = blockIdx.x * 128;
    const int wm = (wid & 1) * 64, wn = (wid >> 1) * 32;
    const int r = lane >> 2, c2 = (lane & 3) * 2;

    float acc[4][4][4];
#pragma unroll
    for (int mi = 0; mi < 4; mi++)
#pragma unroll
        for (int ni = 0; ni < 4; ni++)
#pragma unroll
            for (int j = 0; j < 4; j++) acc[mi][ni][j] = 0.f;

    uint4 aR[2], bR[2];
    auto ldg = [&](int c) {
        int seg = c / 24, kin = (c % 24) * 32;
        const __nv_bfloat16* Aseg = g_Ab + (seg == 2 ? KTOT : 0);
        const __nv_bfloat16* Wseg = (seg == 1) ? g_Wlo : g_Whi;
#pragma unroll
        for (int v = 0; v < 2; v++) {
            int i = tid + v*256;
            int row = i >> 2, cg = i & 3;
            aR[v] = *(const uint4*)(Aseg + (size_t)(m0+row)*(2*KTOT) + kin + cg*8);
            bR[v] = *(const uint4*)(Wseg + (size_t)(n0+row)*KTOT    + kin + cg*8);
        }
    };
    auto sts = [&](int buf) {
#pragma unroll
        for (int v = 0; v < 2; v++) {
            int i = tid + v*256;
            int row = i >> 2, cg = i & 3;
            *(uint4*)&As[buf][row][cg*8] = aR[v];
            *(uint4*)&Bs[buf][row][cg*8] = bR[v];
        }
    };
    auto comp = [&](int buf) {
#pragma unroll
        for (int kt = 0; kt < 32; kt += 16) {
            uint32_t af[4][4], bfv[4][2];
#pragma unroll
            for (int mi = 0; mi < 4; mi++) {
                af[mi][0] = *(const uint32_t*)&As[buf][wm + mi*16 + r    ][kt + c2];
                af[mi][1] = *(const uint32_t*)&As[buf][wm + mi*16 + r + 8][kt + c2];
                af[mi][2] = *(const uint32_t*)&As[buf][wm + mi*16 + r    ][kt + c2 + 8];
                af[mi][3] = *(const uint32_t*)&As[buf][wm + mi*16 + r + 8][kt + c2 + 8];
            }
#pragma unroll
            for (int ni = 0; ni < 4; ni++) {
                bfv[ni][0] = *(const uint32_t*)&Bs[buf][wn + ni*8 + r][kt + c2];
                bfv[ni][1] = *(const uint32_t*)&Bs[buf][wn + ni*8 + r][kt + c2 + 8];
            }
#pragma unroll
            for (int mi = 0; mi < 4; mi++)
#pragma unroll
                for (int ni = 0; ni < 4; ni++)
                    mma16816(acc[mi][ni], af[mi], bfv[ni]);
        }
    };

    ldg(0); sts(0); __syncthreads();
    int cur = 0;
    for (int c = 1; c < NCHUNK; c++) {
        ldg(c);
        comp(cur);
        sts(cur^1);
        __syncthreads();
        cur ^= 1;
    }
    comp(cur);

    // epilogue
#pragma unroll
    for (int mi = 0; mi < 4; mi++) {
        int row0 = m0 + wm + mi*16 + r;
#pragma unroll
        for (int ni = 0; ni < 4; ni++) {
            int col = n0 + wn + ni*8 + c2;
            float2 v0, v1;
            v0.x = acc[mi][ni][0] + bias[col];
            v0.y = acc[mi][ni][1] + bias[col+1];
            v1.x = acc[mi][ni][2] + bias[col];
            v1.y = acc[mi][ni][3] + bias[col+1];
            *(float2*)&C[(size_t)row0*Vv + col]       = v0;
            *(float2*)&C[(size_t)(row0+8)*Vv + col]   = v1;
        }
    }
}

// ---------------- scan init ----------------
__global__ void k_scan_init(const float* __restrict__ mem_init, const float* __restrict__ iface,
                            const float* __restrict__ b_if) {
    int stride = gridDim.x*blockDim.x;
    int tid0 = blockIdx.x*blockDim.x + threadIdx.x;
    for (int idx = tid0; idx < Bb*Nn*Dd; idx += stride)
        g_mem[idx] = mem_init[idx % (Nn*Dd)];
    for (int idx = tid0; idx < Bb*Nn*HM; idx += stride) {
        int h = idx % HM;
        int n = (idx / HM) % Nn;
        const float* r = mem_init + (size_t)n*Dd + h*HD;
        float s = 0.f;
#pragma unroll
        for (int d = 0; d < HD; d++) s += r[d]*r[d];
        g_sumsq[idx] = s;
    }
    for (int idx = tid0; idx < Bb*IFc; idx += stride) {
        int b = idx / IFc, c = idx - b*IFc;
        g_ibuf[0][idx] = iface[((size_t)(b*Tt))*IFc + c] + b_if[c];
    }
    for (int idx = tid0; idx < Bb*Dd; idx += stride) {
        g_rv[idx] = 0.f;
        int b = idx / Dd, d = idx % Dd;
        g_rvhist[((size_t)(b*Tt))*Dd + d] = 0.f;
    }
    if (tid0 == 0) { g_cnt = 0u; g_gen = 0u; }
}

// ---------------- software grid barrier ----------------
__device__ __forceinline__ void gridbar() {
    __syncthreads();
    if (threadIdx.x == 0) {
        __threadfence();
        unsigned gen = atomicAdd(&g_gen, 0u);
        if (atomicAdd(&g_cnt, 1u) == GRIDB - 1u) {
            g_cnt = 0u;
            __threadfence();
            atomicExch(&g_gen, gen + 1u);
        } else {
            while (atomicAdd(&g_gen, 0u) == gen) { }
        }
    }
    __syncthreads();
}

__device__ __forceinline__ float sigmoidf_(float x) { return 1.f/(1.f + expf(-x)); }

// ---------------- persistent scan kernel ----------------
__global__ void __launch_bounds__(256, 1) k_scan(const float* __restrict__ iface,
                                                 const float* __restrict__ b_if,
                                                 const float* __restrict__ brp,
                                                 const float* __restrict__ bwp) {
    const int blk = blockIdx.x, tid = threadIdx.x;
    const int warp = tid >> 5, lane = tid & 31;
    __shared__ float ssim[Nn];
    __shared__ float skr[64], skw[64];
    __shared__ float kq[128];
    __shared__ float rv8[8]; __shared__ int ri8[8];
    __shared__ float lw[48]; __shared__ int li[48];
    __shared__ int s_cnt; __shared__ int s_win;
    __shared__ float s_scal[4];

    float beta_r, beta_w;
    {
        float b0 = *brp; b0 = log1pf(expf(b0)); beta_r = fminf(fmaxf(b0, 1.f), 20.f);
        float b1 = *bwp; b1 = log1pf(expf(b1)); beta_w = fminf(fmaxf(b1, 1.f), 20.f);
    }
    const int s_bh = blk >> 2, s_sub = blk & 3;
    const int s_b = s_bh >> 2, s_h = s_bh & 3;
    const int c_b = blk >> 2, c_h = blk & 3;

    for (int t = 0; t < Tt; t++) {
        const float* ib = g_ibuf[t & 1];
        // ---------- SIM ----------
        {
            if (tid < 128) {
                int rw = tid >> 6, d = tid & 63;
                float kx = ib[s_b*IFc + rw*Dd + s_h*64 + d];
                if (rw) skw[d] = kx; else skr[d] = kx;
                kq[tid] = kx*kx;
            }
            __syncthreads();
            if (tid < 2) {
                float s = 0.f;
                for (int d2 = 0; d2 < 64; d2++) s += kq[tid*64 + d2];
                s_scal[tid] = rsqrtf(s + 1e-8f);
            }
            __syncthreads();
            if (tid < 128) {
                int rw = tid >> 6, d = tid & 63;
                if (rw) skw[d] *= s_scal[1]; else skr[d] *= s_scal[0];
            }
            __syncthreads();
            int n0 = s_sub*512 + warp*64;
            for (int r = 0; r < 64; r++) {
                int n = n0 + r;
                const float* mrow = g_mem + ((size_t)(s_b*Nn + n))*Dd + s_h*64;
                float m0 = mrow[lane], m1 = mrow[lane + 32];
                float dr = m0*skr[lane] + m1*skr[lane+32];
                float dw = m0*skw[lane] + m1*skw[lane+32];
#pragma unroll
                for (int off = 16; off > 0; off >>= 1) {
                    dr += __shfl_down_sync(0xffffffffu, dr, off);
                    dw += __shfl_down_sync(0xffffffffu, dw, off);
                }
                if (lane == 0) {
                    float inv = rsqrtf(g_sumsq[(s_b*Nn + n)*HM + s_h] + 1e-8f);
                    g_sim[(size_t)s_bh*Nn + n]        = dr * inv;
                    g_sim[(size_t)(32 + s_bh)*Nn + n] = dw * inv;
                }
            }
        }
        gridbar();
        // ---------- topk + rv + mem update ----------
        if (blk < 32) {
            for (int rw = 0; rw < 2; rw++) {
                float beta = rw ? beta_w : beta_r;
                const float* s0 = g_sim + ((size_t)(rw*32 + blk))*Nn;
                float v[8];
#pragma unroll
                for (int j2 = 0; j2 < 8; j2++) { v[j2] = s0[tid + 256*j2]; ssim[tid + 256*j2] = v[j2]; }
                if (tid == 0) s_cnt = 0;
                __syncthreads();
                for (int k = 0; k < TOPK; k++) {
                    float bv = -3.4e38f; int bi = 0;
#pragma unroll
                    for (int j2 = 0; j2 < 8; j2++) if (v[j2] > bv) { bv = v[j2]; bi = tid + 256*j2; }
#pragma unroll
                    for (int off = 16; off > 0; off >>= 1) {
                        float ov = __shfl_down_sync(0xffffffffu, bv, off);
                        int   oi = __shfl_down_sync(0xffffffffu, bi, off);
                        if (ov > bv) { bv = ov; bi = oi; }
                    }
                    if (lane == 0) { rv8[warp] = bv; ri8[warp] = bi; }
                    __syncthreads();
                    if (tid == 0) {
                        float mv = rv8[0]; int mi = ri8[0];
                        for (int w2 = 1; w2 < 8; w2++) if (rv8[w2] > mv) { mv = rv8[w2]; mi = ri8[w2]; }
                        if (k == 0)       s_scal[0] = mv;
                        if (k == TOPK-1)  s_scal[1] = mv;
                        s_win = mi;
                    }
                    __syncthreads();
                    int wn = s_win;
                    if ((wn & 255) == tid) v[wn >> 8] = -3.4e38f;
                }
                float smax = s_scal[0], kth = s_scal[1];
#pragma unroll
                for (int j2 = 0; j2 < 8; j2++) {
                    int n = tid + 256*j2;
                    float sv = ssim[n];
                    if (sv >= kth) {
                        int p = atomicAdd(&s_cnt, 1);
                        if (p < 48) { li[p] = n; lw[p] = expf(beta*(sv - smax)); }
                    }
                }
                __syncthreads();
                int ln = s_cnt < 48 ? s_cnt : 48;
                if (tid == 0) {
                    for (int a2 = 1; a2 < ln; a2++) {
                        int key = li[a2]; float kw2 = lw[a2]; int c2s = a2 - 1;
                        while (c2s >= 0 && li[c2s] > key) { li[c2s+1] = li[c2s]; lw[c2s+1] = lw[c2s]; c2s--; }
                        li[c2s+1] = key; lw[c2s+1] = kw2;
                    }
                    float s = 0.f;
                    for (int j = 0; j < ln; j++) s += lw[j];
                    s_scal[2] = 1.f / s;
                }
                __syncthreads();
                float invs = s_scal[2];
                if (rw == 0) {
                    if (tid < 64) {
                        float acc = 0.f;
                        for (int j = 0; j < ln; j++)
                            acc += (lw[j]*invs) * g_mem[((size_t)(c_b*Nn + li[j]))*Dd + c_h*64 + tid];
                        g_rv[c_b*Dd + c_h*64 + tid] = acc;
                        if (t + 1 < Tt) g_rvhist[((size_t)(c_b*Tt + t + 1))*Dd + c_h*64 + tid] = acc;
                    }
                    __syncthreads();
                } else {
                    float gh   = sigmoidf_(ib[c_b*IFc + 4*Dd + c_h]);
                    float er0  = sigmoidf_(ib[c_b*IFc + 3*Dd + c_h*64 + lane]);
                    float er1  = sigmoidf_(ib[c_b*IFc + 3*Dd + c_h*64 + lane + 32]);
                    float val0 = ib[c_b*IFc + 2*Dd + c_h*64 + lane];
                    float val1 = ib[c_b*IFc + 2*Dd + c_h*64 + lane + 32];
                    for (int j = warp; j < ln; j += 8) {
                        int n = li[j]; float w = lw[j]*invs;
                        size_t base = ((size_t)(c_b*Nn + n))*Dd + c_h*64;
                        float m0 = g_mem[base + lane], m1 = g_mem[base + lane + 32];
                        float nm0 = m0*(1.f - w*er0) + w*(gh*val0);
                        float nm1 = m1*(1.f - w*er1) + w*(gh*val1);
                        g_mem[base + lane] = nm0;
                        g_mem[base + lane + 32] = nm1;
                        float ss2 = nm0*nm0 + nm1*nm1;
#pragma unroll
                        for (int off = 16; off > 0; off >>= 1) ss2 += __shfl_down_sync(0xffffffffu, ss2, off);
                        if (lane == 0) g_sumsq[(c_b*Nn + n)*HM + c_h] = ss2;
                    }
                    __syncthreads();
                }
            }
        }
        gridbar();
        // ---------- iface for t+1 ----------
        if (t + 1 < Tt) {
            for (int idx = blk*256 + tid; idx < Bb*IFc; idx += GRIDB*256) {
                int b2 = idx / IFc, c = idx - b2*IFc;
                float acc = iface[((size_t)(b2*Tt + t + 1))*IFc + c] + b_if[c];
                const float4* wp = (const float4*)(g_wifrT + (size_t)c*Dd);
                const float4* rp = (const float4*)(g_rv + b2*Dd);
#pragma unroll 8
                for (int d4 = 0; d4 < Dd/4; d4++) {
                    float4 w4 = wp[d4], r4 = rp[d4];
                    acc += r4.x*w4.x + r4.y*w4.y + r4.z*w4.z + r4.w*w4.w;
                }
                g_ibuf[(t + 1) & 1][idx] = acc;
            }
        }
        gridbar();
    }
}

static float* addr_of(const void* symbol) {
    void* p = nullptr;
    cudaGetSymbolAddress(&p, symbol);
    return (float*)p;
}

extern "C" void kernel_launch(void* const* d_in, const int* in_sizes, int n_in,
                              void* d_out, int out_size) {
    const int*   input_seq = (const int*)  d_in[0];
    const float* emb       = (const float*)d_in[1];
    const float* pos       = (const float*)d_in[2];
    const float* ln1_g     = (const float*)d_in[3];
    const float* ln1_b     = (const float*)d_in[4];
    const float* ln2_g     = (const float*)d_in[5];
    const float* ln2_b     = (const float*)d_in[6];
    const float* Wq        = (const float*)d_in[7];
    const float* Wk        = (const float*)d_in[8];
    const float* Wv        = (const float*)d_in[9];
    const float* Wo        = (const float*)d_in[10];
    const float* W1        = (const float*)d_in[11];
    const float* b1        = (const float*)d_in[12];
    const float* W2        = (const float*)d_in[13];
    const float* b2        = (const float*)d_in[14];
    const float* lnf_g     = (const float*)d_in[15];
    const float* lnf_b     = (const float*)d_in[16];
    const float* W_if_h    = (const float*)d_in[17];
    const float* W_if_r    = (const float*)d_in[18];
    const float* b_if      = (const float*)d_in[19];
    const float* W_lg_h    = (const float*)d_in[20];
    const float* W_lg_r    = (const float*)d_in[21];
    const float* b_lg      = (const float*)d_in[22];
    const float* beta_read = (const float*)d_in[23];
    const float* beta_write= (const float*)d_in[24];
    const float* mem_init  = (const float*)d_in[25];
    float* out = (float*)d_out;

    static float* p_x = nullptr, *p_h, *p_q, *p_k, *p_v, *p_attno, *p_hf, *p_ffn, *p_iface;
    if (!p_x) {
        p_x      = addr_of(g_x);      p_h     = addr_of(g_h);
        p_q      = addr_of(g_q);      p_k     = addr_of(g_k);
        p_v      = addr_of(g_v);      p_attno = addr_of(g_attno);
        p_hf     = addr_of(g_hf);     p_ffn   = addr_of(g_ffn);
        p_iface  = addr_of(g_iface);
    }

    k_embed<<<2048, 256>>>(input_seq, emb, pos);
    // W prep (independent of everything else)
    k_convW<<<dim3(Vv/32, KTOT/32), dim3(32,8)>>>(W_lg_h, W_lg_r);
    k_twifr<<<dim3((IFc+31)/32, Dd/32), dim3(32,8)>>>(W_if_r);

    dim3 gE(4, 32);
    dim3 gF(16, 16);
    for (int l = 0; l < Ll; l++) {
        k_ln<<<Mrows, 256>>>(p_x, p_h, ln1_g + l*Ee, ln1_b + l*Ee);
        k_gemm<64,4><<<gE, 256>>>(p_h, Wq + (size_t)l*Ee*Ee, nullptr, nullptr, p_q, Mrows, Ee, Ee, 0);
        k_gemm<64,4><<<gE, 256>>>(p_h, Wk + (size_t)l*Ee*Ee, nullptr, nullptr, p_k, Mrows, Ee, Ee, 0);
        k_gemm<64,4><<<gE, 256>>>(p_h, Wv + (size_t)l*Ee*Ee, nullptr, nullptr, p_v, Mrows, Ee, Ee, 0);
        k_attn<<<dim3(Tt, HA, Bb), 256>>>();
        k_gemm<64,4><<<gE, 256>>>(p_attno, Wo + (size_t)l*Ee*Ee, nullptr, p_x, p_x, Mrows, Ee, Ee, 0);
        k_ln<<<Mrows, 256>>>(p_x, p_h, ln2_g + l*Ee, ln2_b + l*Ee);
        k_gemm<128,8><<<gF, 256>>>(p_h, W1 + (size_t)l*Ee*Ff, b1 + l*Ff, nullptr, p_ffn, Mrows, Ee, Ff, 1);
        k_gemm<64,4><<<gE, 256>>>(p_ffn, W2 + (size_t)l*Ff*Ee, b2 + l*Ee, p_x, p_x, Mrows, Ff, Ee, 0);
    }

    k_ln<<<Mrows, 256>>>(p_x, p_hf, lnf_g, lnf_b);
    k_gemm<128,8><<<dim3(9, 16), 256>>>(p_hf, W_if_h, nullptr, nullptr, p_iface, Mrows, Ee, IFc, 0);

    // ---- memory scan ----
    k_scan_init<<<2048, 256>>>(mem_init, p_iface, b_if);
    k_scan<<<GRIDB, 256>>>(p_iface, b_if, beta_read, beta_write);

    // ---- A split, then HMMA logits GEMM ----
    k_convA<<<2048, 256>>>();
    k_lgemm<<<dim3(Vv/128, Mrows/128), 256>>>(b_lg, out);
}

// round 6
// speedup vs baseline: 1.6506x; 1.3360x over previous
#include <cuda_runtime.h>
#include <cuda_bf16.h>
#include <math.h>
#include <stdint.h>

// ---------------- problem constants ----------------
#define Vv 32000
#define Ee 512
#define Ff 2048
#define Dd 256
#define Nn 2048
#define Ll 2
#define Bb 8
#define Tt 256
#define HM 4
#define TOPK 8
#define HA 8
#define HD 64
#define DH 64
#define IFc 1028
#define Mrows (Bb*Tt)
#define GRIDB 128
#define WORKERS 168
#define KTOT 768
#define NTILE (250*16)   // logits tiles (n,m)

// ---------------- scratch ----------------
__device__ float g_x[Mrows*Ee];
__device__ float g_h[Mrows*Ee];
__device__ float g_q[Mrows*Ee];
__device__ float g_k[Mrows*Ee];
__device__ float g_v[Mrows*Ee];
__device__ float g_attno[Mrows*Ee];
__device__ float g_hf[Mrows*Ee];
__device__ float g_ffn[Mrows*Ff];
__device__ float g_iface[Mrows*IFc];
__device__ float g_mem[Bb*Nn*Dd];            // row layout [b][n][h*64+d]
__device__ float g_memT[32*64*Nn];           // transposed [bh][d][n]
__device__ float g_sumsq[32*Nn];             // [bh][n]
__device__ float g_rvhist[Mrows*Dd];
__device__ float g_rv[Bb*Dd];
__device__ float g_ibuf[2][Bb*IFc];
__device__ float g_sim[2*Bb*HM*Nn];
__device__ float g_wifrT[IFc*Dd];
__device__ __nv_bfloat16 g_Whi[(size_t)Vv*KTOT];
__device__ __nv_bfloat16 g_Wlo[(size_t)Vv*KTOT];
__device__ __nv_bfloat16 g_Ab[(size_t)Mrows*2*KTOT]; // [m][hi(768) | lo(768)]
__device__ unsigned g_cnt;
__device__ unsigned g_gen;
__device__ unsigned g_tile;

// ---------------- embedding ----------------
__global__ void k_embed(const int* __restrict__ seq, const float* __restrict__ emb,
                        const float* __restrict__ pos) {
    int stride = gridDim.x * blockDim.x;
    for (int idx = blockIdx.x*blockDim.x + threadIdx.x; idx < Mrows*Ee; idx += stride) {
        int e  = idx % Ee;
        int bt = idx / Ee;
        int t  = bt % Tt;
        g_x[idx] = emb[(size_t)seq[bt]*Ee + e] + pos[t*Ee + e];
    }
}

// ---------------- layernorm ----------------
__global__ void k_ln(const float* __restrict__ in, float* __restrict__ outp,
                     const float* __restrict__ g, const float* __restrict__ b) {
    int row = blockIdx.x;
    int tid = threadIdx.x;
    const float* x = in + (size_t)row*Ee;
    __shared__ float red[256];
    float v0 = x[tid], v1 = x[tid+256];
    red[tid] = v0 + v1;
    __syncthreads();
    for (int s = 128; s > 0; s >>= 1) { if (tid < s) red[tid] += red[tid+s]; __syncthreads(); }
    float mean = red[0] * (1.f/Ee);
    __syncthreads();
    float d0 = v0 - mean, d1 = v1 - mean;
    red[tid] = d0*d0 + d1*d1;
    __syncthreads();
    for (int s = 128; s > 0; s >>= 1) { if (tid < s) red[tid] += red[tid+s]; __syncthreads(); }
    float inv = rsqrtf(red[0] * (1.f/Ee) + 1e-5f);
    outp[(size_t)row*Ee + tid]       = d0*inv*g[tid]     + b[tid];
    outp[(size_t)row*Ee + tid + 256] = d1*inv*g[tid+256] + b[tid+256];
}

__device__ __forceinline__ float geluf_(float xx) {
    float tt = tanhf(0.7978845608028654f * (xx + 0.044715f*xx*xx*xx));
    return 0.5f * xx * (1.f + tt);
}

// ---------------- SIMT GEMM (transformer-sized) ----------------
template<int BM, int TM>
__global__ void __launch_bounds__(256) k_gemm(const float* __restrict__ A, const float* __restrict__ W,
                       const float* __restrict__ bias, const float* __restrict__ res,
                       float* __restrict__ C, int M, int K, int N, int act) {
    __shared__ float As[2][16][BM];
    __shared__ float Bs[2][16][128];
    const int tid = threadIdx.x;
    const int bm = blockIdx.y * BM, bn = blockIdx.x * 128;
    const int tx = tid & 15, ty = tid >> 4;
    constexpr int AV = BM/64;
    float4 aR[AV], bR[2];
    float acc[TM][8];
#pragma unroll
    for (int i = 0; i < TM; i++)
#pragma unroll
        for (int j = 0; j < 8; j++) acc[i][j] = 0.f;

    auto ldg = [&](int k0) {
#pragma unroll
        for (int v = 0; v < AV; v++) {
            int i = tid + v*256;
            int row = i >> 2, cg = i & 3;
            aR[v] = *(const float4*)(A + (size_t)(bm+row)*K + k0 + cg*4);
        }
#pragma unroll
        for (int v = 0; v < 2; v++) {
            int i = tid + v*256;
            int row = i >> 5, cg = i & 31;
            int col = bn + cg*4;
            if (col < N) bR[v] = *(const float4*)(W + (size_t)(k0+row)*N + col);
            else { bR[v].x = bR[v].y = bR[v].z = bR[v].w = 0.f; }
        }
    };
    auto sts = [&](int buf) {
#pragma unroll
        for (int v = 0; v < AV; v++) {
            int i = tid + v*256;
            int row = i >> 2, cg = i & 3;
            As[buf][cg*4+0][row] = aR[v].x; As[buf][cg*4+1][row] = aR[v].y;
            As[buf][cg*4+2][row] = aR[v].z; As[buf][cg*4+3][row] = aR[v].w;
        }
#pragma unroll
        for (int v = 0; v < 2; v++) {
            int i = tid + v*256;
            int row = i >> 5, cg = i & 31;
            *(float4*)&Bs[buf][row][cg*4] = bR[v];
        }
    };
    auto comp = [&](int buf) {
#pragma unroll
        for (int kk = 0; kk < 16; kk++) {
            float a[TM], bfr[8];
#pragma unroll
            for (int v = 0; v < TM/4; v++)
                *(float4*)&a[v*4] = *(const float4*)&As[buf][kk][ty*TM + v*4];
            *(float4*)&bfr[0] = *(const float4*)&Bs[buf][kk][tx*8];
            *(float4*)&bfr[4] = *(const float4*)&Bs[buf][kk][tx*8+4];
#pragma unroll
            for (int i = 0; i < TM; i++)
#pragma unroll
                for (int j = 0; j < 8; j++) acc[i][j] += a[i]*bfr[j];
        }
    };

    ldg(0); sts(0); __syncthreads();
    int cur = 0;
    for (int k0 = 16; k0 < K; k0 += 16) {
        ldg(k0);
        comp(cur);
        sts(cur^1);
        __syncthreads();
        cur ^= 1;
    }
    comp(cur);

#pragma unroll
    for (int i = 0; i < TM; i++) {
        int row = bm + ty*TM + i;
#pragma unroll
        for (int jv = 0; jv < 2; jv++) {
            int col = bn + tx*8 + jv*4;
            if (col < N) {
                float4 v4;
                v4.x = acc[i][jv*4+0]; v4.y = acc[i][jv*4+1];
                v4.z = acc[i][jv*4+2]; v4.w = acc[i][jv*4+3];
                if (bias) { v4.x += bias[col]; v4.y += bias[col+1]; v4.z += bias[col+2]; v4.w += bias[col+3]; }
                if (act == 1) { v4.x = geluf_(v4.x); v4.y = geluf_(v4.y); v4.z = geluf_(v4.z); v4.w = geluf_(v4.w); }
                if (res) {
                    float4 r4 = *(const float4*)&res[(size_t)row*N + col];
                    v4.x += r4.x; v4.y += r4.y; v4.z += r4.z; v4.w += r4.w;
                }
                *(float4*)&C[(size_t)row*N + col] = v4;
            }
        }
    }
}

// ---------------- attention ----------------
__global__ void k_attn() {
    int t = blockIdx.x, hh = blockIdx.y, b = blockIdx.z;
    int tid = threadIdx.x;
    __shared__ float sq[64];
    __shared__ float ss[256];
    __shared__ float red[256];
    const float* qrow = g_q + ((size_t)(b*Tt + t))*Ee + hh*DH;
    if (tid < 64) sq[tid] = qrow[tid];
    __syncthreads();
    float lmax = -3.4e38f;
    for (int j = tid; j <= t; j += 256) {
        const float* krow = g_k + ((size_t)(b*Tt + j))*Ee + hh*DH;
        float d = 0.f;
#pragma unroll
        for (int e = 0; e < 64; e++) d += sq[e]*krow[e];
        d *= 0.125f;
        ss[j] = d;
        lmax = fmaxf(lmax, d);
    }
    red[tid] = lmax;
    __syncthreads();
    for (int s = 128; s > 0; s >>= 1) { if (tid < s) red[tid] = fmaxf(red[tid], red[tid+s]); __syncthreads(); }
    float mx = red[0];
    __syncthreads();
    float lsum = 0.f;
    for (int j = tid; j <= t; j += 256) { float p = expf(ss[j]-mx); ss[j] = p; lsum += p; }
    red[tid] = lsum;
    __syncthreads();
    for (int s = 128; s > 0; s >>= 1) { if (tid < s) red[tid] += red[tid+s]; __syncthreads(); }
    float inv = 1.f / red[0];
    __syncthreads();
    if (tid < 64) {
        float acc = 0.f;
        for (int j = 0; j <= t; j++)
            acc += ss[j] * g_v[((size_t)(b*Tt + j))*Ee + hh*DH + tid];
        g_attno[((size_t)(b*Tt + t))*Ee + hh*DH + tid] = acc * inv;
    }
}

// ---------------- W_lg split + transpose ----------------
__global__ void k_convW(const float* __restrict__ Wh, const float* __restrict__ Wr) {
    __shared__ float tile[32][33];
    int nt = blockIdx.x*32, kt = blockIdx.y*32;
    int tx = threadIdx.x, ty = threadIdx.y;
#pragma unroll
    for (int r = 0; r < 32; r += 8) {
        int k = kt + ty + r, n = nt + tx;
        float v = (k < 512) ? Wh[(size_t)k*Vv + n] : Wr[(size_t)(k-512)*Vv + n];
        tile[ty+r][tx] = v;
    }
    __syncthreads();
#pragma unroll
    for (int r = 0; r < 32; r += 8) {
        int n = nt + ty + r, k = kt + tx;
        float v = tile[tx][ty+r];
        __nv_bfloat16 hi = __float2bfloat16(v);
        __nv_bfloat16 lo = __float2bfloat16(v - __bfloat162float(hi));
        g_Whi[(size_t)n*KTOT + k] = hi;
        g_Wlo[(size_t)n*KTOT + k] = lo;
    }
}

// ---------------- A splits ----------------
__global__ void k_convA1() {   // k < 512, from h_f
    int stride = gridDim.x*blockDim.x;
    for (int idx = blockIdx.x*blockDim.x + threadIdx.x; idx < Mrows*512; idx += stride) {
        int m = idx >> 9, k = idx & 511;
        float v = g_hf[(size_t)m*Ee + k];
        __nv_bfloat16 hi = __float2bfloat16(v);
        __nv_bfloat16 lo = __float2bfloat16(v - __bfloat162float(hi));
        g_Ab[(size_t)m*(2*KTOT) + k]        = hi;
        g_Ab[(size_t)m*(2*KTOT) + KTOT + k] = lo;
    }
}
__global__ void k_convA2() {   // k in [512,768), from rvhist
    int stride = gridDim.x*blockDim.x;
    for (int idx = blockIdx.x*blockDim.x + threadIdx.x; idx < Mrows*256; idx += stride) {
        int m = idx >> 8, kk = idx & 255;
        float v = g_rvhist[(size_t)m*Dd + kk];
        __nv_bfloat16 hi = __float2bfloat16(v);
        __nv_bfloat16 lo = __float2bfloat16(v - __bfloat162float(hi));
        g_Ab[(size_t)m*(2*KTOT) + 512 + kk]        = hi;
        g_Ab[(size_t)m*(2*KTOT) + KTOT + 512 + kk] = lo;
    }
}

// ---------------- transpose W_if_r ----------------
__global__ void k_twifr(const float* __restrict__ W) {
    __shared__ float tile[32][33];
    int ct = blockIdx.x*32, dt = blockIdx.y*32;
    int tx = threadIdx.x, ty = threadIdx.y;
#pragma unroll
    for (int r = 0; r < 32; r += 8) {
        int d = dt + ty + r, c = ct + tx;
        tile[ty+r][tx] = (c < IFc) ? W[(size_t)d*IFc + c] : 0.f;
    }
    __syncthreads();
#pragma unroll
    for (int r = 0; r < 32; r += 8) {
        int c = ct + ty + r, d = dt + tx;
        if (c < IFc) g_wifrT[(size_t)c*Dd + d] = tile[tx][ty+r];
    }
}

// ---------------- bf16 mma.sync ----------------
__device__ __forceinline__ void mma16816(float* c, const uint32_t* a, const uint32_t* b) {
    asm volatile(
        "mma.sync.aligned.m16n8k16.row.col.f32.bf16.bf16.f32 "
        "{%0,%1,%2,%3}, {%4,%5,%6,%7}, {%8,%9}, {%0,%1,%2,%3};"
        : "+f"(c[0]), "+f"(c[1]), "+f"(c[2]), "+f"(c[3])
        : "r"(a[0]), "r"(a[1]), "r"(a[2]), "r"(a[3]), "r"(b[0]), "r"(b[1]));
}

// ---------------- shared layouts ----------------
struct GemmSm {
    __nv_bfloat16 As[2][128][40];
    __nv_bfloat16 Bs[2][128][40];
};
struct ScanSm {
    float ssim[Nn];
    float skr[64], skw[64];
    float kq[128];
    float rv8[8]; int ri8[8];
    float lw[48]; int li[48];
    int s_cnt; int s_win;
    float s_scal[4];
    float rvred[4][64];
};

// ---------------- one 128x128 logits tile over K range [kb, kb+nseg*32)*3 passes ----------------
__device__ void lgemm_tile(GemmSm* sm, int m0, int n0, int kb, int nseg,
                           const float* __restrict__ bias, float* __restrict__ C, int accum) {
    const int tid = threadIdx.x, wid = tid >> 5, lane = tid & 31;
    const int wm = (wid & 1) * 64, wn = (wid >> 1) * 32;
    const int r = lane >> 2, c2 = (lane & 3) * 2;
    const int nchunks = nseg * 3;

    float acc[4][4][4];
#pragma unroll
    for (int mi = 0; mi < 4; mi++)
#pragma unroll
        for (int ni = 0; ni < 4; ni++)
#pragma unroll
            for (int j = 0; j < 4; j++) acc[mi][ni][j] = 0.f;

    uint4 aR[2], bR[2];
    auto ldg = [&](int c) {
        int seg = c / nseg, kin = kb + (c - seg*nseg)*32;
        const __nv_bfloat16* Aseg = g_Ab + (seg == 2 ? KTOT : 0);
        const __nv_bfloat16* Wseg = (seg == 1) ? g_Wlo : g_Whi;
#pragma unroll
        for (int v = 0; v < 2; v++) {
            int i = tid + v*256;
            int row = i >> 2, cg = i & 3;
            aR[v] = *(const uint4*)(Aseg + (size_t)(m0+row)*(2*KTOT) + kin + cg*8);
            bR[v] = *(const uint4*)(Wseg + (size_t)(n0+row)*KTOT    + kin + cg*8);
        }
    };
    auto sts = [&](int buf) {
#pragma unroll
        for (int v = 0; v < 2; v++) {
            int i = tid + v*256;
            int row = i >> 2, cg = i & 3;
            *(uint4*)&sm->As[buf][row][cg*8] = aR[v];
            *(uint4*)&sm->Bs[buf][row][cg*8] = bR[v];
        }
    };
    auto comp = [&](int buf) {
#pragma unroll
        for (int kt = 0; kt < 32; kt += 16) {
            uint32_t af[4][4], bfv[4][2];
#pragma unroll
            for (int mi = 0; mi < 4; mi++) {
                af[mi][0] = *(const uint32_t*)&sm->As[buf][wm + mi*16 + r    ][kt + c2];
                af[mi][1] = *(const uint32_t*)&sm->As[buf][wm + mi*16 + r + 8][kt + c2];
                af[mi][2] = *(const uint32_t*)&sm->As[buf][wm + mi*16 + r    ][kt + c2 + 8];
                af[mi][3] = *(const uint32_t*)&sm->As[buf][wm + mi*16 + r + 8][kt + c2 + 8];
            }
#pragma unroll
            for (int ni = 0; ni < 4; ni++) {
                bfv[ni][0] = *(const uint32_t*)&sm->Bs[buf][wn + ni*8 + r][kt + c2];
                bfv[ni][1] = *(const uint32_t*)&sm->Bs[buf][wn + ni*8 + r][kt + c2 + 8];
            }
#pragma unroll
            for (int mi = 0; mi < 4; mi++)
#pragma unroll
                for (int ni = 0; ni < 4; ni++)
                    mma16816(acc[mi][ni], af[mi], bfv[ni]);
        }
    };

    ldg(0); sts(0); __syncthreads();
    int cur = 0;
    for (int c = 1; c < nchunks; c++) {
        ldg(c);
        comp(cur);
        sts(cur^1);
        __syncthreads();
        cur ^= 1;
    }
    comp(cur);

#pragma unroll
    for (int mi = 0; mi < 4; mi++) {
        int row0 = m0 + wm + mi*16 + r;
#pragma unroll
        for (int ni = 0; ni < 4; ni++) {
            int col = n0 + wn + ni*8 + c2;
            float2 v0, v1;
            if (accum) {
                float2 o0 = *(const float2*)&C[(size_t)row0*Vv + col];
                float2 o1 = *(const float2*)&C[(size_t)(row0+8)*Vv + col];
                v0.x = acc[mi][ni][0] + o0.x; v0.y = acc[mi][ni][1] + o0.y;
                v1.x = acc[mi][ni][2] + o1.x; v1.y = acc[mi][ni][3] + o1.y;
            } else {
                v0.x = acc[mi][ni][0] + bias[col]; v0.y = acc[mi][ni][1] + bias[col+1];
                v1.x = acc[mi][ni][2] + bias[col]; v1.y = acc[mi][ni][3] + bias[col+1];
            }
            *(float2*)&C[(size_t)row0*Vv + col]     = v0;
            *(float2*)&C[(size_t)(row0+8)*Vv + col] = v1;
        }
    }
}

// ---------------- p2 logits kernel (K 512..767, accumulate) ----------------
__global__ void __launch_bounds__(256, 2) k_lgemm2(float* __restrict__ C) {
    __shared__ GemmSm sm;
    lgemm_tile(&sm, blockIdx.y*128, blockIdx.x*128, 512, 8, nullptr, C, 1);
}

// ---------------- scan init ----------------
__global__ void k_scan_init(const float* __restrict__ mem_init, const float* __restrict__ iface,
                            const float* __restrict__ b_if) {
    int stride = gridDim.x*blockDim.x;
    int tid0 = blockIdx.x*blockDim.x + threadIdx.x;
    for (int idx = tid0; idx < Bb*Nn*Dd; idx += stride)
        g_mem[idx] = mem_init[idx % (Nn*Dd)];
    for (int idx = tid0; idx < 32*64*Nn; idx += stride) {
        int n = idx & (Nn-1);
        int rest = idx >> 11;          // /Nn
        int d = rest & 63;
        int bh = rest >> 6;
        int h = bh & 3;
        g_memT[idx] = mem_init[(size_t)n*Dd + h*64 + d];
    }
    for (int idx = tid0; idx < 32*Nn; idx += stride) {
        int n = idx & (Nn-1);
        int bh = idx >> 11;
        int h = bh & 3;
        const float* r = mem_init + (size_t)n*Dd + h*HD;
        float s = 0.f;
#pragma unroll
        for (int d = 0; d < HD; d++) s += r[d]*r[d];
        g_sumsq[idx] = s;
    }
    for (int idx = tid0; idx < Bb*IFc; idx += stride) {
        int b = idx / IFc, c = idx - b*IFc;
        g_ibuf[0][idx] = iface[((size_t)(b*Tt))*IFc + c] + b_if[c];
    }
    for (int idx = tid0; idx < Bb*Dd; idx += stride) {
        g_rv[idx] = 0.f;
        int b = idx / Dd, d = idx % Dd;
        g_rvhist[((size_t)(b*Tt))*Dd + d] = 0.f;
    }
    if (tid0 == 0) { g_cnt = 0u; g_gen = 0u; g_tile = 0u; }
}

// ---------------- software grid barrier (scan blocks only) ----------------
__device__ __forceinline__ void gridbar() {
    __syncthreads();
    if (threadIdx.x == 0) {
        __threadfence();
        unsigned gen = atomicAdd(&g_gen, 0u);
        if (atomicAdd(&g_cnt, 1u) == GRIDB - 1u) {
            g_cnt = 0u;
            __threadfence();
            atomicExch(&g_gen, gen + 1u);
        } else {
            while (atomicAdd(&g_gen, 0u) == gen) { __nanosleep(64); }
        }
    }
    __syncthreads();
}

__device__ __forceinline__ float sigmoidf_(float x) { return 1.f/(1.f + expf(-x)); }

// ---------------- persistent scan + fused logits-p1 workers ----------------
__global__ void __launch_bounds__(256, 2) k_scan(const float* __restrict__ iface,
                                                 const float* __restrict__ b_if,
                                                 const float* __restrict__ brp,
                                                 const float* __restrict__ bwp,
                                                 const float* __restrict__ bias,
                                                 float* __restrict__ out) {
    __shared__ __align__(16) char smraw[sizeof(GemmSm)];
    __shared__ int s_tile;
    const int blk = blockIdx.x, tid = threadIdx.x;

    // ---------- worker role: logits GEMM part-1 (K<512) ----------
    if (blk >= GRIDB) {
        GemmSm* gsm = reinterpret_cast<GemmSm*>(smraw);
        for (;;) {
            if (tid == 0) s_tile = (int)atomicAdd(&g_tile, 1u);
            __syncthreads();
            int tl = s_tile;
            if (tl >= NTILE) break;
            lgemm_tile(gsm, (tl/250)*128, (tl%250)*128, 0, 16, bias, out, 0);
            __syncthreads();
        }
        return;
    }

    // ---------- scan role ----------
    ScanSm& S = *reinterpret_cast<ScanSm*>(smraw);
    const int warp = tid >> 5, lane = tid & 31;

    float beta_r, beta_w;
    {
        float b0 = *brp; b0 = log1pf(expf(b0)); beta_r = fminf(fmaxf(b0, 1.f), 20.f);
        float b1 = *bwp; b1 = log1pf(expf(b1)); beta_w = fminf(fmaxf(b1, 1.f), 20.f);
    }
    const int s_bh = blk >> 2, s_sub = blk & 3;
    const int s_b = s_bh >> 2, s_h = s_bh & 3;
    const int c_b = blk >> 2, c_h = blk & 3;   // valid when blk < 32
    const int c_bh = blk;                      // == c_b*4 + c_h when blk<32

    for (int t = 0; t < Tt; t++) {
        const float* ib = g_ibuf[t & 1];
        // ---------- SIM (all 128 scan blocks, coalesced over memT) ----------
        {
            if (tid < 128) {
                int rw = tid >> 6, d = tid & 63;
                float kx = ib[s_b*IFc + rw*Dd + s_h*64 + d];
                if (rw) S.skw[d] = kx; else S.skr[d] = kx;
                S.kq[tid] = kx*kx;
            }
            __syncthreads();
            if (tid < 2) {
                float s = 0.f;
                for (int d2 = 0; d2 < 64; d2++) s += S.kq[tid*64 + d2];
                S.s_scal[tid] = rsqrtf(s + 1e-8f);
            }
            __syncthreads();
            if (tid < 128) {
                int rw = tid >> 6, d = tid & 63;
                if (rw) S.skw[d] *= S.s_scal[1]; else S.skr[d] *= S.s_scal[0];
            }
            __syncthreads();
            int nbase = s_sub*512;
            const float* mt = g_memT + (size_t)s_bh*64*Nn + nbase;
            float ar0 = 0.f, aw0 = 0.f, ar1 = 0.f, aw1 = 0.f;
#pragma unroll 8
            for (int d = 0; d < 64; d++) {
                float kr = S.skr[d], kw = S.skw[d];
                float m0 = mt[(size_t)d*Nn + tid];
                float m1 = mt[(size_t)d*Nn + tid + 256];
                ar0 += m0*kr; aw0 += m0*kw;
                ar1 += m1*kr; aw1 += m1*kw;
            }
            int n1 = nbase + tid, n2 = n1 + 256;
            float i1 = rsqrtf(g_sumsq[s_bh*Nn + n1] + 1e-8f);
            float i2 = rsqrtf(g_sumsq[s_bh*Nn + n2] + 1e-8f);
            g_sim[(size_t)s_bh*Nn + n1]        = ar0 * i1;
            g_sim[(size_t)s_bh*Nn + n2]        = ar1 * i2;
            g_sim[(size_t)(32 + s_bh)*Nn + n1] = aw0 * i1;
            g_sim[(size_t)(32 + s_bh)*Nn + n2] = aw1 * i2;
        }
        gridbar();
        // ---------- topk + rv + mem update (blocks 0..31) ----------
        if (blk < 32) {
            for (int rw = 0; rw < 2; rw++) {
                float beta = rw ? beta_w : beta_r;
                const float* s0 = g_sim + ((size_t)(rw*32 + blk))*Nn;
                float v[8];
#pragma unroll
                for (int j2 = 0; j2 < 8; j2++) { v[j2] = s0[tid + 256*j2]; S.ssim[tid + 256*j2] = v[j2]; }
                if (tid == 0) S.s_cnt = 0;
                __syncthreads();
                for (int k = 0; k < TOPK; k++) {
                    float bv = -3.4e38f; int bi = 0;
#pragma unroll
                    for (int j2 = 0; j2 < 8; j2++) if (v[j2] > bv) { bv = v[j2]; bi = tid + 256*j2; }
#pragma unroll
                    for (int off = 16; off > 0; off >>= 1) {
                        float ov = __shfl_down_sync(0xffffffffu, bv, off);
                        int   oi = __shfl_down_sync(0xffffffffu, bi, off);
                        if (ov > bv) { bv = ov; bi = oi; }
                    }
                    if (lane == 0) { S.rv8[warp] = bv; S.ri8[warp] = bi; }
                    __syncthreads();
                    if (tid == 0) {
                        float mv = S.rv8[0]; int mi = S.ri8[0];
                        for (int w2 = 1; w2 < 8; w2++) if (S.rv8[w2] > mv) { mv = S.rv8[w2]; mi = S.ri8[w2]; }
                        if (k == 0)       S.s_scal[0] = mv;
                        if (k == TOPK-1)  S.s_scal[1] = mv;
                        S.s_win = mi;
                    }
                    __syncthreads();
                    int wn = S.s_win;
                    if ((wn & 255) == tid) v[wn >> 8] = -3.4e38f;
                }
                float smax = S.s_scal[0], kth = S.s_scal[1];
#pragma unroll
                for (int j2 = 0; j2 < 8; j2++) {
                    int n = tid + 256*j2;
                    float sv = S.ssim[n];
                    if (sv >= kth) {
                        int p = atomicAdd(&S.s_cnt, 1);
                        if (p < 48) { S.li[p] = n; S.lw[p] = expf(beta*(sv - smax)); }
                    }
                }
                __syncthreads();
                int ln = S.s_cnt < 48 ? S.s_cnt : 48;
                if (tid == 0) {
                    for (int a2 = 1; a2 < ln; a2++) {
                        int key = S.li[a2]; float kw2 = S.lw[a2]; int c2s = a2 - 1;
                        while (c2s >= 0 && S.li[c2s] > key) { S.li[c2s+1] = S.li[c2s]; S.lw[c2s+1] = S.lw[c2s]; c2s--; }
                        S.li[c2s+1] = key; S.lw[c2s+1] = kw2;
                    }
                    float s = 0.f;
                    for (int j = 0; j < ln; j++) s += S.lw[j];
                    S.s_scal[2] = 1.f / s;
                }
                __syncthreads();
                float invs = S.s_scal[2];
                if (rw == 0) {
                    // rv gather: 4 j-groups x 64 d
                    {
                        int d = tid & 63, jj = tid >> 6;
                        float part = 0.f;
                        for (int j = jj; j < ln; j += 4)
                            part += (S.lw[j]*invs) * g_mem[((size_t)(c_b*Nn + S.li[j]))*Dd + c_h*64 + d];
                        S.rvred[jj][d] = part;
                    }
                    __syncthreads();
                    if (tid < 64) {
                        float acc = S.rvred[0][tid] + S.rvred[1][tid] + S.rvred[2][tid] + S.rvred[3][tid];
                        g_rv[c_b*Dd + c_h*64 + tid] = acc;
                        if (t + 1 < Tt) g_rvhist[((size_t)(c_b*Tt + t + 1))*Dd + c_h*64 + tid] = acc;
                    }
                    __syncthreads();
                } else {
                    float gh   = sigmoidf_(ib[c_b*IFc + 4*Dd + c_h]);
                    float er0  = sigmoidf_(ib[c_b*IFc + 3*Dd + c_h*64 + lane]);
                    float er1  = sigmoidf_(ib[c_b*IFc + 3*Dd + c_h*64 + lane + 32]);
                    float val0 = ib[c_b*IFc + 2*Dd + c_h*64 + lane];
                    float val1 = ib[c_b*IFc + 2*Dd + c_h*64 + lane + 32];
                    for (int j = warp; j < ln; j += 8) {
                        int n = S.li[j]; float w = S.lw[j]*invs;
                        size_t base = ((size_t)(c_b*Nn + n))*Dd + c_h*64;
                        float m0 = g_mem[base + lane], m1 = g_mem[base + lane + 32];
                        float nm0 = m0*(1.f - w*er0) + w*(gh*val0);
                        float nm1 = m1*(1.f - w*er1) + w*(gh*val1);
                        g_mem[base + lane] = nm0;
                        g_mem[base + lane + 32] = nm1;
                        g_memT[((size_t)c_bh*64 + lane)*Nn + n]      = nm0;
                        g_memT[((size_t)c_bh*64 + lane + 32)*Nn + n] = nm1;
                        float ss2 = nm0*nm0 + nm1*nm1;
#pragma unroll
                        for (int off = 16; off > 0; off >>= 1) ss2 += __shfl_down_sync(0xffffffffu, ss2, off);
                        if (lane == 0) g_sumsq[c_bh*Nn + n] = ss2;
                    }
                    __syncthreads();
                }
            }
        }
        gridbar();
        // ---------- iface for t+1 ----------
        if (t + 1 < Tt) {
            for (int idx = blk*256 + tid; idx < Bb*IFc; idx += GRIDB*256) {
                int b2 = idx / IFc, c = idx - b2*IFc;
                float acc = iface[((size_t)(b2*Tt + t + 1))*IFc + c] + b_if[c];
                const float4* wp = (const float4*)(g_wifrT + (size_t)c*Dd);
                const float4* rp = (const float4*)(g_rv + b2*Dd);
#pragma unroll 8
                for (int d4 = 0; d4 < Dd/4; d4++) {
                    float4 w4 = wp[d4], r4 = rp[d4];
                    acc += r4.x*w4.x + r4.y*w4.y + r4.z*w4.z + r4.w*w4.w;
                }
                g_ibuf[(t + 1) & 1][idx] = acc;
            }
        }
        gridbar();
    }
}

static float* addr_of(const void* symbol) {
    void* p = nullptr;
    cudaGetSymbolAddress(&p, symbol);
    return (float*)p;
}

extern "C" void kernel_launch(void* const* d_in, const int* in_sizes, int n_in,
                              void* d_out, int out_size) {
    const int*   input_seq = (const int*)  d_in[0];
    const float* emb       = (const float*)d_in[1];
    const float* pos       = (const float*)d_in[2];
    const float* ln1_g     = (const float*)d_in[3];
    const float* ln1_b     = (const float*)d_in[4];
    const float* ln2_g     = (const float*)d_in[5];
    const float* ln2_b     = (const float*)d_in[6];
    const float* Wq        = (const float*)d_in[7];
    const float* Wk        = (const float*)d_in[8];
    const float* Wv        = (const float*)d_in[9];
    const float* Wo        = (const float*)d_in[10];
    const float* W1        = (const float*)d_in[11];
    const float* b1        = (const float*)d_in[12];
    const float* W2        = (const float*)d_in[13];
    const float* b2        = (const float*)d_in[14];
    const float* lnf_g     = (const float*)d_in[15];
    const float* lnf_b     = (const float*)d_in[16];
    const float* W_if_h    = (const float*)d_in[17];
    const float* W_if_r    = (const float*)d_in[18];
    const float* b_if      = (const float*)d_in[19];
    const float* W_lg_h    = (const float*)d_in[20];
    const float* W_lg_r    = (const float*)d_in[21];
    const float* b_lg      = (const float*)d_in[22];
    const float* beta_read = (const float*)d_in[23];
    const float* beta_write= (const float*)d_in[24];
    const float* mem_init  = (const float*)d_in[25];
    float* out = (float*)d_out;

    static float* p_x = nullptr, *p_h, *p_q, *p_k, *p_v, *p_attno, *p_hf, *p_ffn, *p_iface;
    if (!p_x) {
        p_x      = addr_of(g_x);      p_h     = addr_of(g_h);
        p_q      = addr_of(g_q);      p_k     = addr_of(g_k);
        p_v      = addr_of(g_v);      p_attno = addr_of(g_attno);
        p_hf     = addr_of(g_hf);     p_ffn   = addr_of(g_ffn);
        p_iface  = addr_of(g_iface);
    }

    k_embed<<<2048, 256>>>(input_seq, emb, pos);
    k_convW<<<dim3(Vv/32, KTOT/32), dim3(32,8)>>>(W_lg_h, W_lg_r);
    k_twifr<<<dim3((IFc+31)/32, Dd/32), dim3(32,8)>>>(W_if_r);

    dim3 gE(4, 32);
    dim3 gF(16, 16);
    for (int l = 0; l < Ll; l++) {
        k_ln<<<Mrows, 256>>>(p_x, p_h, ln1_g + l*Ee, ln1_b + l*Ee);
        k_gemm<64,4><<<gE, 256>>>(p_h, Wq + (size_t)l*Ee*Ee, nullptr, nullptr, p_q, Mrows, Ee, Ee, 0);
        k_gemm<64,4><<<gE, 256>>>(p_h, Wk + (size_t)l*Ee*Ee, nullptr, nullptr, p_k, Mrows, Ee, Ee, 0);
        k_gemm<64,4><<<gE, 256>>>(p_h, Wv + (size_t)l*Ee*Ee, nullptr, nullptr, p_v, Mrows, Ee, Ee, 0);
        k_attn<<<dim3(Tt, HA, Bb), 256>>>();
        k_gemm<64,4><<<gE, 256>>>(p_attno, Wo + (size_t)l*Ee*Ee, nullptr, p_x, p_x, Mrows, Ee, Ee, 0);
        k_ln<<<Mrows, 256>>>(p_x, p_h, ln2_g + l*Ee, ln2_b + l*Ee);
        k_gemm<128,8><<<gF, 256>>>(p_h, W1 + (size_t)l*Ee*Ff, b1 + l*Ff, nullptr, p_ffn, Mrows, Ee, Ff, 1);
        k_gemm<64,4><<<gE, 256>>>(p_ffn, W2 + (size_t)l*Ff*Ee, b2 + l*Ee, p_x, p_x, Mrows, Ff, Ee, 0);
    }

    k_ln<<<Mrows, 256>>>(p_x, p_hf, lnf_g, lnf_b);
    k_gemm<128,8><<<dim3(9, 16), 256>>>(p_hf, W_if_h, nullptr, nullptr, p_iface, Mrows, Ee, IFc, 0);

    // A-split for the h_f-dependent 2/3 of the logits GEMM
    k_convA1<<<2048, 256>>>();

    // ---- scan + overlapped logits part-1 (one fused kernel) ----
    k_scan_init<<<2048, 256>>>(mem_init, p_iface, b_if);
    k_scan<<<GRIDB + WORKERS, 256>>>(p_iface, b_if, beta_read, beta_write, b_lg, out);

    // ---- rvhist-dependent remainder ----
    k_convA2<<<2048, 256>>>();
    k_lgemm2<<<dim3(250, 16), 256>>>(out);
}

// round 7
// speedup vs baseline: 1.7070x; 1.0342x over previous
#include <cuda_runtime.h>
#include <cuda_bf16.h>
#include <math.h>
#include <stdint.h>

// ---------------- problem constants ----------------
#define Vv 32000
#define Ee 512
#define Ff 2048
#define Dd 256
#define Nn 2048
#define Ll 2
#define Bb 8
#define Tt 256
#define HM 4
#define TOPK 8
#define HA 8
#define HD 64
#define DH 64
#define IFc 1028
#define Mrows (Bb*Tt)
#define GRIDB 128
#define WORKERS 168
#define KTOT 768
#define NT_P1 4000       // 250 n-tiles x 16 m-tiles, K<512
#define NT_TOT 8000      // + 4000 p2 tiles (K 512..767)

// ---------------- scratch ----------------
__device__ float g_x[Mrows*Ee];
__device__ float g_h[Mrows*Ee];
__device__ float g_q[Mrows*Ee];
__device__ float g_k[Mrows*Ee];
__device__ float g_v[Mrows*Ee];
__device__ float g_attno[Mrows*Ee];
__device__ float g_hf[Mrows*Ee];
__device__ float g_ffn[Mrows*Ff];
__device__ float g_iface[Mrows*IFc];
__device__ float g_mem[Bb*Nn*Dd];            // [b][n][h*64+d]
__device__ float g_memT[32*64*Nn];           // [bh][d][n]
__device__ float g_sumsq[32*Nn];             // [bh][n]
__device__ float g_rv[Bb*Dd];
__device__ float g_ibuf[2][Bb*IFc];
__device__ float g_sim[2*Bb*HM*Nn];
__device__ float g_wifrT[IFc*Dd];
__device__ __nv_bfloat16 g_Whi[(size_t)Vv*KTOT];
__device__ __nv_bfloat16 g_Wlo[(size_t)Vv*KTOT];
__device__ __nv_bfloat16 g_Ab[(size_t)Mrows*2*KTOT]; // [m][hi(768) | lo(768)]
__device__ unsigned g_cnt;
__device__ unsigned g_gen;
__device__ unsigned g_tile;

// ---------------- embedding ----------------
__global__ void k_embed(const int* __restrict__ seq, const float* __restrict__ emb,
                        const float* __restrict__ pos) {
    int stride = gridDim.x * blockDim.x;
    for (int idx = blockIdx.x*blockDim.x + threadIdx.x; idx < Mrows*Ee; idx += stride) {
        int e  = idx % Ee;
        int bt = idx / Ee;
        int t  = bt % Tt;
        g_x[idx] = emb[(size_t)seq[bt]*Ee + e] + pos[t*Ee + e];
    }
}

// ---------------- layernorm ----------------
__global__ void k_ln(const float* __restrict__ in, float* __restrict__ outp,
                     const float* __restrict__ g, const float* __restrict__ b) {
    int row = blockIdx.x;
    int tid = threadIdx.x;
    const float* x = in + (size_t)row*Ee;
    __shared__ float red[256];
    float v0 = x[tid], v1 = x[tid+256];
    red[tid] = v0 + v1;
    __syncthreads();
    for (int s = 128; s > 0; s >>= 1) { if (tid < s) red[tid] += red[tid+s]; __syncthreads(); }
    float mean = red[0] * (1.f/Ee);
    __syncthreads();
    float d0 = v0 - mean, d1 = v1 - mean;
    red[tid] = d0*d0 + d1*d1;
    __syncthreads();
    for (int s = 128; s > 0; s >>= 1) { if (tid < s) red[tid] += red[tid+s]; __syncthreads(); }
    float inv = rsqrtf(red[0] * (1.f/Ee) + 1e-5f);
    outp[(size_t)row*Ee + tid]       = d0*inv*g[tid]     + b[tid];
    outp[(size_t)row*Ee + tid + 256] = d1*inv*g[tid+256] + b[tid+256];
}

__device__ __forceinline__ float geluf_(float xx) {
    float tt = tanhf(0.7978845608028654f * (xx + 0.044715f*xx*xx*xx));
    return 0.5f * xx * (1.f + tt);
}

// ---------------- SIMT GEMM (transformer-sized) ----------------
template<int BM, int TM>
__global__ void __launch_bounds__(256) k_gemm(const float* __restrict__ A, const float* __restrict__ W,
                       const float* __restrict__ bias, const float* __restrict__ res,
                       float* __restrict__ C, int M, int K, int N, int act) {
    __shared__ float As[2][16][BM];
    __shared__ float Bs[2][16][128];
    const int tid = threadIdx.x;
    const int bm = blockIdx.y * BM, bn = blockIdx.x * 128;
    const int tx = tid & 15, ty = tid >> 4;
    constexpr int AV = BM/64;
    float4 aR[AV], bR[2];
    float acc[TM][8];
#pragma unroll
    for (int i = 0; i < TM; i++)
#pragma unroll
        for (int j = 0; j < 8; j++) acc[i][j] = 0.f;

    auto ldg = [&](int k0) {
#pragma unroll
        for (int v = 0; v < AV; v++) {
            int i = tid + v*256;
            int row = i >> 2, cg = i & 3;
            aR[v] = *(const float4*)(A + (size_t)(bm+row)*K + k0 + cg*4);
        }
#pragma unroll
        for (int v = 0; v < 2; v++) {
            int i = tid + v*256;
            int row = i >> 5, cg = i & 31;
            int col = bn + cg*4;
            if (col < N) bR[v] = *(const float4*)(W + (size_t)(k0+row)*N + col);
            else { bR[v].x = bR[v].y = bR[v].z = bR[v].w = 0.f; }
        }
    };
    auto sts = [&](int buf) {
#pragma unroll
        for (int v = 0; v < AV; v++) {
            int i = tid + v*256;
            int row = i >> 2, cg = i & 3;
            As[buf][cg*4+0][row] = aR[v].x; As[buf][cg*4+1][row] = aR[v].y;
            As[buf][cg*4+2][row] = aR[v].z; As[buf][cg*4+3][row] = aR[v].w;
        }
#pragma unroll
        for (int v = 0; v < 2; v++) {
            int i = tid + v*256;
            int row = i >> 5, cg = i & 31;
            *(float4*)&Bs[buf][row][cg*4] = bR[v];
        }
    };
    auto comp = [&](int buf) {
#pragma unroll
        for (int kk = 0; kk < 16; kk++) {
            float a[TM], bfr[8];
#pragma unroll
            for (int v = 0; v < TM/4; v++)
                *(float4*)&a[v*4] = *(const float4*)&As[buf][kk][ty*TM + v*4];
            *(float4*)&bfr[0] = *(const float4*)&Bs[buf][kk][tx*8];
            *(float4*)&bfr[4] = *(const float4*)&Bs[buf][kk][tx*8+4];
#pragma unroll
            for (int i = 0; i < TM; i++)
#pragma unroll
                for (int j = 0; j < 8; j++) acc[i][j] += a[i]*bfr[j];
        }
    };

    ldg(0); sts(0); __syncthreads();
    int cur = 0;
    for (int k0 = 16; k0 < K; k0 += 16) {
        ldg(k0);
        comp(cur);
        sts(cur^1);
        __syncthreads();
        cur ^= 1;
    }
    comp(cur);

#pragma unroll
    for (int i = 0; i < TM; i++) {
        int row = bm + ty*TM + i;
#pragma unroll
        for (int jv = 0; jv < 2; jv++) {
            int col = bn + tx*8 + jv*4;
            if (col < N) {
                float4 v4;
                v4.x = acc[i][jv*4+0]; v4.y = acc[i][jv*4+1];
                v4.z = acc[i][jv*4+2]; v4.w = acc[i][jv*4+3];
                if (bias) { v4.x += bias[col]; v4.y += bias[col+1]; v4.z += bias[col+2]; v4.w += bias[col+3]; }
                if (act == 1) { v4.x = geluf_(v4.x); v4.y = geluf_(v4.y); v4.z = geluf_(v4.z); v4.w = geluf_(v4.w); }
                if (res) {
                    float4 r4 = *(const float4*)&res[(size_t)row*N + col];
                    v4.x += r4.x; v4.y += r4.y; v4.z += r4.z; v4.w += r4.w;
                }
                *(float4*)&C[(size_t)row*N + col] = v4;
            }
        }
    }
}

// ---------------- attention ----------------
__global__ void k_attn() {
    int t = blockIdx.x, hh = blockIdx.y, b = blockIdx.z;
    int tid = threadIdx.x;
    __shared__ float sq[64];
    __shared__ float ss[256];
    __shared__ float red[256];
    const float* qrow = g_q + ((size_t)(b*Tt + t))*Ee + hh*DH;
    if (tid < 64) sq[tid] = qrow[tid];
    __syncthreads();
    float lmax = -3.4e38f;
    for (int j = tid; j <= t; j += 256) {
        const float* krow = g_k + ((size_t)(b*Tt + j))*Ee + hh*DH;
        float d = 0.f;
#pragma unroll
        for (int e = 0; e < 64; e++) d += sq[e]*krow[e];
        d *= 0.125f;
        ss[j] = d;
        lmax = fmaxf(lmax, d);
    }
    red[tid] = lmax;
    __syncthreads();
    for (int s = 128; s > 0; s >>= 1) { if (tid < s) red[tid] = fmaxf(red[tid], red[tid+s]); __syncthreads(); }
    float mx = red[0];
    __syncthreads();
    float lsum = 0.f;
    for (int j = tid; j <= t; j += 256) { float p = expf(ss[j]-mx); ss[j] = p; lsum += p; }
    red[tid] = lsum;
    __syncthreads();
    for (int s = 128; s > 0; s >>= 1) { if (tid < s) red[tid] += red[tid+s]; __syncthreads(); }
    float inv = 1.f / red[0];
    __syncthreads();
    if (tid < 64) {
        float acc = 0.f;
        for (int j = 0; j <= t; j++)
            acc += ss[j] * g_v[((size_t)(b*Tt + j))*Ee + hh*DH + tid];
        g_attno[((size_t)(b*Tt + t))*Ee + hh*DH + tid] = acc * inv;
    }
}

// ---------------- W_lg split + transpose ----------------
__global__ void k_convW(const float* __restrict__ Wh, const float* __restrict__ Wr) {
    __shared__ float tile[32][33];
    int nt = blockIdx.x*32, kt = blockIdx.y*32;
    int tx = threadIdx.x, ty = threadIdx.y;
#pragma unroll
    for (int r = 0; r < 32; r += 8) {
        int k = kt + ty + r, n = nt + tx;
        float v = (k < 512) ? Wh[(size_t)k*Vv + n] : Wr[(size_t)(k-512)*Vv + n];
        tile[ty+r][tx] = v;
    }
    __syncthreads();
#pragma unroll
    for (int r = 0; r < 32; r += 8) {
        int n = nt + ty + r, k = kt + tx;
        float v = tile[tx][ty+r];
        __nv_bfloat16 hi = __float2bfloat16(v);
        __nv_bfloat16 lo = __float2bfloat16(v - __bfloat162float(hi));
        g_Whi[(size_t)n*KTOT + k] = hi;
        g_Wlo[(size_t)n*KTOT + k] = lo;
    }
}

// ---------------- A split (h_f part) ----------------
__global__ void k_convA1() {
    int stride = gridDim.x*blockDim.x;
    for (int idx = blockIdx.x*blockDim.x + threadIdx.x; idx < Mrows*512; idx += stride) {
        int m = idx >> 9, k = idx & 511;
        float v = g_hf[(size_t)m*Ee + k];
        __nv_bfloat16 hi = __float2bfloat16(v);
        __nv_bfloat16 lo = __float2bfloat16(v - __bfloat162float(hi));
        g_Ab[(size_t)m*(2*KTOT) + k]        = hi;
        g_Ab[(size_t)m*(2*KTOT) + KTOT + k] = lo;
    }
}

// ---------------- transpose W_if_r ----------------
__global__ void k_twifr(const float* __restrict__ W) {
    __shared__ float tile[32][33];
    int ct = blockIdx.x*32, dt = blockIdx.y*32;
    int tx = threadIdx.x, ty = threadIdx.y;
#pragma unroll
    for (int r = 0; r < 32; r += 8) {
        int d = dt + ty + r, c = ct + tx;
        tile[ty+r][tx] = (c < IFc) ? W[(size_t)d*IFc + c] : 0.f;
    }
    __syncthreads();
#pragma unroll
    for (int r = 0; r < 32; r += 8) {
        int c = ct + ty + r, d = dt + tx;
        if (c < IFc) g_wifrT[(size_t)c*Dd + d] = tile[tx][ty+r];
    }
}

// ---------------- bf16 mma.sync ----------------
__device__ __forceinline__ void mma16816(float* c, const uint32_t* a, const uint32_t* b) {
    asm volatile(
        "mma.sync.aligned.m16n8k16.row.col.f32.bf16.bf16.f32 "
        "{%0,%1,%2,%3}, {%4,%5,%6,%7}, {%8,%9}, {%0,%1,%2,%3};"
        : "+f"(c[0]), "+f"(c[1]), "+f"(c[2]), "+f"(c[3])
        : "r"(a[0]), "r"(a[1]), "r"(a[2]), "r"(a[3]), "r"(b[0]), "r"(b[1]));
}

// ---------------- shared layouts ----------------
struct GemmSm {
    __nv_bfloat16 As[2][128][40];
    __nv_bfloat16 Bs[2][128][40];
};
struct ScanSm {
    float ssim2[2][Nn];                  // 16 KB
    float skr[64], skw[64];
    float kq[128];
    float wtop[2][4][8]; int witop[2][4][8];
    float lw2[2][48]; int li2[2][48];
    int cnt[2];
    float scal2[2][4];                   // smax, kth, invsum
    float s_scal[4];
    float rvred[4][64];
};

// ---------------- one 128x128 logits tile ----------------
__device__ void lgemm_tile(GemmSm* sm, int m0, int n0, int kb, int nseg,
                           const float* __restrict__ bias, float* __restrict__ C, int accum) {
    const int tid = threadIdx.x, wid = tid >> 5, lane = tid & 31;
    const int wm = (wid & 1) * 64, wn = (wid >> 1) * 32;
    const int r = lane >> 2, c2 = (lane & 3) * 2;
    const int nchunks = nseg * 3;

    float acc[4][4][4];
#pragma unroll
    for (int mi = 0; mi < 4; mi++)
#pragma unroll
        for (int ni = 0; ni < 4; ni++)
#pragma unroll
            for (int j = 0; j < 4; j++) acc[mi][ni][j] = 0.f;

    uint4 aR[2], bR[2];
    auto ldg = [&](int c) {
        int seg = c / nseg, kin = kb + (c - seg*nseg)*32;
        const __nv_bfloat16* Aseg = g_Ab + (seg == 2 ? KTOT : 0);
        const __nv_bfloat16* Wseg = (seg == 1) ? g_Wlo : g_Whi;
#pragma unroll
        for (int v = 0; v < 2; v++) {
            int i = tid + v*256;
            int row = i >> 2, cg = i & 3;
            aR[v] = *(const uint4*)(Aseg + (size_t)(m0+row)*(2*KTOT) + kin + cg*8);
            bR[v] = *(const uint4*)(Wseg + (size_t)(n0+row)*KTOT    + kin + cg*8);
        }
    };
    auto sts = [&](int buf) {
#pragma unroll
        for (int v = 0; v < 2; v++) {
            int i = tid + v*256;
            int row = i >> 2, cg = i & 3;
            *(uint4*)&sm->As[buf][row][cg*8] = aR[v];
            *(uint4*)&sm->Bs[buf][row][cg*8] = bR[v];
        }
    };
    auto comp = [&](int buf) {
#pragma unroll
        for (int kt = 0; kt < 32; kt += 16) {
            uint32_t af[4][4], bfv[4][2];
#pragma unroll
            for (int mi = 0; mi < 4; mi++) {
                af[mi][0] = *(const uint32_t*)&sm->As[buf][wm + mi*16 + r    ][kt + c2];
                af[mi][1] = *(const uint32_t*)&sm->As[buf][wm + mi*16 + r + 8][kt + c2];
                af[mi][2] = *(const uint32_t*)&sm->As[buf][wm + mi*16 + r    ][kt + c2 + 8];
                af[mi][3] = *(const uint32_t*)&sm->As[buf][wm + mi*16 + r + 8][kt + c2 + 8];
            }
#pragma unroll
            for (int ni = 0; ni < 4; ni++) {
                bfv[ni][0] = *(const uint32_t*)&sm->Bs[buf][wn + ni*8 + r][kt + c2];
                bfv[ni][1] = *(const uint32_t*)&sm->Bs[buf][wn + ni*8 + r][kt + c2 + 8];
            }
#pragma unroll
            for (int mi = 0; mi < 4; mi++)
#pragma unroll
                for (int ni = 0; ni < 4; ni++)
                    mma16816(acc[mi][ni], af[mi], bfv[ni]);
        }
    };

    ldg(0); sts(0); __syncthreads();
    int cur = 0;
    for (int c = 1; c < nchunks; c++) {
        ldg(c);
        comp(cur);
        sts(cur^1);
        __syncthreads();
        cur ^= 1;
    }
    comp(cur);

#pragma unroll
    for (int mi = 0; mi < 4; mi++) {
        int row0 = m0 + wm + mi*16 + r;
#pragma unroll
        for (int ni = 0; ni < 4; ni++) {
            int col = n0 + wn + ni*8 + c2;
            float2 v0, v1;
            if (accum) {
                float2 o0 = *(const float2*)&C[(size_t)row0*Vv + col];
                float2 o1 = *(const float2*)&C[(size_t)(row0+8)*Vv + col];
                v0.x = acc[mi][ni][0] + o0.x; v0.y = acc[mi][ni][1] + o0.y;
                v1.x = acc[mi][ni][2] + o1.x; v1.y = acc[mi][ni][3] + o1.y;
            } else {
                v0.x = acc[mi][ni][0] + bias[col]; v0.y = acc[mi][ni][1] + bias[col+1];
                v1.x = acc[mi][ni][2] + bias[col]; v1.y = acc[mi][ni][3] + bias[col+1];
            }
            *(float2*)&C[(size_t)row0*Vv + col]     = v0;
            *(float2*)&C[(size_t)(row0+8)*Vv + col] = v1;
        }
    }
}

// ---------------- worker loop: p1 tiles then gated p2 tiles ----------------
__device__ void worker_loop(GemmSm* gsm, volatile int* s_tile,
                            const float* __restrict__ bias, float* __restrict__ out) {
    const int tid = threadIdx.x;
    for (;;) {
        if (tid == 0) *s_tile = (int)atomicAdd(&g_tile, 1u);
        __syncthreads();
        int tl = *s_tile;
        if (tl >= NT_TOT) break;
        if (tl < NT_P1) {
            lgemm_tile(gsm, (tl/250)*128, (tl%250)*128, 0, 16, bias, out, 0);
        } else {
            int id = tl - NT_P1;
            int grp = id / 250, nt = id % 250;
            int mt = (grp < 8) ? (2*grp) : (2*(grp-8)+1);
            unsigned need = (mt & 1) ? 764u : 380u;
            if (tid == 0) { while (atomicAdd(&g_gen, 0u) < need) __nanosleep(256); }
            __syncthreads();
            __threadfence();
            lgemm_tile(gsm, mt*128, nt*128, 512, 8, nullptr, out, 1);
        }
        __syncthreads();
    }
}

// ---------------- scan init ----------------
__global__ void k_scan_init(const float* __restrict__ mem_init, const float* __restrict__ iface,
                            const float* __restrict__ b_if) {
    int stride = gridDim.x*blockDim.x;
    int tid0 = blockIdx.x*blockDim.x + threadIdx.x;
    for (int idx = tid0; idx < Bb*Nn*Dd; idx += stride)
        g_mem[idx] = mem_init[idx % (Nn*Dd)];
    for (int idx = tid0; idx < 32*64*Nn; idx += stride) {
        int n = idx & (Nn-1);
        int rest = idx >> 11;
        int d = rest & 63;
        int bh = rest >> 6;
        int h = bh & 3;
        g_memT[idx] = mem_init[(size_t)n*Dd + h*64 + d];
    }
    for (int idx = tid0; idx < 32*Nn; idx += stride) {
        int n = idx & (Nn-1);
        int bh = idx >> 11;
        int h = bh & 3;
        const float* r = mem_init + (size_t)n*Dd + h*HD;
        float s = 0.f;
#pragma unroll
        for (int d = 0; d < HD; d++) s += r[d]*r[d];
        g_sumsq[idx] = s;
    }
    for (int idx = tid0; idx < Bb*IFc; idx += stride) {
        int b = idx / IFc, c = idx - b*IFc;
        g_ibuf[0][idx] = iface[((size_t)(b*Tt))*IFc + c] + b_if[c];
    }
    for (int idx = tid0; idx < Bb*Dd; idx += stride) {
        g_rv[idx] = 0.f;
        // t=0 rows of the rv part of A are zeros
        int b = idx / Dd, kk = idx % Dd;
        size_t m = (size_t)b*Tt;
        __nv_bfloat16 z = __float2bfloat16(0.f);
        g_Ab[m*(2*KTOT) + 512 + kk]        = z;
        g_Ab[m*(2*KTOT) + KTOT + 512 + kk] = z;
    }
    if (tid0 == 0) { g_cnt = 0u; g_gen = 0u; g_tile = 0u; }
}

// ---------------- software grid barrier (scan blocks only) ----------------
__device__ __forceinline__ void gridbar() {
    __syncthreads();
    if (threadIdx.x == 0) {
        __threadfence();
        unsigned gen = atomicAdd(&g_gen, 0u);
        if (atomicAdd(&g_cnt, 1u) == GRIDB - 1u) {
            g_cnt = 0u;
            __threadfence();
            atomicExch(&g_gen, gen + 1u);
        } else {
            while (atomicAdd(&g_gen, 0u) == gen) { __nanosleep(64); }
        }
    }
    __syncthreads();
}

__device__ __forceinline__ float sigmoidf_(float x) { return 1.f/(1.f + expf(-x)); }

// ---------------- persistent scan + fused logits workers ----------------
__global__ void __launch_bounds__(256, 2) k_scan(const float* __restrict__ iface,
                                                 const float* __restrict__ b_if,
                                                 const float* __restrict__ brp,
                                                 const float* __restrict__ bwp,
                                                 const float* __restrict__ bias,
                                                 float* __restrict__ out) {
    __shared__ __align__(16) char smraw[sizeof(GemmSm)];
    __shared__ int s_tile;
    const int blk = blockIdx.x, tid = threadIdx.x;
    GemmSm* gsm = reinterpret_cast<GemmSm*>(smraw);

    if (blk >= GRIDB) {                 // dedicated workers
        worker_loop(gsm, &s_tile, bias, out);
        return;
    }

    // ---------- scan role ----------
    ScanSm& S = *reinterpret_cast<ScanSm*>(smraw);
    const int warp = tid >> 5, lane = tid & 31;

    float beta_r, beta_w;
    {
        float b0 = *brp; b0 = log1pf(expf(b0)); beta_r = fminf(fmaxf(b0, 1.f), 20.f);
        float b1 = *bwp; b1 = log1pf(expf(b1)); beta_w = fminf(fmaxf(b1, 1.f), 20.f);
    }
    const int s_bh = blk >> 2, s_sub = blk & 3;
    const int s_b = s_bh >> 2, s_h = s_bh & 3;
    const int c_b = blk >> 2, c_h = blk & 3;   // valid when blk < 32
    const int c_bh = blk;

    for (int t = 0; t < Tt; t++) {
        const float* ib = g_ibuf[t & 1];
        // ---------- SIM ----------
        {
            if (tid < 128) {
                int rw = tid >> 6, d = tid & 63;
                float kx = ib[s_b*IFc + rw*Dd + s_h*64 + d];
                if (rw) S.skw[d] = kx; else S.skr[d] = kx;
                S.kq[tid] = kx*kx;
            }
            __syncthreads();
            if (tid < 2) {
                float s = 0.f;
                for (int d2 = 0; d2 < 64; d2++) s += S.kq[tid*64 + d2];
                S.s_scal[tid] = rsqrtf(s + 1e-8f);
            }
            __syncthreads();
            if (tid < 128) {
                int rw = tid >> 6, d = tid & 63;
                if (rw) S.skw[d] *= S.s_scal[1]; else S.skr[d] *= S.s_scal[0];
            }
            __syncthreads();
            int nbase = s_sub*512;
            const float* mt = g_memT + (size_t)s_bh*64*Nn + nbase;
            float ar0 = 0.f, aw0 = 0.f, ar1 = 0.f, aw1 = 0.f;
#pragma unroll 8
            for (int d = 0; d < 64; d++) {
                float kr = S.skr[d], kw = S.skw[d];
                float m0 = mt[(size_t)d*Nn + tid];
                float m1 = mt[(size_t)d*Nn + tid + 256];
                ar0 += m0*kr; aw0 += m0*kw;
                ar1 += m1*kr; aw1 += m1*kw;
            }
            int n1 = nbase + tid, n2 = n1 + 256;
            float i1 = rsqrtf(g_sumsq[s_bh*Nn + n1] + 1e-8f);
            float i2 = rsqrtf(g_sumsq[s_bh*Nn + n2] + 1e-8f);
            g_sim[(size_t)s_bh*Nn + n1]        = ar0 * i1;
            g_sim[(size_t)s_bh*Nn + n2]        = ar1 * i2;
            g_sim[(size_t)(32 + s_bh)*Nn + n1] = aw0 * i1;
            g_sim[(size_t)(32 + s_bh)*Nn + n2] = aw1 * i2;
        }
        gridbar();
        // ---------- phase C: parallel read/write topk + rv + mem update ----------
        if (blk < 32) {
            const int half = warp >> 2;      // 0 = read, 1 = write
            const int hw = warp & 3;
            const float beta = half ? beta_w : beta_r;
            const float* s0 = g_sim + ((size_t)(half*32 + blk))*Nn;
            float v[16];
#pragma unroll
            for (int j = 0; j < 16; j++) {
                int n = hw*512 + j*32 + lane;
                v[j] = s0[n];
                S.ssim2[half][n] = v[j];
            }
            if (tid < 2) S.cnt[tid] = 0;
            // per-warp top-8 of its 512 values
            float wt8[8]; int wi8[8];
#pragma unroll
            for (int k = 0; k < TOPK; k++) {
                float bv = -3.4e38f; int bj = 0;
#pragma unroll
                for (int j = 0; j < 16; j++) if (v[j] > bv) { bv = v[j]; bj = j; }
                int bi = hw*512 + bj*32 + lane;
#pragma unroll
                for (int off = 16; off > 0; off >>= 1) {
                    float ov = __shfl_xor_sync(0xffffffffu, bv, off);
                    int   oi = __shfl_xor_sync(0xffffffffu, bi, off);
                    if (ov > bv || (ov == bv && oi < bi)) { bv = ov; bi = oi; }
                }
                wt8[k] = bv; wi8[k] = bi;
                if (lane == (bi & 31)) v[(bi >> 5) & 15] = -3.4e38f;
            }
            if (lane < 8) { S.wtop[half][hw][lane] = wt8[lane]; S.witop[half][hw][lane] = wi8[lane]; }
            __syncthreads();
            // merge 32 candidates per half (warps 0 and 4)
            if (hw == 0) {
                float cv = S.wtop[half][lane >> 3][lane & 7];
                int   ci = S.witop[half][lane >> 3][lane & 7];
#pragma unroll
                for (int k = 0; k < TOPK; k++) {
                    float bv = cv; int bi = ci;
#pragma unroll
                    for (int off = 16; off > 0; off >>= 1) {
                        float ov = __shfl_xor_sync(0xffffffffu, bv, off);
                        int   oi = __shfl_xor_sync(0xffffffffu, bi, off);
                        if (ov > bv || (ov == bv && oi < bi)) { bv = ov; bi = oi; }
                    }
                    if (lane == 0) {
                        if (k == 0)       S.scal2[half][0] = bv;
                        if (k == TOPK-1)  S.scal2[half][1] = bv;
                    }
                    if (ci == bi) cv = -3.4e38f;
                }
            }
            __syncthreads();
            float smax = S.scal2[half][0], kth = S.scal2[half][1];
            // survivor collection
#pragma unroll
            for (int j = 0; j < 16; j++) {
                int n = hw*512 + j*32 + lane;
                float sv = S.ssim2[half][n];
                if (sv >= kth) {
                    int p = atomicAdd(&S.cnt[half], 1);
                    if (p < 48) { S.li2[half][p] = n; S.lw2[half][p] = expf(beta*(sv - smax)); }
                }
            }
            __syncthreads();
            if (tid == 0 || tid == 128) {
                int hh = tid >> 7;
                int ln = S.cnt[hh] < 48 ? S.cnt[hh] : 48;
                for (int a2 = 1; a2 < ln; a2++) {
                    int key = S.li2[hh][a2]; float kw2 = S.lw2[hh][a2]; int c2s = a2 - 1;
                    while (c2s >= 0 && S.li2[hh][c2s] > key) {
                        S.li2[hh][c2s+1] = S.li2[hh][c2s]; S.lw2[hh][c2s+1] = S.lw2[hh][c2s]; c2s--;
                    }
                    S.li2[hh][c2s+1] = key; S.lw2[hh][c2s+1] = kw2;
                }
                float s = 0.f;
                for (int j = 0; j < ln; j++) s += S.lw2[hh][j];
                S.scal2[hh][2] = 1.f / s;
                S.cnt[hh] = ln;
            }
            __syncthreads();
            // rv gather (read list, pre-update mem)
            {
                int ln0 = S.cnt[0];
                float inv0 = S.scal2[0][2];
                int d = tid & 63, jj = tid >> 6;
                float part = 0.f;
                for (int j = jj; j < ln0; j += 4)
                    part += (S.lw2[0][j]*inv0) * g_mem[((size_t)(c_b*Nn + S.li2[0][j]))*Dd + c_h*64 + d];
                S.rvred[jj][d] = part;
            }
            __syncthreads();
            if (tid < 64) {
                float acc = S.rvred[0][tid] + S.rvred[1][tid] + S.rvred[2][tid] + S.rvred[3][tid];
                g_rv[c_b*Dd + c_h*64 + tid] = acc;
                if (t + 1 < Tt) {
                    size_t m = (size_t)(c_b*Tt + t + 1);
                    __nv_bfloat16 hi = __float2bfloat16(acc);
                    __nv_bfloat16 lo = __float2bfloat16(acc - __bfloat162float(hi));
                    g_Ab[m*(2*KTOT) + 512 + c_h*64 + tid]        = hi;
                    g_Ab[m*(2*KTOT) + KTOT + 512 + c_h*64 + tid] = lo;
                }
            }
            __syncthreads();
            // mem update (write list)
            {
                int ln1 = S.cnt[1];
                float inv1 = S.scal2[1][2];
                float gh   = sigmoidf_(ib[c_b*IFc + 4*Dd + c_h]);
                float er0  = sigmoidf_(ib[c_b*IFc + 3*Dd + c_h*64 + lane]);
                float er1  = sigmoidf_(ib[c_b*IFc + 3*Dd + c_h*64 + lane + 32]);
                float val0 = ib[c_b*IFc + 2*Dd + c_h*64 + lane];
                float val1 = ib[c_b*IFc + 2*Dd + c_h*64 + lane + 32];
                for (int j = warp; j < ln1; j += 8) {
                    int n = S.li2[1][j]; float w = S.lw2[1][j]*inv1;
                    size_t base = ((size_t)(c_b*Nn + n))*Dd + c_h*64;
                    float m0 = g_mem[base + lane], m1 = g_mem[base + lane + 32];
                    float nm0 = m0*(1.f - w*er0) + w*(gh*val0);
                    float nm1 = m1*(1.f - w*er1) + w*(gh*val1);
                    g_mem[base + lane] = nm0;
                    g_mem[base + lane + 32] = nm1;
                    g_memT[((size_t)c_bh*64 + lane)*Nn + n]      = nm0;
                    g_memT[((size_t)c_bh*64 + lane + 32)*Nn + n] = nm1;
                    float ss2 = nm0*nm0 + nm1*nm1;
#pragma unroll
                    for (int off = 16; off > 0; off >>= 1) ss2 += __shfl_down_sync(0xffffffffu, ss2, off);
                    if (lane == 0) g_sumsq[c_bh*Nn + n] = ss2;
                }
            }
        }
        gridbar();
        // ---------- iface for t+1 ----------
        if (t + 1 < Tt) {
            for (int idx = blk*256 + tid; idx < Bb*IFc; idx += GRIDB*256) {
                int b2 = idx / IFc, c = idx - b2*IFc;
                float acc = iface[((size_t)(b2*Tt + t + 1))*IFc + c] + b_if[c];
                const float4* wp = (const float4*)(g_wifrT + (size_t)c*Dd);
                const float4* rp = (const float4*)(g_rv + b2*Dd);
#pragma unroll 8
                for (int d4 = 0; d4 < Dd/4; d4++) {
                    float4 w4 = wp[d4], r4 = rp[d4];
                    acc += r4.x*w4.x + r4.y*w4.y + r4.z*w4.z + r4.w*w4.w;
                }
                g_ibuf[(t + 1) & 1][idx] = acc;
            }
        }
        gridbar();
    }

    // scan blocks become workers for remaining tiles
    worker_loop(gsm, &s_tile, bias, out);
}

static float* addr_of(const void* symbol) {
    void* p = nullptr;
    cudaGetSymbolAddress(&p, symbol);
    return (float*)p;
}

extern "C" void kernel_launch(void* const* d_in, const int* in_sizes, int n_in,
                              void* d_out, int out_size) {
    const int*   input_seq = (const int*)  d_in[0];
    const float* emb       = (const float*)d_in[1];
    const float* pos       = (const float*)d_in[2];
    const float* ln1_g     = (const float*)d_in[3];
    const float* ln1_b     = (const float*)d_in[4];
    const float* ln2_g     = (const float*)d_in[5];
    const float* ln2_b     = (const float*)d_in[6];
    const float* Wq        = (const float*)d_in[7];
    const float* Wk        = (const float*)d_in[8];
    const float* Wv        = (const float*)d_in[9];
    const float* Wo        = (const float*)d_in[10];
    const float* W1        = (const float*)d_in[11];
    const float* b1        = (const float*)d_in[12];
    const float* W2        = (const float*)d_in[13];
    const float* b2        = (const float*)d_in[14];
    const float* lnf_g     = (const float*)d_in[15];
    const float* lnf_b     = (const float*)d_in[16];
    const float* W_if_h    = (const float*)d_in[17];
    const float* W_if_r    = (const float*)d_in[18];
    const float* b_if      = (const float*)d_in[19];
    const float* W_lg_h    = (const float*)d_in[20];
    const float* W_lg_r    = (const float*)d_in[21];
    const float* b_lg      = (const float*)d_in[22];
    const float* beta_read = (const float*)d_in[23];
    const float* beta_write= (const float*)d_in[24];
    const float* mem_init  = (const float*)d_in[25];
    float* out = (float*)d_out;

    static float* p_x = nullptr, *p_h, *p_q, *p_k, *p_v, *p_attno, *p_hf, *p_ffn, *p_iface;
    if (!p_x) {
        p_x      = addr_of(g_x);      p_h     = addr_of(g_h);
        p_q      = addr_of(g_q);      p_k     = addr_of(g_k);
        p_v      = addr_of(g_v);      p_attno = addr_of(g_attno);
        p_hf     = addr_of(g_hf);     p_ffn   = addr_of(g_ffn);
        p_iface  = addr_of(g_iface);
    }

    k_embed<<<2048, 256>>>(input_seq, emb, pos);
    k_convW<<<dim3(Vv/32, KTOT/32), dim3(32,8)>>>(W_lg_h, W_lg_r);
    k_twifr<<<dim3((IFc+31)/32, Dd/32), dim3(32,8)>>>(W_if_r);

    dim3 gE(4, 32);
    dim3 gF(16, 16);
    for (int l = 0; l < Ll; l++) {
        k_ln<<<Mrows, 256>>>(p_x, p_h, ln1_g + l*Ee, ln1_b + l*Ee);
        k_gemm<64,4><<<gE, 256>>>(p_h, Wq + (size_t)l*Ee*Ee, nullptr, nullptr, p_q, Mrows, Ee, Ee, 0);
        k_gemm<64,4><<<gE, 256>>>(p_h, Wk + (size_t)l*Ee*Ee, nullptr, nullptr, p_k, Mrows, Ee, Ee, 0);
        k_gemm<64,4><<<gE, 256>>>(p_h, Wv + (size_t)l*Ee*Ee, nullptr, nullptr, p_v, Mrows, Ee, Ee, 0);
        k_attn<<<dim3(Tt, HA, Bb), 256>>>();
        k_gemm<64,4><<<gE, 256>>>(p_attno, Wo + (size_t)l*Ee*Ee, nullptr, p_x, p_x, Mrows, Ee, Ee, 0);
        k_ln<<<Mrows, 256>>>(p_x, p_h, ln2_g + l*Ee, ln2_b + l*Ee);
        k_gemm<128,8><<<gF, 256>>>(p_h, W1 + (size_t)l*Ee*Ff, b1 + l*Ff, nullptr, p_ffn, Mrows, Ee, Ff, 1);
        k_gemm<64,4><<<gE, 256>>>(p_ffn, W2 + (size_t)l*Ff*Ee, b2 + l*Ee, p_x, p_x, Mrows, Ff, Ee, 0);
    }

    k_ln<<<Mrows, 256>>>(p_x, p_hf, lnf_g, lnf_b);
    k_gemm<128,8><<<dim3(9, 16), 256>>>(p_hf, W_if_h, nullptr, nullptr, p_iface, Mrows, Ee, IFc, 0);

    k_convA1<<<2048, 256>>>();

    // ---- scan + fully overlapped logits GEMM (p1 ungated, p2 gated on scan progress) ----
    k_scan_init<<<2048, 256>>>(mem_init, p_iface, b_if);
    k_scan<<<GRIDB + WORKERS, 256>>>(p_iface, b_if, beta_read, beta_write, b_lg, out);
}

// round 8
// speedup vs baseline: 1.7190x; 1.0070x over previous
#include <cuda_runtime.h>
#include <cuda_bf16.h>
#include <math.h>
#include <stdint.h>

// ---------------- problem constants ----------------
#define Vv 32000
#define Ee 512
#define Ff 2048
#define Dd 256
#define Nn 2048
#define Ll 2
#define Bb 8
#define Tt 256
#define HM 4
#define TOPK 8
#define HA 8
#define HD 64
#define DH 64
#define IFc 1028
#define Mrows (Bb*Tt)
#define GRIDB 128
#define WORKERS 168
#define KTOT 768
#define NT_P1 4000
#define NT_TOT 8000

// ---------------- scratch ----------------
__device__ float g_x[Mrows*Ee];
__device__ float g_h[Mrows*Ee];
__device__ float g_q[Mrows*Ee];
__device__ float g_k[Mrows*Ee];
__device__ float g_v[Mrows*Ee];
__device__ float g_attno[Mrows*Ee];
__device__ float g_hf[Mrows*Ee];
__device__ float g_ffn[Mrows*Ff];
__device__ float g_iface[Mrows*IFc];
__device__ float g_mem[Bb*Nn*Dd];
__device__ float g_memT[32*64*Nn];
__device__ float g_sumsq[32*Nn];
__device__ float g_rv[Bb*Dd];
__device__ float g_ibuf[2][Bb*IFc];
__device__ float g_sim[2*Bb*HM*Nn];
__device__ float g_wifrT[IFc*Dd];
__device__ __nv_bfloat16 g_Whi[(size_t)Vv*KTOT];
__device__ __nv_bfloat16 g_Wlo[(size_t)Vv*KTOT];
__device__ __nv_bfloat16 g_Ab[(size_t)Mrows*2*KTOT];
__device__ unsigned g_cnt;
__device__ unsigned g_gen;
__device__ unsigned g_tile;

// ---------------- embedding ----------------
__global__ void k_embed(const int* __restrict__ seq, const float* __restrict__ emb,
                        const float* __restrict__ pos) {
    int stride = gridDim.x * blockDim.x;
    for (int idx = blockIdx.x*blockDim.x + threadIdx.x; idx < Mrows*Ee; idx += stride) {
        int e  = idx % Ee;
        int bt = idx / Ee;
        int t  = bt % Tt;
        g_x[idx] = emb[(size_t)seq[bt]*Ee + e] + pos[t*Ee + e];
    }
}

// ---------------- layernorm ----------------
__global__ void k_ln(const float* __restrict__ in, float* __restrict__ outp,
                     const float* __restrict__ g, const float* __restrict__ b) {
    int row = blockIdx.x;
    int tid = threadIdx.x;
    const float* x = in + (size_t)row*Ee;
    __shared__ float red[256];
    float v0 = x[tid], v1 = x[tid+256];
    red[tid] = v0 + v1;
    __syncthreads();
    for (int s = 128; s > 0; s >>= 1) { if (tid < s) red[tid] += red[tid+s]; __syncthreads(); }
    float mean = red[0] * (1.f/Ee);
    __syncthreads();
    float d0 = v0 - mean, d1 = v1 - mean;
    red[tid] = d0*d0 + d1*d1;
    __syncthreads();
    for (int s = 128; s > 0; s >>= 1) { if (tid < s) red[tid] += red[tid+s]; __syncthreads(); }
    float inv = rsqrtf(red[0] * (1.f/Ee) + 1e-5f);
    outp[(size_t)row*Ee + tid]       = d0*inv*g[tid]     + b[tid];
    outp[(size_t)row*Ee + tid + 256] = d1*inv*g[tid+256] + b[tid+256];
}

__device__ __forceinline__ float geluf_(float xx) {
    float tt = tanhf(0.7978845608028654f * (xx + 0.044715f*xx*xx*xx));
    return 0.5f * xx * (1.f + tt);
}

// ---------------- SIMT GEMM (transformer-sized) ----------------
template<int BM, int TM>
__global__ void __launch_bounds__(256) k_gemm(const float* __restrict__ A, const float* __restrict__ W,
                       const float* __restrict__ bias, const float* __restrict__ res,
                       float* __restrict__ C, int M, int K, int N, int act) {
    __shared__ float As[2][16][BM];
    __shared__ float Bs[2][16][128];
    const int tid = threadIdx.x;
    const int bm = blockIdx.y * BM, bn = blockIdx.x * 128;
    const int tx = tid & 15, ty = tid >> 4;
    constexpr int AV = BM/64;
    float4 aR[AV], bR[2];
    float acc[TM][8];
#pragma unroll
    for (int i = 0; i < TM; i++)
#pragma unroll
        for (int j = 0; j < 8; j++) acc[i][j] = 0.f;

    auto ldg = [&](int k0) {
#pragma unroll
        for (int v = 0; v < AV; v++) {
            int i = tid + v*256;
            int row = i >> 2, cg = i & 3;
            aR[v] = *(const float4*)(A + (size_t)(bm+row)*K + k0 + cg*4);
        }
#pragma unroll
        for (int v = 0; v < 2; v++) {
            int i = tid + v*256;
            int row = i >> 5, cg = i & 31;
            int col = bn + cg*4;
            if (col < N) bR[v] = *(const float4*)(W + (size_t)(k0+row)*N + col);
            else { bR[v].x = bR[v].y = bR[v].z = bR[v].w = 0.f; }
        }
    };
    auto sts = [&](int buf) {
#pragma unroll
        for (int v = 0; v < AV; v++) {
            int i = tid + v*256;
            int row = i >> 2, cg = i & 3;
            As[buf][cg*4+0][row] = aR[v].x; As[buf][cg*4+1][row] = aR[v].y;
            As[buf][cg*4+2][row] = aR[v].z; As[buf][cg*4+3][row] = aR[v].w;
        }
#pragma unroll
        for (int v = 0; v < 2; v++) {
            int i = tid + v*256;
            int row = i >> 5, cg = i & 31;
            *(float4*)&Bs[buf][row][cg*4] = bR[v];
        }
    };
    auto comp = [&](int buf) {
#pragma unroll
        for (int kk = 0; kk < 16; kk++) {
            float a[TM], bfr[8];
#pragma unroll
            for (int v = 0; v < TM/4; v++)
                *(float4*)&a[v*4] = *(const float4*)&As[buf][kk][ty*TM + v*4];
            *(float4*)&bfr[0] = *(const float4*)&Bs[buf][kk][tx*8];
            *(float4*)&bfr[4] = *(const float4*)&Bs[buf][kk][tx*8+4];
#pragma unroll
            for (int i = 0; i < TM; i++)
#pragma unroll
                for (int j = 0; j < 8; j++) acc[i][j] += a[i]*bfr[j];
        }
    };

    ldg(0); sts(0); __syncthreads();
    int cur = 0;
    for (int k0 = 16; k0 < K; k0 += 16) {
        ldg(k0);
        comp(cur);
        sts(cur^1);
        __syncthreads();
        cur ^= 1;
    }
    comp(cur);

#pragma unroll
    for (int i = 0; i < TM; i++) {
        int row = bm + ty*TM + i;
#pragma unroll
        for (int jv = 0; jv < 2; jv++) {
            int col = bn + tx*8 + jv*4;
            if (col < N) {
                float4 v4;
                v4.x = acc[i][jv*4+0]; v4.y = acc[i][jv*4+1];
                v4.z = acc[i][jv*4+2]; v4.w = acc[i][jv*4+3];
                if (bias) { v4.x += bias[col]; v4.y += bias[col+1]; v4.z += bias[col+2]; v4.w += bias[col+3]; }
                if (act == 1) { v4.x = geluf_(v4.x); v4.y = geluf_(v4.y); v4.z = geluf_(v4.z); v4.w = geluf_(v4.w); }
                if (res) {
                    float4 r4 = *(const float4*)&res[(size_t)row*N + col];
                    v4.x += r4.x; v4.y += r4.y; v4.z += r4.z; v4.w += r4.w;
                }
                *(float4*)&C[(size_t)row*N + col] = v4;
            }
        }
    }
}

// ---------------- attention ----------------
__global__ void k_attn() {
    int t = blockIdx.x, hh = blockIdx.y, b = blockIdx.z;
    int tid = threadIdx.x;
    __shared__ float sq[64];
    __shared__ float ss[256];
    __shared__ float red[256];
    const float* qrow = g_q + ((size_t)(b*Tt + t))*Ee + hh*DH;
    if (tid < 64) sq[tid] = qrow[tid];
    __syncthreads();
    float lmax = -3.4e38f;
    for (int j = tid; j <= t; j += 256) {
        const float* krow = g_k + ((size_t)(b*Tt + j))*Ee + hh*DH;
        float d = 0.f;
#pragma unroll
        for (int e = 0; e < 64; e++) d += sq[e]*krow[e];
        d *= 0.125f;
        ss[j] = d;
        lmax = fmaxf(lmax, d);
    }
    red[tid] = lmax;
    __syncthreads();
    for (int s = 128; s > 0; s >>= 1) { if (tid < s) red[tid] = fmaxf(red[tid], red[tid+s]); __syncthreads(); }
    float mx = red[0];
    __syncthreads();
    float lsum = 0.f;
    for (int j = tid; j <= t; j += 256) { float p = expf(ss[j]-mx); ss[j] = p; lsum += p; }
    red[tid] = lsum;
    __syncthreads();
    for (int s = 128; s > 0; s >>= 1) { if (tid < s) red[tid] += red[tid+s]; __syncthreads(); }
    float inv = 1.f / red[0];
    __syncthreads();
    if (tid < 64) {
        float acc = 0.f;
        for (int j = 0; j <= t; j++)
            acc += ss[j] * g_v[((size_t)(b*Tt + j))*Ee + hh*DH + tid];
        g_attno[((size_t)(b*Tt + t))*Ee + hh*DH + tid] = acc * inv;
    }
}

// ---------------- W_lg split + transpose ----------------
__global__ void k_convW(const float* __restrict__ Wh, const float* __restrict__ Wr) {
    __shared__ float tile[32][33];
    int nt = blockIdx.x*32, kt = blockIdx.y*32;
    int tx = threadIdx.x, ty = threadIdx.y;
#pragma unroll
    for (int r = 0; r < 32; r += 8) {
        int k = kt + ty + r, n = nt + tx;
        float v = (k < 512) ? Wh[(size_t)k*Vv + n] : Wr[(size_t)(k-512)*Vv + n];
        tile[ty+r][tx] = v;
    }
    __syncthreads();
#pragma unroll
    for (int r = 0; r < 32; r += 8) {
        int n = nt + ty + r, k = kt + tx;
        float v = tile[tx][ty+r];
        __nv_bfloat16 hi = __float2bfloat16(v);
        __nv_bfloat16 lo = __float2bfloat16(v - __bfloat162float(hi));
        g_Whi[(size_t)n*KTOT + k] = hi;
        g_Wlo[(size_t)n*KTOT + k] = lo;
    }
}

// ---------------- A split (h_f part) ----------------
__global__ void k_convA1() {
    int stride = gridDim.x*blockDim.x;
    for (int idx = blockIdx.x*blockDim.x + threadIdx.x; idx < Mrows*512; idx += stride) {
        int m = idx >> 9, k = idx & 511;
        float v = g_hf[(size_t)m*Ee + k];
        __nv_bfloat16 hi = __float2bfloat16(v);
        __nv_bfloat16 lo = __float2bfloat16(v - __bfloat162float(hi));
        g_Ab[(size_t)m*(2*KTOT) + k]        = hi;
        g_Ab[(size_t)m*(2*KTOT) + KTOT + k] = lo;
    }
}

// ---------------- transpose W_if_r ----------------
__global__ void k_twifr(const float* __restrict__ W) {
    __shared__ float tile[32][33];
    int ct = blockIdx.x*32, dt = blockIdx.y*32;
    int tx = threadIdx.x, ty = threadIdx.y;
#pragma unroll
    for (int r = 0; r < 32; r += 8) {
        int d = dt + ty + r, c = ct + tx;
        tile[ty+r][tx] = (c < IFc) ? W[(size_t)d*IFc + c] : 0.f;
    }
    __syncthreads();
#pragma unroll
    for (int r = 0; r < 32; r += 8) {
        int c = ct + ty + r, d = dt + tx;
        if (c < IFc) g_wifrT[(size_t)c*Dd + d] = tile[tx][ty+r];
    }
}

// ---------------- bf16 mma.sync + ldmatrix ----------------
__device__ __forceinline__ void mma16816(float* c, const uint32_t* a, const uint32_t* b) {
    asm volatile(
        "mma.sync.aligned.m16n8k16.row.col.f32.bf16.bf16.f32 "
        "{%0,%1,%2,%3}, {%4,%5,%6,%7}, {%8,%9}, {%0,%1,%2,%3};"
        : "+f"(c[0]), "+f"(c[1]), "+f"(c[2]), "+f"(c[3])
        : "r"(a[0]), "r"(a[1]), "r"(a[2]), "r"(a[3]), "r"(b[0]), "r"(b[1]));
}
__device__ __forceinline__ void ldmat_x4(uint32_t* r, uint32_t saddr) {
    asm volatile("ldmatrix.sync.aligned.m8n8.x4.shared.b16 {%0,%1,%2,%3}, [%4];"
        : "=r"(r[0]), "=r"(r[1]), "=r"(r[2]), "=r"(r[3]) : "r"(saddr));
}

// ---------------- shared layouts ----------------
struct GemmSm {
    __nv_bfloat16 As[2][128][40];   // 10240 B per buffer, 80 B row stride
    __nv_bfloat16 Bs[2][128][40];
};
struct ScanSm {
    float ssim2[2][Nn];
    float skr[64], skw[64];
    float kq[128];
    float wtop[2][4][8]; int witop[2][4][8];
    float lw2[2][48]; int li2[2][48];
    int cnt[2];
    float scal2[2][4];
    float s_scal[4];
    float rvred[4][64];
};

// ---------------- one 128x128 logits tile (ldmatrix inner loop) ----------------
__device__ void lgemm_tile(GemmSm* sm, int m0, int n0, int kb, int nseg,
                           const float* __restrict__ bias, float* __restrict__ C, int accum) {
    const int tid = threadIdx.x, wid = tid >> 5, lane = tid & 31;
    const int wm = (wid & 1) * 64, wn = (wid >> 1) * 32;
    const int nchunks = nseg * 3;

    const uint32_t aBase0 = (uint32_t)__cvta_generic_to_shared(&sm->As[0][0][0]);
    const uint32_t bBase0 = (uint32_t)__cvta_generic_to_shared(&sm->Bs[0][0][0]);
    // ldmatrix per-lane address components
    const uint32_t aLane = (uint32_t)((wm + (lane & 15)) * 80 + ((lane >> 4) * 8) * 2);
    const uint32_t bLane = (uint32_t)((wn + ((lane >> 4) & 1) * 8 + (lane & 7)) * 80
                                      + (((lane >> 3) & 1) * 8) * 2);

    float acc[4][4][4];
#pragma unroll
    for (int mi = 0; mi < 4; mi++)
#pragma unroll
        for (int ni = 0; ni < 4; ni++)
#pragma unroll
            for (int j = 0; j < 4; j++) acc[mi][ni][j] = 0.f;

    uint4 aR[2], bR[2];
    auto ldg = [&](int c) {
        int seg = c / nseg, kin = kb + (c - seg*nseg)*32;
        const __nv_bfloat16* Aseg = g_Ab + (seg == 2 ? KTOT : 0);
        const __nv_bfloat16* Wseg = (seg == 1) ? g_Wlo : g_Whi;
#pragma unroll
        for (int v = 0; v < 2; v++) {
            int i = tid + v*256;
            int row = i >> 2, cg = i & 3;
            aR[v] = *(const uint4*)(Aseg + (size_t)(m0+row)*(2*KTOT) + kin + cg*8);
            bR[v] = *(const uint4*)(Wseg + (size_t)(n0+row)*KTOT    + kin + cg*8);
        }
    };
    auto sts = [&](int buf) {
#pragma unroll
        for (int v = 0; v < 2; v++) {
            int i = tid + v*256;
            int row = i >> 2, cg = i & 3;
            *(uint4*)&sm->As[buf][row][cg*8] = aR[v];
            *(uint4*)&sm->Bs[buf][row][cg*8] = bR[v];
        }
    };
    auto comp = [&](int buf) {
        uint32_t aB = aBase0 + (uint32_t)buf*10240u + aLane;
        uint32_t bB = bBase0 + (uint32_t)buf*10240u + bLane;
#pragma unroll
        for (int kt = 0; kt < 32; kt += 16) {
            uint32_t af[4][4], bq[2][4];
#pragma unroll
            for (int mi = 0; mi < 4; mi++)
                ldmat_x4(af[mi], aB + (uint32_t)(mi*16*80) + (uint32_t)(kt*2));
#pragma unroll
            for (int p = 0; p < 2; p++)
                ldmat_x4(bq[p], bB + (uint32_t)(p*16*80) + (uint32_t)(kt*2));
#pragma unroll
            for (int mi = 0; mi < 4; mi++)
#pragma unroll
                for (int ni = 0; ni < 4; ni++)
                    mma16816(acc[mi][ni], af[mi], &bq[ni >> 1][(ni & 1) * 2]);
        }
    };

    ldg(0); sts(0); __syncthreads();
    int cur = 0;
    for (int c = 1; c < nchunks; c++) {
        ldg(c);
        comp(cur);
        sts(cur^1);
        __syncthreads();
        cur ^= 1;
    }
    comp(cur);

    const int r = lane >> 2, c2 = (lane & 3) * 2;
#pragma unroll
    for (int mi = 0; mi < 4; mi++) {
        int row0 = m0 + wm + mi*16 + r;
#pragma unroll
        for (int ni = 0; ni < 4; ni++) {
            int col = n0 + wn + ni*8 + c2;
            float2 v0, v1;
            if (accum) {
                float2 o0 = *(const float2*)&C[(size_t)row0*Vv + col];
                float2 o1 = *(const float2*)&C[(size_t)(row0+8)*Vv + col];
                v0.x = acc[mi][ni][0] + o0.x; v0.y = acc[mi][ni][1] + o0.y;
                v1.x = acc[mi][ni][2] + o1.x; v1.y = acc[mi][ni][3] + o1.y;
            } else {
                v0.x = acc[mi][ni][0] + bias[col]; v0.y = acc[mi][ni][1] + bias[col+1];
                v1.x = acc[mi][ni][2] + bias[col]; v1.y = acc[mi][ni][3] + bias[col+1];
            }
            *(float2*)&C[(size_t)row0*Vv + col]     = v0;
            *(float2*)&C[(size_t)(row0+8)*Vv + col] = v1;
        }
    }
}

// ---------------- worker loop: p1 tiles then gated p2 tiles ----------------
__device__ void worker_loop(GemmSm* gsm, volatile int* s_tile,
                            const float* __restrict__ bias, float* __restrict__ out) {
    const int tid = threadIdx.x;
    for (;;) {
        if (tid == 0) *s_tile = (int)atomicAdd(&g_tile, 1u);
        __syncthreads();
        int tl = *s_tile;
        if (tl >= NT_TOT) break;
        if (tl < NT_P1) {
            lgemm_tile(gsm, (tl/250)*128, (tl%250)*128, 0, 16, bias, out, 0);
        } else {
            int id = tl - NT_P1;
            int grp = id / 250, nt = id % 250;
            int mt = (grp < 8) ? (2*grp) : (2*(grp-8)+1);
            unsigned need = (mt & 1) ? 764u : 380u;
            if (tid == 0) { while (atomicAdd(&g_gen, 0u) < need) __nanosleep(256); }
            __syncthreads();
            __threadfence();
            lgemm_tile(gsm, mt*128, nt*128, 512, 8, nullptr, out, 1);
        }
        __syncthreads();
    }
}

// ---------------- scan init ----------------
__global__ void k_scan_init(const float* __restrict__ mem_init, const float* __restrict__ iface,
                            const float* __restrict__ b_if) {
    int stride = gridDim.x*blockDim.x;
    int tid0 = blockIdx.x*blockDim.x + threadIdx.x;
    for (int idx = tid0; idx < Bb*Nn*Dd; idx += stride)
        g_mem[idx] = mem_init[idx % (Nn*Dd)];
    for (int idx = tid0; idx < 32*64*Nn; idx += stride) {
        int n = idx & (Nn-1);
        int rest = idx >> 11;
        int d = rest & 63;
        int bh = rest >> 6;
        int h = bh & 3;
        g_memT[idx] = mem_init[(size_t)n*Dd + h*64 + d];
    }
    for (int idx = tid0; idx < 32*Nn; idx += stride) {
        int n = idx & (Nn-1);
        int bh = idx >> 11;
        int h = bh & 3;
        const float* r = mem_init + (size_t)n*Dd + h*HD;
        float s = 0.f;
#pragma unroll
        for (int d = 0; d < HD; d++) s += r[d]*r[d];
        g_sumsq[idx] = s;
    }
    for (int idx = tid0; idx < Bb*IFc; idx += stride) {
        int b = idx / IFc, c = idx - b*IFc;
        g_ibuf[0][idx] = iface[((size_t)(b*Tt))*IFc + c] + b_if[c];
    }
    for (int idx = tid0; idx < Bb*Dd; idx += stride) {
        g_rv[idx] = 0.f;
        int b = idx / Dd, kk = idx % Dd;
        size_t m = (size_t)b*Tt;
        __nv_bfloat16 z = __float2bfloat16(0.f);
        g_Ab[m*(2*KTOT) + 512 + kk]        = z;
        g_Ab[m*(2*KTOT) + KTOT + 512 + kk] = z;
    }
    if (tid0 == 0) { g_cnt = 0u; g_gen = 0u; g_tile = 0u; }
}

// ---------------- software grid barrier (scan blocks only) ----------------
__device__ __forceinline__ void gridbar() {
    __syncthreads();
    if (threadIdx.x == 0) {
        __threadfence();
        unsigned gen = atomicAdd(&g_gen, 0u);
        if (atomicAdd(&g_cnt, 1u) == GRIDB - 1u) {
            g_cnt = 0u;
            __threadfence();
            atomicExch(&g_gen, gen + 1u);
        } else {
            while (atomicAdd(&g_gen, 0u) == gen) { __nanosleep(64); }
        }
    }
    __syncthreads();
}

__device__ __forceinline__ float sigmoidf_(float x) { return 1.f/(1.f + expf(-x)); }

// ---------------- persistent scan + fused logits workers ----------------
__global__ void __launch_bounds__(256, 2) k_scan(const float* __restrict__ iface,
                                                 const float* __restrict__ b_if,
                                                 const float* __restrict__ brp,
                                                 const float* __restrict__ bwp,
                                                 const float* __restrict__ bias,
                                                 float* __restrict__ out) {
    __shared__ __align__(16) char smraw[sizeof(GemmSm)];
    __shared__ int s_tile;
    const int blk = blockIdx.x, tid = threadIdx.x;
    GemmSm* gsm = reinterpret_cast<GemmSm*>(smraw);

    if (blk >= GRIDB) {
        worker_loop(gsm, &s_tile, bias, out);
        return;
    }

    ScanSm& S = *reinterpret_cast<ScanSm*>(smraw);
    const int warp = tid >> 5, lane = tid & 31;

    float beta_r, beta_w;
    {
        float b0 = *brp; b0 = log1pf(expf(b0)); beta_r = fminf(fmaxf(b0, 1.f), 20.f);
        float b1 = *bwp; b1 = log1pf(expf(b1)); beta_w = fminf(fmaxf(b1, 1.f), 20.f);
    }
    const int s_bh = blk >> 2, s_sub = blk & 3;
    const int s_b = s_bh >> 2, s_h = s_bh & 3;
    const int c_b = blk >> 2, c_h = blk & 3;
    const int c_bh = blk;

    for (int t = 0; t < Tt; t++) {
        const float* ib = g_ibuf[t & 1];
        // ---------- SIM ----------
        {
            if (tid < 128) {
                int rw = tid >> 6, d = tid & 63;
                float kx = ib[s_b*IFc + rw*Dd + s_h*64 + d];
                if (rw) S.skw[d] = kx; else S.skr[d] = kx;
                S.kq[tid] = kx*kx;
            }
            __syncthreads();
            if (tid < 2) {
                float s = 0.f;
                for (int d2 = 0; d2 < 64; d2++) s += S.kq[tid*64 + d2];
                S.s_scal[tid] = rsqrtf(s + 1e-8f);
            }
            __syncthreads();
            if (tid < 128) {
                int rw = tid >> 6, d = tid & 63;
                if (rw) S.skw[d] *= S.s_scal[1]; else S.skr[d] *= S.s_scal[0];
            }
            __syncthreads();
            int nbase = s_sub*512;
            const float* mt = g_memT + (size_t)s_bh*64*Nn + nbase;
            float ar0 = 0.f, aw0 = 0.f, ar1 = 0.f, aw1 = 0.f;
#pragma unroll 8
            for (int d = 0; d < 64; d++) {
                float kr = S.skr[d], kw = S.skw[d];
                float m0 = mt[(size_t)d*Nn + tid];
                float m1 = mt[(size_t)d*Nn + tid + 256];
                ar0 += m0*kr; aw0 += m0*kw;
                ar1 += m1*kr; aw1 += m1*kw;
            }
            int n1 = nbase + tid, n2 = n1 + 256;
            float i1 = rsqrtf(g_sumsq[s_bh*Nn + n1] + 1e-8f);
            float i2 = rsqrtf(g_sumsq[s_bh*Nn + n2] + 1e-8f);
            g_sim[(size_t)s_bh*Nn + n1]        = ar0 * i1;
            g_sim[(size_t)s_bh*Nn + n2]        = ar1 * i2;
            g_sim[(size_t)(32 + s_bh)*Nn + n1] = aw0 * i1;
            g_sim[(size_t)(32 + s_bh)*Nn + n2] = aw1 * i2;
        }
        gridbar();
        // ---------- phase C ----------
        if (blk < 32) {
            const int half = warp >> 2;
            const int hw = warp & 3;
            const float beta = half ? beta_w : beta_r;
            const float* s0 = g_sim + ((size_t)(half*32 + blk))*Nn;
            float v[16];
#pragma unroll
            for (int j = 0; j < 16; j++) {
                int n = hw*512 + j*32 + lane;
                v[j] = s0[n];
                S.ssim2[half][n] = v[j];
            }
            if (tid < 2) S.cnt[tid] = 0;
            float wt8[8]; int wi8[8];
#pragma unroll
            for (int k = 0; k < TOPK; k++) {
                float bv = -3.4e38f; int bj = 0;
#pragma unroll
                for (int j = 0; j < 16; j++) if (v[j] > bv) { bv = v[j]; bj = j; }
                int bi = hw*512 + bj*32 + lane;
#pragma unroll
                for (int off = 16; off > 0; off >>= 1) {
                    float ov = __shfl_xor_sync(0xffffffffu, bv, off);
                    int   oi = __shfl_xor_sync(0xffffffffu, bi, off);
                    if (ov > bv || (ov == bv && oi < bi)) { bv = ov; bi = oi; }
                }
                wt8[k] = bv; wi8[k] = bi;
                if (lane == (bi & 31)) v[(bi >> 5) & 15] = -3.4e38f;
            }
            if (lane < 8) { S.wtop[half][hw][lane] = wt8[lane]; S.witop[half][hw][lane] = wi8[lane]; }
            __syncthreads();
            if (hw == 0) {
                float cv = S.wtop[half][lane >> 3][lane & 7];
                int   ci = S.witop[half][lane >> 3][lane & 7];
#pragma unroll
                for (int k = 0; k < TOPK; k++) {
                    float bv = cv; int bi = ci;
#pragma unroll
                    for (int off = 16; off > 0; off >>= 1) {
                        float ov = __shfl_xor_sync(0xffffffffu, bv, off);
                        int   oi = __shfl_xor_sync(0xffffffffu, bi, off);
                        if (ov > bv || (ov == bv && oi < bi)) { bv = ov; bi = oi; }
                    }
                    if (lane == 0) {
                        if (k == 0)       S.scal2[half][0] = bv;
                        if (k == TOPK-1)  S.scal2[half][1] = bv;
                    }
                    if (ci == bi) cv = -3.4e38f;
                }
            }
            __syncthreads();
            float smax = S.scal2[half][0], kth = S.scal2[half][1];
#pragma unroll
            for (int j = 0; j < 16; j++) {
                int n = hw*512 + j*32 + lane;
                float sv = S.ssim2[half][n];
                if (sv >= kth) {
                    int p = atomicAdd(&S.cnt[half], 1);
                    if (p < 48) { S.li2[half][p] = n; S.lw2[half][p] = expf(beta*(sv - smax)); }
                }
            }
            __syncthreads();
            if (tid == 0 || tid == 128) {
                int hh = tid >> 7;
                int ln = S.cnt[hh] < 48 ? S.cnt[hh] : 48;
                for (int a2 = 1; a2 < ln; a2++) {
                    int key = S.li2[hh][a2]; float kw2 = S.lw2[hh][a2]; int c2s = a2 - 1;
                    while (c2s >= 0 && S.li2[hh][c2s] > key) {
                        S.li2[hh][c2s+1] = S.li2[hh][c2s]; S.lw2[hh][c2s+1] = S.lw2[hh][c2s]; c2s--;
                    }
                    S.li2[hh][c2s+1] = key; S.lw2[hh][c2s+1] = kw2;
                }
                float s = 0.f;
                for (int j = 0; j < ln; j++) s += S.lw2[hh][j];
                S.scal2[hh][2] = 1.f / s;
                S.cnt[hh] = ln;
            }
            __syncthreads();
            {
                int ln0 = S.cnt[0];
                float inv0 = S.scal2[0][2];
                int d = tid & 63, jj = tid >> 6;
                float part = 0.f;
                for (int j = jj; j < ln0; j += 4)
                    part += (S.lw2[0][j]*inv0) * g_mem[((size_t)(c_b*Nn + S.li2[0][j]))*Dd + c_h*64 + d];
                S.rvred[jj][d] = part;
            }
            __syncthreads();
            if (tid < 64) {
                float acc = S.rvred[0][tid] + S.rvred[1][tid] + S.rvred[2][tid] + S.rvred[3][tid];
                g_rv[c_b*Dd + c_h*64 + tid] = acc;
                if (t + 1 < Tt) {
                    size_t m = (size_t)(c_b*Tt + t + 1);
                    __nv_bfloat16 hi = __float2bfloat16(acc);
                    __nv_bfloat16 lo = __float2bfloat16(acc - __bfloat162float(hi));
                    g_Ab[m*(2*KTOT) + 512 + c_h*64 + tid]        = hi;
                    g_Ab[m*(2*KTOT) + KTOT + 512 + c_h*64 + tid] = lo;
                }
            }
            __syncthreads();
            {
                int ln1 = S.cnt[1];
                float inv1 = S.scal2[1][2];
                float gh   = sigmoidf_(ib[c_b*IFc + 4*Dd + c_h]);
                float er0  = sigmoidf_(ib[c_b*IFc + 3*Dd + c_h*64 + lane]);
                float er1  = sigmoidf_(ib[c_b*IFc + 3*Dd + c_h*64 + lane + 32]);
                float val0 = ib[c_b*IFc + 2*Dd + c_h*64 + lane];
                float val1 = ib[c_b*IFc + 2*Dd + c_h*64 + lane + 32];
                for (int j = warp; j < ln1; j += 8) {
                    int n = S.li2[1][j]; float w = S.lw2[1][j]*inv1;
                    size_t base = ((size_t)(c_b*Nn + n))*Dd + c_h*64;
                    float m0 = g_mem[base + lane], m1 = g_mem[base + lane + 32];
                    float nm0 = m0*(1.f - w*er0) + w*(gh*val0);
                    float nm1 = m1*(1.f - w*er1) + w*(gh*val1);
                    g_mem[base + lane] = nm0;
                    g_mem[base + lane + 32] = nm1;
                    g_memT[((size_t)c_bh*64 + lane)*Nn + n]      = nm0;
                    g_memT[((size_t)c_bh*64 + lane + 32)*Nn + n] = nm1;
                    float ss2 = nm0*nm0 + nm1*nm1;
#pragma unroll
                    for (int off = 16; off > 0; off >>= 1) ss2 += __shfl_down_sync(0xffffffffu, ss2, off);
                    if (lane == 0) g_sumsq[c_bh*Nn + n] = ss2;
                }
            }
        }
        gridbar();
        // ---------- iface for t+1 ----------
        if (t + 1 < Tt) {
            for (int idx = blk*256 + tid; idx < Bb*IFc; idx += GRIDB*256) {
                int b2 = idx / IFc, c = idx - b2*IFc;
                float acc = iface[((size_t)(b2*Tt + t + 1))*IFc + c] + b_if[c];
                const float4* wp = (const float4*)(g_wifrT + (size_t)c*Dd);
                const float4* rp = (const float4*)(g_rv + b2*Dd);
#pragma unroll 8
                for (int d4 = 0; d4 < Dd/4; d4++) {
                    float4 w4 = wp[d4], r4 = rp[d4];
                    acc += r4.x*w4.x + r4.y*w4.y + r4.z*w4.z + r4.w*w4.w;
                }
                g_ibuf[(t + 1) & 1][idx] = acc;
            }
        }
        gridbar();
    }

    worker_loop(gsm, &s_tile, bias, out);
}

static float* addr_of(const void* symbol) {
    void* p = nullptr;
    cudaGetSymbolAddress(&p, symbol);
    return (float*)p;
}

extern "C" void kernel_launch(void* const* d_in, const int* in_sizes, int n_in,
                              void* d_out, int out_size) {
    const int*   input_seq = (const int*)  d_in[0];
    const float* emb       = (const float*)d_in[1];
    const float* pos       = (const float*)d_in[2];
    const float* ln1_g     = (const float*)d_in[3];
    const float* ln1_b     = (const float*)d_in[4];
    const float* ln2_g     = (const float*)d_in[5];
    const float* ln2_b     = (const float*)d_in[6];
    const float* Wq        = (const float*)d_in[7];
    const float* Wk        = (const float*)d_in[8];
    const float* Wv        = (const float*)d_in[9];
    const float* Wo        = (const float*)d_in[10];
    const float* W1        = (const float*)d_in[11];
    const float* b1        = (const float*)d_in[12];
    const float* W2        = (const float*)d_in[13];
    const float* b2        = (const float*)d_in[14];
    const float* lnf_g     = (const float*)d_in[15];
    const float* lnf_b     = (const float*)d_in[16];
    const float* W_if_h    = (const float*)d_in[17];
    const float* W_if_r    = (const float*)d_in[18];
    const float* b_if      = (const float*)d_in[19];
    const float* W_lg_h    = (const float*)d_in[20];
    const float* W_lg_r    = (const float*)d_in[21];
    const float* b_lg      = (const float*)d_in[22];
    const float* beta_read = (const float*)d_in[23];
    const float* beta_write= (const float*)d_in[24];
    const float* mem_init  = (const float*)d_in[25];
    float* out = (float*)d_out;

    static float* p_x = nullptr, *p_h, *p_q, *p_k, *p_v, *p_attno, *p_hf, *p_ffn, *p_iface;
    if (!p_x) {
        p_x      = addr_of(g_x);      p_h     = addr_of(g_h);
        p_q      = addr_of(g_q);      p_k     = addr_of(g_k);
        p_v      = addr_of(g_v);      p_attno = addr_of(g_attno);
        p_hf     = addr_of(g_hf);     p_ffn   = addr_of(g_ffn);
        p_iface  = addr_of(g_iface);
    }

    k_embed<<<2048, 256>>>(input_seq, emb, pos);
    k_convW<<<dim3(Vv/32, KTOT/32), dim3(32,8)>>>(W_lg_h, W_lg_r);
    k_twifr<<<dim3((IFc+31)/32, Dd/32), dim3(32,8)>>>(W_if_r);

    dim3 gE(4, 32);
    dim3 gF(16, 16);
    for (int l = 0; l < Ll; l++) {
        k_ln<<<Mrows, 256>>>(p_x, p_h, ln1_g + l*Ee, ln1_b + l*Ee);
        k_gemm<64,4><<<gE, 256>>>(p_h, Wq + (size_t)l*Ee*Ee, nullptr, nullptr, p_q, Mrows, Ee, Ee, 0);
        k_gemm<64,4><<<gE, 256>>>(p_h, Wk + (size_t)l*Ee*Ee, nullptr, nullptr, p_k, Mrows, Ee, Ee, 0);
        k_gemm<64,4><<<gE, 256>>>(p_h, Wv + (size_t)l*Ee*Ee, nullptr, nullptr, p_v, Mrows, Ee, Ee, 0);
        k_attn<<<dim3(Tt, HA, Bb), 256>>>();
        k_gemm<64,4><<<gE, 256>>>(p_attno, Wo + (size_t)l*Ee*Ee, nullptr, p_x, p_x, Mrows, Ee, Ee, 0);
        k_ln<<<Mrows, 256>>>(p_x, p_h, ln2_g + l*Ee, ln2_b + l*Ee);
        k_gemm<128,8><<<gF, 256>>>(p_h, W1 + (size_t)l*Ee*Ff, b1 + l*Ff, nullptr, p_ffn, Mrows, Ee, Ff, 1);
        k_gemm<64,4><<<gE, 256>>>(p_ffn, W2 + (size_t)l*Ff*Ee, b2 + l*Ee, p_x, p_x, Mrows, Ff, Ee, 0);
    }

    k_ln<<<Mrows, 256>>>(p_x, p_hf, lnf_g, lnf_b);
    k_gemm<128,8><<<dim3(9, 16), 256>>>(p_hf, W_if_h, nullptr, nullptr, p_iface, Mrows, Ee, IFc, 0);

    k_convA1<<<2048, 256>>>();

    k_scan_init<<<2048, 256>>>(mem_init, p_iface, b_if);
    k_scan<<<GRIDB + WORKERS, 256>>>(p_iface, b_if, beta_read, beta_write, b_lg, out);
}

// round 9
// speedup vs baseline: 1.8085x; 1.0521x over previous
#include <cuda_runtime.h>
#include <cuda_bf16.h>
#include <math.h>
#include <stdint.h>

// ---------------- problem constants ----------------
#define Vv 32000
#define Ee 512
#define Ff 2048
#define Dd 256
#define Nn 2048
#define Ll 2
#define Bb 8
#define Tt 256
#define HM 4
#define TOPK 8
#define HA 8
#define HD 64
#define DH 64
#define IFc 1028
#define Mrows (Bb*Tt)
#define GRIDB 128
#define WORKERS 168
#define KTOT 768
#define NT_P1 4000
#define NT_TOT 8000

// ---------------- scratch ----------------
__device__ float g_x[Mrows*Ee];
__device__ float g_h[Mrows*Ee];
__device__ float g_q[Mrows*Ee];
__device__ float g_k[Mrows*Ee];
__device__ float g_v[Mrows*Ee];
__device__ float g_attno[Mrows*Ee];
__device__ float g_hf[Mrows*Ee];
__device__ float g_ffn[Mrows*Ff];
__device__ float g_iface[Mrows*IFc];
__device__ float g_mem[Bb*Nn*Dd];
__device__ float g_memT[32*64*Nn];
__device__ float g_sumsq[32*Nn];
__device__ float g_rv[Bb*Dd];
__device__ float g_ibuf[2][Bb*IFc];
__device__ float g_sim[2*Bb*HM*Nn];
__device__ float g_wifrT[IFc*Dd];
__device__ __nv_bfloat16 g_Whi[(size_t)Vv*KTOT];
__device__ __nv_bfloat16 g_Wlo[(size_t)Vv*KTOT];
__device__ __nv_bfloat16 g_Ab[(size_t)Mrows*2*KTOT];
__device__ unsigned g_cnt;
__device__ unsigned g_gen;
__device__ unsigned g_tile;
__device__ unsigned g_rvflag;

// ---------------- embedding ----------------
__global__ void k_embed(const int* __restrict__ seq, const float* __restrict__ emb,
                        const float* __restrict__ pos) {
    int stride = gridDim.x * blockDim.x;
    for (int idx = blockIdx.x*blockDim.x + threadIdx.x; idx < Mrows*Ee; idx += stride) {
        int e  = idx % Ee;
        int bt = idx / Ee;
        int t  = bt % Tt;
        g_x[idx] = emb[(size_t)seq[bt]*Ee + e] + pos[t*Ee + e];
    }
}

// ---------------- layernorm ----------------
__global__ void k_ln(const float* __restrict__ in, float* __restrict__ outp,
                     const float* __restrict__ g, const float* __restrict__ b) {
    int row = blockIdx.x;
    int tid = threadIdx.x;
    const float* x = in + (size_t)row*Ee;
    __shared__ float red[256];
    float v0 = x[tid], v1 = x[tid+256];
    red[tid] = v0 + v1;
    __syncthreads();
    for (int s = 128; s > 0; s >>= 1) { if (tid < s) red[tid] += red[tid+s]; __syncthreads(); }
    float mean = red[0] * (1.f/Ee);
    __syncthreads();
    float d0 = v0 - mean, d1 = v1 - mean;
    red[tid] = d0*d0 + d1*d1;
    __syncthreads();
    for (int s = 128; s > 0; s >>= 1) { if (tid < s) red[tid] += red[tid+s]; __syncthreads(); }
    float inv = rsqrtf(red[0] * (1.f/Ee) + 1e-5f);
    outp[(size_t)row*Ee + tid]       = d0*inv*g[tid]     + b[tid];
    outp[(size_t)row*Ee + tid + 256] = d1*inv*g[tid+256] + b[tid+256];
}

__device__ __forceinline__ float geluf_(float xx) {
    float tt = tanhf(0.7978845608028654f * (xx + 0.044715f*xx*xx*xx));
    return 0.5f * xx * (1.f + tt);
}

// ---------------- SIMT GEMM (transformer-sized) ----------------
template<int BM, int TM>
__global__ void __launch_bounds__(256) k_gemm(const float* __restrict__ A, const float* __restrict__ W,
                       const float* __restrict__ bias, const float* __restrict__ res,
                       float* __restrict__ C, int M, int K, int N, int act) {
    __shared__ float As[2][16][BM];
    __shared__ float Bs[2][16][128];
    const int tid = threadIdx.x;
    const int bm = blockIdx.y * BM, bn = blockIdx.x * 128;
    const int tx = tid & 15, ty = tid >> 4;
    constexpr int AV = BM/64;
    float4 aR[AV], bR[2];
    float acc[TM][8];
#pragma unroll
    for (int i = 0; i < TM; i++)
#pragma unroll
        for (int j = 0; j < 8; j++) acc[i][j] = 0.f;

    auto ldg = [&](int k0) {
#pragma unroll
        for (int v = 0; v < AV; v++) {
            int i = tid + v*256;
            int row = i >> 2, cg = i & 3;
            aR[v] = *(const float4*)(A + (size_t)(bm+row)*K + k0 + cg*4);
        }
#pragma unroll
        for (int v = 0; v < 2; v++) {
            int i = tid + v*256;
            int row = i >> 5, cg = i & 31;
            int col = bn + cg*4;
            if (col < N) bR[v] = *(const float4*)(W + (size_t)(k0+row)*N + col);
            else { bR[v].x = bR[v].y = bR[v].z = bR[v].w = 0.f; }
        }
    };
    auto sts = [&](int buf) {
#pragma unroll
        for (int v = 0; v < AV; v++) {
            int i = tid + v*256;
            int row = i >> 2, cg = i & 3;
            As[buf][cg*4+0][row] = aR[v].x; As[buf][cg*4+1][row] = aR[v].y;
            As[buf][cg*4+2][row] = aR[v].z; As[buf][cg*4+3][row] = aR[v].w;
        }
#pragma unroll
        for (int v = 0; v < 2; v++) {
            int i = tid + v*256;
            int row = i >> 5, cg = i & 31;
            *(float4*)&Bs[buf][row][cg*4] = bR[v];
        }
    };
    auto comp = [&](int buf) {
#pragma unroll
        for (int kk = 0; kk < 16; kk++) {
            float a[TM], bfr[8];
#pragma unroll
            for (int v = 0; v < TM/4; v++)
                *(float4*)&a[v*4] = *(const float4*)&As[buf][kk][ty*TM + v*4];
            *(float4*)&bfr[0] = *(const float4*)&Bs[buf][kk][tx*8];
            *(float4*)&bfr[4] = *(const float4*)&Bs[buf][kk][tx*8+4];
#pragma unroll
            for (int i = 0; i < TM; i++)
#pragma unroll
                for (int j = 0; j < 8; j++) acc[i][j] += a[i]*bfr[j];
        }
    };

    ldg(0); sts(0); __syncthreads();
    int cur = 0;
    for (int k0 = 16; k0 < K; k0 += 16) {
        ldg(k0);
        comp(cur);
        sts(cur^1);
        __syncthreads();
        cur ^= 1;
    }
    comp(cur);

#pragma unroll
    for (int i = 0; i < TM; i++) {
        int row = bm + ty*TM + i;
#pragma unroll
        for (int jv = 0; jv < 2; jv++) {
            int col = bn + tx*8 + jv*4;
            if (col < N) {
                float4 v4;
                v4.x = acc[i][jv*4+0]; v4.y = acc[i][jv*4+1];
                v4.z = acc[i][jv*4+2]; v4.w = acc[i][jv*4+3];
                if (bias) { v4.x += bias[col]; v4.y += bias[col+1]; v4.z += bias[col+2]; v4.w += bias[col+3]; }
                if (act == 1) { v4.x = geluf_(v4.x); v4.y = geluf_(v4.y); v4.z = geluf_(v4.z); v4.w = geluf_(v4.w); }
                if (res) {
                    float4 r4 = *(const float4*)&res[(size_t)row*N + col];
                    v4.x += r4.x; v4.y += r4.y; v4.z += r4.z; v4.w += r4.w;
                }
                *(float4*)&C[(size_t)row*N + col] = v4;
            }
        }
    }
}

// ---------------- attention ----------------
__global__ void k_attn() {
    int t = blockIdx.x, hh = blockIdx.y, b = blockIdx.z;
    int tid = threadIdx.x;
    __shared__ float sq[64];
    __shared__ float ss[256];
    __shared__ float red[256];
    const float* qrow = g_q + ((size_t)(b*Tt + t))*Ee + hh*DH;
    if (tid < 64) sq[tid] = qrow[tid];
    __syncthreads();
    float lmax = -3.4e38f;
    for (int j = tid; j <= t; j += 256) {
        const float* krow = g_k + ((size_t)(b*Tt + j))*Ee + hh*DH;
        float d = 0.f;
#pragma unroll
        for (int e = 0; e < 64; e++) d += sq[e]*krow[e];
        d *= 0.125f;
        ss[j] = d;
        lmax = fmaxf(lmax, d);
    }
    red[tid] = lmax;
    __syncthreads();
    for (int s = 128; s > 0; s >>= 1) { if (tid < s) red[tid] = fmaxf(red[tid], red[tid+s]); __syncthreads(); }
    float mx = red[0];
    __syncthreads();
    float lsum = 0.f;
    for (int j = tid; j <= t; j += 256) { float p = expf(ss[j]-mx); ss[j] = p; lsum += p; }
    red[tid] = lsum;
    __syncthreads();
    for (int s = 128; s > 0; s >>= 1) { if (tid < s) red[tid] += red[tid+s]; __syncthreads(); }
    float inv = 1.f / red[0];
    __syncthreads();
    if (tid < 64) {
        float acc = 0.f;
        for (int j = 0; j <= t; j++)
            acc += ss[j] * g_v[((size_t)(b*Tt + j))*Ee + hh*DH + tid];
        g_attno[((size_t)(b*Tt + t))*Ee + hh*DH + tid] = acc * inv;
    }
}

// ---------------- W_lg split + transpose ----------------
__global__ void k_convW(const float* __restrict__ Wh, const float* __restrict__ Wr) {
    __shared__ float tile[32][33];
    int nt = blockIdx.x*32, kt = blockIdx.y*32;
    int tx = threadIdx.x, ty = threadIdx.y;
#pragma unroll
    for (int r = 0; r < 32; r += 8) {
        int k = kt + ty + r, n = nt + tx;
        float v = (k < 512) ? Wh[(size_t)k*Vv + n] : Wr[(size_t)(k-512)*Vv + n];
        tile[ty+r][tx] = v;
    }
    __syncthreads();
#pragma unroll
    for (int r = 0; r < 32; r += 8) {
        int n = nt + ty + r, k = kt + tx;
        float v = tile[tx][ty+r];
        __nv_bfloat16 hi = __float2bfloat16(v);
        __nv_bfloat16 lo = __float2bfloat16(v - __bfloat162float(hi));
        g_Whi[(size_t)n*KTOT + k] = hi;
        g_Wlo[(size_t)n*KTOT + k] = lo;
    }
}

// ---------------- A split (h_f part) ----------------
__global__ void k_convA1() {
    int stride = gridDim.x*blockDim.x;
    for (int idx = blockIdx.x*blockDim.x + threadIdx.x; idx < Mrows*512; idx += stride) {
        int m = idx >> 9, k = idx & 511;
        float v = g_hf[(size_t)m*Ee + k];
        __nv_bfloat16 hi = __float2bfloat16(v);
        __nv_bfloat16 lo = __float2bfloat16(v - __bfloat162float(hi));
        g_Ab[(size_t)m*(2*KTOT) + k]        = hi;
        g_Ab[(size_t)m*(2*KTOT) + KTOT + k] = lo;
    }
}

// ---------------- transpose W_if_r ----------------
__global__ void k_twifr(const float* __restrict__ W) {
    __shared__ float tile[32][33];
    int ct = blockIdx.x*32, dt = blockIdx.y*32;
    int tx = threadIdx.x, ty = threadIdx.y;
#pragma unroll
    for (int r = 0; r < 32; r += 8) {
        int d = dt + ty + r, c = ct + tx;
        tile[ty+r][tx] = (c < IFc) ? W[(size_t)d*IFc + c] : 0.f;
    }
    __syncthreads();
#pragma unroll
    for (int r = 0; r < 32; r += 8) {
        int c = ct + ty + r, d = dt + tx;
        if (c < IFc) g_wifrT[(size_t)c*Dd + d] = tile[tx][ty+r];
    }
}

// ---------------- bf16 mma.sync + ldmatrix ----------------
__device__ __forceinline__ void mma16816(float* c, const uint32_t* a, const uint32_t* b) {
    asm volatile(
        "mma.sync.aligned.m16n8k16.row.col.f32.bf16.bf16.f32 "
        "{%0,%1,%2,%3}, {%4,%5,%6,%7}, {%8,%9}, {%0,%1,%2,%3};"
        : "+f"(c[0]), "+f"(c[1]), "+f"(c[2]), "+f"(c[3])
        : "r"(a[0]), "r"(a[1]), "r"(a[2]), "r"(a[3]), "r"(b[0]), "r"(b[1]));
}
__device__ __forceinline__ void ldmat_x4(uint32_t* r, uint32_t saddr) {
    asm volatile("ldmatrix.sync.aligned.m8n8.x4.shared.b16 {%0,%1,%2,%3}, [%4];"
        : "=r"(r[0]), "=r"(r[1]), "=r"(r[2]), "=r"(r[3]) : "r"(saddr));
}

// ---------------- shared layouts ----------------
struct GemmSm {
    __nv_bfloat16 As[2][128][40];
    __nv_bfloat16 Bs[2][128][40];
};
struct ScanSm {
    float ssim2[2][Nn];
    float skr[64], skw[64];
    float kq[128];
    float wtop[2][4][8]; int witop[2][4][8];
    float lw2[2][48]; int li2[2][48];
    int cnt[2];
    float scal2[2][4];
    float s_scal[4];
    float rvred[4][64];
};

// ---------------- one 128x128 logits tile (ldmatrix inner loop) ----------------
__device__ void lgemm_tile(GemmSm* sm, int m0, int n0, int kb, int nseg,
                           const float* __restrict__ bias, float* __restrict__ C, int accum) {
    const int tid = threadIdx.x, wid = tid >> 5, lane = tid & 31;
    const int wm = (wid & 1) * 64, wn = (wid >> 1) * 32;
    const int nchunks = nseg * 3;

    const uint32_t aBase0 = (uint32_t)__cvta_generic_to_shared(&sm->As[0][0][0]);
    const uint32_t bBase0 = (uint32_t)__cvta_generic_to_shared(&sm->Bs[0][0][0]);
    const uint32_t aLane = (uint32_t)((wm + (lane & 15)) * 80 + ((lane >> 4) * 8) * 2);
    const uint32_t bLane = (uint32_t)((wn + ((lane >> 4) & 1) * 8 + (lane & 7)) * 80
                                      + (((lane >> 3) & 1) * 8) * 2);

    float acc[4][4][4];
#pragma unroll
    for (int mi = 0; mi < 4; mi++)
#pragma unroll
        for (int ni = 0; ni < 4; ni++)
#pragma unroll
            for (int j = 0; j < 4; j++) acc[mi][ni][j] = 0.f;

    uint4 aR[2], bR[2];
    auto ldg = [&](int c) {
        int seg = c / nseg, kin = kb + (c - seg*nseg)*32;
        const __nv_bfloat16* Aseg = g_Ab + (seg == 2 ? KTOT : 0);
        const __nv_bfloat16* Wseg = (seg == 1) ? g_Wlo : g_Whi;
#pragma unroll
        for (int v = 0; v < 2; v++) {
            int i = tid + v*256;
            int row = i >> 2, cg = i & 3;
            aR[v] = *(const uint4*)(Aseg + (size_t)(m0+row)*(2*KTOT) + kin + cg*8);
            bR[v] = *(const uint4*)(Wseg + (size_t)(n0+row)*KTOT    + kin + cg*8);
        }
    };
    auto sts = [&](int buf) {
#pragma unroll
        for (int v = 0; v < 2; v++) {
            int i = tid + v*256;
            int row = i >> 2, cg = i & 3;
            *(uint4*)&sm->As[buf][row][cg*8] = aR[v];
            *(uint4*)&sm->Bs[buf][row][cg*8] = bR[v];
        }
    };
    auto comp = [&](int buf) {
        uint32_t aB = aBase0 + (uint32_t)buf*10240u + aLane;
        uint32_t bB = bBase0 + (uint32_t)buf*10240u + bLane;
#pragma unroll
        for (int kt = 0; kt < 32; kt += 16) {
            uint32_t af[4][4], bq[2][4];
#pragma unroll
            for (int mi = 0; mi < 4; mi++)
                ldmat_x4(af[mi], aB + (uint32_t)(mi*16*80) + (uint32_t)(kt*2));
#pragma unroll
            for (int p = 0; p < 2; p++)
                ldmat_x4(bq[p], bB + (uint32_t)(p*16*80) + (uint32_t)(kt*2));
#pragma unroll
            for (int mi = 0; mi < 4; mi++)
#pragma unroll
                for (int ni = 0; ni < 4; ni++)
                    mma16816(acc[mi][ni], af[mi], &bq[ni >> 1][(ni & 1) * 2]);
        }
    };

    ldg(0); sts(0); __syncthreads();
    int cur = 0;
    for (int c = 1; c < nchunks; c++) {
        ldg(c);
        comp(cur);
        sts(cur^1);
        __syncthreads();
        cur ^= 1;
    }
    comp(cur);

    const int r = lane >> 2, c2 = (lane & 3) * 2;
#pragma unroll
    for (int mi = 0; mi < 4; mi++) {
        int row0 = m0 + wm + mi*16 + r;
#pragma unroll
        for (int ni = 0; ni < 4; ni++) {
            int col = n0 + wn + ni*8 + c2;
            float2 v0, v1;
            if (accum) {
                float2 o0 = *(const float2*)&C[(size_t)row0*Vv + col];
                float2 o1 = *(const float2*)&C[(size_t)(row0+8)*Vv + col];
                v0.x = acc[mi][ni][0] + o0.x; v0.y = acc[mi][ni][1] + o0.y;
                v1.x = acc[mi][ni][2] + o1.x; v1.y = acc[mi][ni][3] + o1.y;
            } else {
                v0.x = acc[mi][ni][0] + bias[col]; v0.y = acc[mi][ni][1] + bias[col+1];
                v1.x = acc[mi][ni][2] + bias[col]; v1.y = acc[mi][ni][3] + bias[col+1];
            }
            *(float2*)&C[(size_t)row0*Vv + col]     = v0;
            *(float2*)&C[(size_t)(row0+8)*Vv + col] = v1;
        }
    }
}

// ---------------- worker loop: p1 tiles then gated p2 tiles ----------------
__device__ void worker_loop(GemmSm* gsm, volatile int* s_tile,
                            const float* __restrict__ bias, float* __restrict__ out) {
    const int tid = threadIdx.x;
    volatile unsigned* vgen = &g_gen;
    for (;;) {
        if (tid == 0) *s_tile = (int)atomicAdd(&g_tile, 1u);
        __syncthreads();
        int tl = *s_tile;
        if (tl >= NT_TOT) break;
        if (tl < NT_P1) {
            lgemm_tile(gsm, (tl/250)*128, (tl%250)*128, 0, 16, bias, out, 0);
        } else {
            int id = tl - NT_P1;
            int grp = id / 250, nt = id % 250;
            int mt = (grp < 8) ? (2*grp) : (2*(grp-8)+1);
            unsigned need = (mt & 1) ? 510u : 254u;
            if (tid == 0) { while (*vgen < need) __nanosleep(128); }
            __syncthreads();
            __threadfence();
            lgemm_tile(gsm, mt*128, nt*128, 512, 8, nullptr, out, 1);
        }
        __syncthreads();
    }
}

// ---------------- scan init ----------------
__global__ void k_scan_init(const float* __restrict__ mem_init, const float* __restrict__ iface,
                            const float* __restrict__ b_if) {
    int stride = gridDim.x*blockDim.x;
    int tid0 = blockIdx.x*blockDim.x + threadIdx.x;
    for (int idx = tid0; idx < Bb*Nn*Dd; idx += stride)
        g_mem[idx] = mem_init[idx % (Nn*Dd)];
    for (int idx = tid0; idx < 32*64*Nn; idx += stride) {
        int n = idx & (Nn-1);
        int rest = idx >> 11;
        int d = rest & 63;
        int bh = rest >> 6;
        int h = bh & 3;
        g_memT[idx] = mem_init[(size_t)n*Dd + h*64 + d];
    }
    for (int idx = tid0; idx < 32*Nn; idx += stride) {
        int n = idx & (Nn-1);
        int bh = idx >> 11;
        int h = bh & 3;
        const float* r = mem_init + (size_t)n*Dd + h*HD;
        float s = 0.f;
#pragma unroll
        for (int d = 0; d < HD; d++) s += r[d]*r[d];
        g_sumsq[idx] = s;
    }
    for (int idx = tid0; idx < Bb*IFc; idx += stride) {
        int b = idx / IFc, c = idx - b*IFc;
        g_ibuf[0][idx] = iface[((size_t)(b*Tt))*IFc + c] + b_if[c];
    }
    for (int idx = tid0; idx < Bb*Dd; idx += stride) {
        g_rv[idx] = 0.f;
        int b = idx / Dd, kk = idx % Dd;
        size_t m = (size_t)b*Tt;
        __nv_bfloat16 z = __float2bfloat16(0.f);
        g_Ab[m*(2*KTOT) + 512 + kk]        = z;
        g_Ab[m*(2*KTOT) + KTOT + 512 + kk] = z;
    }
    if (tid0 == 0) { g_cnt = 0u; g_gen = 0u; g_tile = 0u; g_rvflag = 0u; }
}

// ---------------- software grid barrier (volatile-load polling) ----------------
__device__ __forceinline__ void gridbar() {
    __syncthreads();
    if (threadIdx.x == 0) {
        volatile unsigned* vgen = &g_gen;
        __threadfence();
        unsigned gen = *vgen;
        if (atomicAdd(&g_cnt, 1u) == GRIDB - 1u) {
            atomicExch(&g_cnt, 0u);
            __threadfence();
            atomicExch(&g_gen, gen + 1u);
        } else {
            while (*vgen == gen) { }
        }
    }
    __syncthreads();
}

__device__ __forceinline__ float sigmoidf_(float x) { return 1.f/(1.f + expf(-x)); }

// ---------------- persistent scan + fused logits workers ----------------
__global__ void __launch_bounds__(256, 2) k_scan(const float* __restrict__ iface,
                                                 const float* __restrict__ b_if,
                                                 const float* __restrict__ brp,
                                                 const float* __restrict__ bwp,
                                                 const float* __restrict__ bias,
                                                 float* __restrict__ out) {
    __shared__ __align__(16) char smraw[sizeof(GemmSm)];
    __shared__ int s_tile;
    const int blk = blockIdx.x, tid = threadIdx.x;
    GemmSm* gsm = reinterpret_cast<GemmSm*>(smraw);

    if (blk >= GRIDB) {
        worker_loop(gsm, &s_tile, bias, out);
        return;
    }

    ScanSm& S = *reinterpret_cast<ScanSm*>(smraw);
    const int warp = tid >> 5, lane = tid & 31;

    float beta_r, beta_w;
    {
        float b0 = *brp; b0 = log1pf(expf(b0)); beta_r = fminf(fmaxf(b0, 1.f), 20.f);
        float b1 = *bwp; b1 = log1pf(expf(b1)); beta_w = fminf(fmaxf(b1, 1.f), 20.f);
    }
    const int s_bh = blk >> 2, s_sub = blk & 3;
    const int s_b = s_bh >> 2, s_h = s_bh & 3;
    const int c_b = blk >> 2, c_h = blk & 3;
    const int c_bh = blk;

    for (int t = 0; t < Tt; t++) {
        const float* ib = g_ibuf[t & 1];
        // ---------- SIM ----------
        {
            if (tid < 128) {
                int rw = tid >> 6, d = tid & 63;
                float kx = ib[s_b*IFc + rw*Dd + s_h*64 + d];
                if (rw) S.skw[d] = kx; else S.skr[d] = kx;
                S.kq[tid] = kx*kx;
            }
            __syncthreads();
            if (tid < 2) {
                float s = 0.f;
                for (int d2 = 0; d2 < 64; d2++) s += S.kq[tid*64 + d2];
                S.s_scal[tid] = rsqrtf(s + 1e-8f);
            }
            __syncthreads();
            if (tid < 128) {
                int rw = tid >> 6, d = tid & 63;
                if (rw) S.skw[d] *= S.s_scal[1]; else S.skr[d] *= S.s_scal[0];
            }
            __syncthreads();
            int nbase = s_sub*512;
            const float* mt = g_memT + (size_t)s_bh*64*Nn + nbase;
            float ar0 = 0.f, aw0 = 0.f, ar1 = 0.f, aw1 = 0.f;
#pragma unroll 8
            for (int d = 0; d < 64; d++) {
                float kr = S.skr[d], kw = S.skw[d];
                float m0 = mt[(size_t)d*Nn + tid];
                float m1 = mt[(size_t)d*Nn + tid + 256];
                ar0 += m0*kr; aw0 += m0*kw;
                ar1 += m1*kr; aw1 += m1*kw;
            }
            int n1 = nbase + tid, n2 = n1 + 256;
            float i1 = rsqrtf(g_sumsq[s_bh*Nn + n1] + 1e-8f);
            float i2 = rsqrtf(g_sumsq[s_bh*Nn + n2] + 1e-8f);
            g_sim[(size_t)s_bh*Nn + n1]        = ar0 * i1;
            g_sim[(size_t)s_bh*Nn + n2]        = ar1 * i2;
            g_sim[(size_t)(32 + s_bh)*Nn + n1] = aw0 * i1;
            g_sim[(size_t)(32 + s_bh)*Nn + n2] = aw1 * i2;
        }
        gridbar();   // bar A
        // ---------- phase C (blocks 0..31)  ||  iface t+1 (blocks 32..127) ----------
        if (blk < 32) {
            const int half = warp >> 5 ? 0 : (warp >> 2);   // warp/4: 0=read,1=write
            const int hw = warp & 3;
            const float beta = half ? beta_w : beta_r;
            const float* s0 = g_sim + ((size_t)(half*32 + blk))*Nn;
            float v[16];
#pragma unroll
            for (int j = 0; j < 16; j++) {
                int n = hw*512 + j*32 + lane;
                v[j] = s0[n];
                S.ssim2[half][n] = v[j];
            }
            if (tid < 2) S.cnt[tid] = 0;
            float wt8[8]; int wi8[8];
#pragma unroll
            for (int k = 0; k < TOPK; k++) {
                float bv = -3.4e38f; int bj = 0;
#pragma unroll
                for (int j = 0; j < 16; j++) if (v[j] > bv) { bv = v[j]; bj = j; }
                int bi = hw*512 + bj*32 + lane;
#pragma unroll
                for (int off = 16; off > 0; off >>= 1) {
                    float ov = __shfl_xor_sync(0xffffffffu, bv, off);
                    int   oi = __shfl_xor_sync(0xffffffffu, bi, off);
                    if (ov > bv || (ov == bv && oi < bi)) { bv = ov; bi = oi; }
                }
                wt8[k] = bv; wi8[k] = bi;
                if (lane == (bi & 31)) v[(bi >> 5) & 15] = -3.4e38f;
            }
            if (lane < 8) { S.wtop[half][hw][lane] = wt8[lane]; S.witop[half][hw][lane] = wi8[lane]; }
            __syncthreads();
            if (hw == 0) {
                float cv = S.wtop[half][lane >> 3][lane & 7];
                int   ci = S.witop[half][lane >> 3][lane & 7];
#pragma unroll
                for (int k = 0; k < TOPK; k++) {
                    float bv = cv; int bi = ci;
#pragma unroll
                    for (int off = 16; off > 0; off >>= 1) {
                        float ov = __shfl_xor_sync(0xffffffffu, bv, off);
                        int   oi = __shfl_xor_sync(0xffffffffu, bi, off);
                        if (ov > bv || (ov == bv && oi < bi)) { bv = ov; bi = oi; }
                    }
                    if (lane == 0) {
                        if (k == 0)       S.scal2[half][0] = bv;
                        if (k == TOPK-1)  S.scal2[half][1] = bv;
                    }
                    if (ci == bi) cv = -3.4e38f;
                }
            }
            __syncthreads();
            float smax = S.scal2[half][0], kth = S.scal2[half][1];
#pragma unroll
            for (int j = 0; j < 16; j++) {
                int n = hw*512 + j*32 + lane;
                float sv = S.ssim2[half][n];
                if (sv >= kth) {
                    int p = atomicAdd(&S.cnt[half], 1);
                    if (p < 48) { S.li2[half][p] = n; S.lw2[half][p] = expf(beta*(sv - smax)); }
                }
            }
            __syncthreads();
            if (tid == 0 || tid == 128) {
                int hh = tid >> 7;
                int ln = S.cnt[hh] < 48 ? S.cnt[hh] : 48;
                for (int a2 = 1; a2 < ln; a2++) {
                    int key = S.li2[hh][a2]; float kw2 = S.lw2[hh][a2]; int c2s = a2 - 1;
                    while (c2s >= 0 && S.li2[hh][c2s] > key) {
                        S.li2[hh][c2s+1] = S.li2[hh][c2s]; S.lw2[hh][c2s+1] = S.lw2[hh][c2s]; c2s--;
                    }
                    S.li2[hh][c2s+1] = key; S.lw2[hh][c2s+1] = kw2;
                }
                float s = 0.f;
                for (int j = 0; j < ln; j++) s += S.lw2[hh][j];
                S.scal2[hh][2] = 1.f / s;
                S.cnt[hh] = ln;
            }
            __syncthreads();
            // rv gather
            {
                int ln0 = S.cnt[0];
                float inv0 = S.scal2[0][2];
                int d = tid & 63, jj = tid >> 6;
                float part = 0.f;
                for (int j = jj; j < ln0; j += 4)
                    part += (S.lw2[0][j]*inv0) * g_mem[((size_t)(c_b*Nn + S.li2[0][j]))*Dd + c_h*64 + d];
                S.rvred[jj][d] = part;
            }
            __syncthreads();
            if (tid < 64) {
                float acc = S.rvred[0][tid] + S.rvred[1][tid] + S.rvred[2][tid] + S.rvred[3][tid];
                g_rv[c_b*Dd + c_h*64 + tid] = acc;
                if (t + 1 < Tt) {
                    size_t m = (size_t)(c_b*Tt + t + 1);
                    __nv_bfloat16 hi = __float2bfloat16(acc);
                    __nv_bfloat16 lo = __float2bfloat16(acc - __bfloat162float(hi));
                    g_Ab[m*(2*KTOT) + 512 + c_h*64 + tid]        = hi;
                    g_Ab[m*(2*KTOT) + KTOT + 512 + c_h*64 + tid] = lo;
                }
            }
            __syncthreads();
            // signal rv ready (release), then mem update
            if (tid == 0) { __threadfence(); atomicAdd(&g_rvflag, 1u); }
            {
                int ln1 = S.cnt[1];
                float inv1 = S.scal2[1][2];
                float gh   = sigmoidf_(ib[c_b*IFc + 4*Dd + c_h]);
                float er0  = sigmoidf_(ib[c_b*IFc + 3*Dd + c_h*64 + lane]);
                float er1  = sigmoidf_(ib[c_b*IFc + 3*Dd + c_h*64 + lane + 32]);
                float val0 = ib[c_b*IFc + 2*Dd + c_h*64 + lane];
                float val1 = ib[c_b*IFc + 2*Dd + c_h*64 + lane + 32];
                for (int j = warp; j < ln1; j += 8) {
                    int n = S.li2[1][j]; float w = S.lw2[1][j]*inv1;
                    size_t base = ((size_t)(c_b*Nn + n))*Dd + c_h*64;
                    float m0 = g_mem[base + lane], m1 = g_mem[base + lane + 32];
                    float nm0 = m0*(1.f - w*er0) + w*(gh*val0);
                    float nm1 = m1*(1.f - w*er1) + w*(gh*val1);
                    g_mem[base + lane] = nm0;
                    g_mem[base + lane + 32] = nm1;
                    g_memT[((size_t)c_bh*64 + lane)*Nn + n]      = nm0;
                    g_memT[((size_t)c_bh*64 + lane + 32)*Nn + n] = nm1;
                    float ss2 = nm0*nm0 + nm1*nm1;
#pragma unroll
                    for (int off = 16; off > 0; off >>= 1) ss2 += __shfl_down_sync(0xffffffffu, ss2, off);
                    if (lane == 0) g_sumsq[c_bh*Nn + n] = ss2;
                }
            }
        } else if (t + 1 < Tt) {
            // wait for all 32 phase-C blocks' rv, then compute iface for t+1
            if (tid == 0) {
                volatile unsigned* vf = &g_rvflag;
                unsigned target = 32u*(unsigned)(t + 1);
                while (*vf < target) { }
            }
            __syncthreads();
            __threadfence();
            for (int idx = (blk-32)*256 + tid; idx < Bb*IFc; idx += 96*256) {
                int b2 = idx / IFc, c = idx - b2*IFc;
                float acc = iface[((size_t)(b2*Tt + t + 1))*IFc + c] + b_if[c];
                const float4* wp = (const float4*)(g_wifrT + (size_t)c*Dd);
                const float4* rp = (const float4*)(g_rv + b2*Dd);
#pragma unroll 8
                for (int d4 = 0; d4 < Dd/4; d4++) {
                    float4 w4 = wp[d4], r4 = rp[d4];
                    acc += r4.x*w4.x + r4.y*w4.y + r4.z*w4.z + r4.w*w4.w;
                }
                g_ibuf[(t + 1) & 1][idx] = acc;
            }
        }
        gridbar();   // bar B
    }

    worker_loop(gsm, &s_tile, bias, out);
}

static float* addr_of(const void* symbol) {
    void* p = nullptr;
    cudaGetSymbolAddress(&p, symbol);
    return (float*)p;
}

extern "C" void kernel_launch(void* const* d_in, const int* in_sizes, int n_in,
                              void* d_out, int out_size) {
    const int*   input_seq = (const int*)  d_in[0];
    const float* emb       = (const float*)d_in[1];
    const float* pos       = (const float*)d_in[2];
    const float* ln1_g     = (const float*)d_in[3];
    const float* ln1_b     = (const float*)d_in[4];
    const float* ln2_g     = (const float*)d_in[5];
    const float* ln2_b     = (const float*)d_in[6];
    const float* Wq        = (const float*)d_in[7];
    const float* Wk        = (const float*)d_in[8];
    const float* Wv        = (const float*)d_in[9];
    const float* Wo        = (const float*)d_in[10];
    const float* W1        = (const float*)d_in[11];
    const float* b1        = (const float*)d_in[12];
    const float* W2        = (const float*)d_in[13];
    const float* b2        = (const float*)d_in[14];
    const float* lnf_g     = (const float*)d_in[15];
    const float* lnf_b     = (const float*)d_in[16];
    const float* W_if_h    = (const float*)d_in[17];
    const float* W_if_r    = (const float*)d_in[18];
    const float* b_if      = (const float*)d_in[19];
    const float* W_lg_h    = (const float*)d_in[20];
    const float* W_lg_r    = (const float*)d_in[21];
    const float* b_lg      = (const float*)d_in[22];
    const float* beta_read = (const float*)d_in[23];
    const float* beta_write= (const float*)d_in[24];
    const float* mem_init  = (const float*)d_in[25];
    float* out = (float*)d_out;

    static float* p_x = nullptr, *p_h, *p_q, *p_k, *p_v, *p_attno, *p_hf, *p_ffn, *p_iface;
    if (!p_x) {
        p_x      = addr_of(g_x);      p_h     = addr_of(g_h);
        p_q      = addr_of(g_q);      p_k     = addr_of(g_k);
        p_v      = addr_of(g_v);      p_attno = addr_of(g_attno);
        p_hf     = addr_of(g_hf);     p_ffn   = addr_of(g_ffn);
        p_iface  = addr_of(g_iface);
    }

    k_embed<<<2048, 256>>>(input_seq, emb, pos);
    k_convW<<<dim3(Vv/32, KTOT/32), dim3(32,8)>>>(W_lg_h, W_lg_r);
    k_twifr<<<dim3((IFc+31)/32, Dd/32), dim3(32,8)>>>(W_if_r);

    dim3 gE(4, 32);
    dim3 gF(16, 16);
    for (int l = 0; l < Ll; l++) {
        k_ln<<<Mrows, 256>>>(p_x, p_h, ln1_g + l*Ee, ln1_b + l*Ee);
        k_gemm<64,4><<<gE, 256>>>(p_h, Wq + (size_t)l*Ee*Ee, nullptr, nullptr, p_q, Mrows, Ee, Ee, 0);
        k_gemm<64,4><<<gE, 256>>>(p_h, Wk + (size_t)l*Ee*Ee, nullptr, nullptr, p_k, Mrows, Ee, Ee, 0);
        k_gemm<64,4><<<gE, 256>>>(p_h, Wv + (size_t)l*Ee*Ee, nullptr, nullptr, p_v, Mrows, Ee, Ee, 0);
        k_attn<<<dim3(Tt, HA, Bb), 256>>>();
        k_gemm<64,4><<<gE, 256>>>(p_attno, Wo + (size_t)l*Ee*Ee, nullptr, p_x, p_x, Mrows, Ee, Ee, 0);
        k_ln<<<Mrows, 256>>>(p_x, p_h, ln2_g + l*Ee, ln2_b + l*Ee);
        k_gemm<128,8><<<gF, 256>>>(p_h, W1 + (size_t)l*Ee*Ff, b1 + l*Ff, nullptr, p_ffn, Mrows, Ee, Ff, 1);
        k_gemm<64,4><<<gE, 256>>>(p_ffn, W2 + (size_t)l*Ff*Ee, b2 + l*Ee, p_x, p_x, Mrows, Ff, Ee, 0);
    }

    k_ln<<<Mrows, 256>>>(p_x, p_hf, lnf_g, lnf_b);
    k_gemm<128,8><<<dim3(9, 16), 256>>>(p_hf, W_if_h, nullptr, nullptr, p_iface, Mrows, Ee, IFc, 0);

    k_convA1<<<2048, 256>>>();

    k_scan_init<<<2048, 256>>>(mem_init, p_iface, b_if);
    k_scan<<<GRIDB + WORKERS, 256>>>(p_iface, b_if, beta_read, beta_write, b_lg, out);
}

// round 10
// speedup vs baseline: 1.8774x; 1.0381x over previous
#include <cuda_runtime.h>
#include <cuda_bf16.h>
#include <cuda_fp16.h>
#include <math.h>
#include <stdint.h>

// ---------------- problem constants ----------------
#define Vv 32000
#define Ee 512
#define Ff 2048
#define Dd 256
#define Nn 2048
#define Ll 2
#define Bb 8
#define Tt 256
#define HM 4
#define TOPK 8
#define HA 8
#define HD 64
#define DH 64
#define IFc 1028
#define Mrows (Bb*Tt)
#define GRIDB 128
#define WORKERS 168
#define KTOT 768
#define NT_P1 4000
#define NT_TOT 8000

// ---------------- scratch ----------------
__device__ float g_x[Mrows*Ee];
__device__ float g_h[Mrows*Ee];
__device__ float g_q[Mrows*Ee];
__device__ float g_k[Mrows*Ee];
__device__ float g_v[Mrows*Ee];
__device__ float g_attno[Mrows*Ee];
__device__ float g_hf[Mrows*Ee];
__device__ float g_ffn[Mrows*Ff];
__device__ float g_iface[Mrows*IFc];
__device__ float g_mem[Bb*Nn*Dd];
__device__ float g_memT[32*64*Nn];
__device__ float g_sumsq[32*Nn];
__device__ float g_rv[Bb*Dd];
__device__ float g_ibuf[2][Bb*IFc];
__device__ float g_sim[2*Bb*HM*Nn];
__device__ float g_wifrT[IFc*Dd];
__device__ __half g_W16[(size_t)Vv*KTOT];   // [n][k] fp16
__device__ __half g_A16[(size_t)Mrows*KTOT]; // [m][hf(512) | rv(256)] fp16
__device__ unsigned g_cnt;
__device__ unsigned g_gen;
__device__ unsigned g_tile;
__device__ unsigned g_rvflag;

// ---------------- embedding ----------------
__global__ void k_embed(const int* __restrict__ seq, const float* __restrict__ emb,
                        const float* __restrict__ pos) {
    int stride = gridDim.x * blockDim.x;
    for (int idx = blockIdx.x*blockDim.x + threadIdx.x; idx < Mrows*Ee; idx += stride) {
        int e  = idx % Ee;
        int bt = idx / Ee;
        int t  = bt % Tt;
        g_x[idx] = emb[(size_t)seq[bt]*Ee + e] + pos[t*Ee + e];
    }
}

// ---------------- layernorm ----------------
__global__ void k_ln(const float* __restrict__ in, float* __restrict__ outp,
                     const float* __restrict__ g, const float* __restrict__ b) {
    int row = blockIdx.x;
    int tid = threadIdx.x;
    const float* x = in + (size_t)row*Ee;
    __shared__ float red[256];
    float v0 = x[tid], v1 = x[tid+256];
    red[tid] = v0 + v1;
    __syncthreads();
    for (int s = 128; s > 0; s >>= 1) { if (tid < s) red[tid] += red[tid+s]; __syncthreads(); }
    float mean = red[0] * (1.f/Ee);
    __syncthreads();
    float d0 = v0 - mean, d1 = v1 - mean;
    red[tid] = d0*d0 + d1*d1;
    __syncthreads();
    for (int s = 128; s > 0; s >>= 1) { if (tid < s) red[tid] += red[tid+s]; __syncthreads(); }
    float inv = rsqrtf(red[0] * (1.f/Ee) + 1e-5f);
    outp[(size_t)row*Ee + tid]       = d0*inv*g[tid]     + b[tid];
    outp[(size_t)row*Ee + tid + 256] = d1*inv*g[tid+256] + b[tid+256];
}

__device__ __forceinline__ float geluf_(float xx) {
    float tt = tanhf(0.7978845608028654f * (xx + 0.044715f*xx*xx*xx));
    return 0.5f * xx * (1.f + tt);
}

// ---------------- SIMT GEMM (transformer-sized) ----------------
template<int BM, int TM>
__global__ void __launch_bounds__(256) k_gemm(const float* __restrict__ A, const float* __restrict__ W,
                       const float* __restrict__ bias, const float* __restrict__ res,
                       float* __restrict__ C, int M, int K, int N, int act) {
    __shared__ float As[2][16][BM];
    __shared__ float Bs[2][16][128];
    const int tid = threadIdx.x;
    const int bm = blockIdx.y * BM, bn = blockIdx.x * 128;
    const int tx = tid & 15, ty = tid >> 4;
    constexpr int AV = BM/64;
    float4 aR[AV], bR[2];
    float acc[TM][8];
#pragma unroll
    for (int i = 0; i < TM; i++)
#pragma unroll
        for (int j = 0; j < 8; j++) acc[i][j] = 0.f;

    auto ldg = [&](int k0) {
#pragma unroll
        for (int v = 0; v < AV; v++) {
            int i = tid + v*256;
            int row = i >> 2, cg = i & 3;
            aR[v] = *(const float4*)(A + (size_t)(bm+row)*K + k0 + cg*4);
        }
#pragma unroll
        for (int v = 0; v < 2; v++) {
            int i = tid + v*256;
            int row = i >> 5, cg = i & 31;
            int col = bn + cg*4;
            if (col < N) bR[v] = *(const float4*)(W + (size_t)(k0+row)*N + col);
            else { bR[v].x = bR[v].y = bR[v].z = bR[v].w = 0.f; }
        }
    };
    auto sts = [&](int buf) {
#pragma unroll
        for (int v = 0; v < AV; v++) {
            int i = tid + v*256;
            int row = i >> 2, cg = i & 3;
            As[buf][cg*4+0][row] = aR[v].x; As[buf][cg*4+1][row] = aR[v].y;
            As[buf][cg*4+2][row] = aR[v].z; As[buf][cg*4+3][row] = aR[v].w;
        }
#pragma unroll
        for (int v = 0; v < 2; v++) {
            int i = tid + v*256;
            int row = i >> 5, cg = i & 31;
            *(float4*)&Bs[buf][row][cg*4] = bR[v];
        }
    };
    auto comp = [&](int buf) {
#pragma unroll
        for (int kk = 0; kk < 16; kk++) {
            float a[TM], bfr[8];
#pragma unroll
            for (int v = 0; v < TM/4; v++)
                *(float4*)&a[v*4] = *(const float4*)&As[buf][kk][ty*TM + v*4];
            *(float4*)&bfr[0] = *(const float4*)&Bs[buf][kk][tx*8];
            *(float4*)&bfr[4] = *(const float4*)&Bs[buf][kk][tx*8+4];
#pragma unroll
            for (int i = 0; i < TM; i++)
#pragma unroll
                for (int j = 0; j < 8; j++) acc[i][j] += a[i]*bfr[j];
        }
    };

    ldg(0); sts(0); __syncthreads();
    int cur = 0;
    for (int k0 = 16; k0 < K; k0 += 16) {
        ldg(k0);
        comp(cur);
        sts(cur^1);
        __syncthreads();
        cur ^= 1;
    }
    comp(cur);

#pragma unroll
    for (int i = 0; i < TM; i++) {
        int row = bm + ty*TM + i;
#pragma unroll
        for (int jv = 0; jv < 2; jv++) {
            int col = bn + tx*8 + jv*4;
            if (col < N) {
                float4 v4;
                v4.x = acc[i][jv*4+0]; v4.y = acc[i][jv*4+1];
                v4.z = acc[i][jv*4+2]; v4.w = acc[i][jv*4+3];
                if (bias) { v4.x += bias[col]; v4.y += bias[col+1]; v4.z += bias[col+2]; v4.w += bias[col+3]; }
                if (act == 1) { v4.x = geluf_(v4.x); v4.y = geluf_(v4.y); v4.z = geluf_(v4.z); v4.w = geluf_(v4.w); }
                if (res) {
                    float4 r4 = *(const float4*)&res[(size_t)row*N + col];
                    v4.x += r4.x; v4.y += r4.y; v4.z += r4.z; v4.w += r4.w;
                }
                *(float4*)&C[(size_t)row*N + col] = v4;
            }
        }
    }
}

// ---------------- attention ----------------
__global__ void k_attn() {
    int t = blockIdx.x, hh = blockIdx.y, b = blockIdx.z;
    int tid = threadIdx.x;
    __shared__ float sq[64];
    __shared__ float ss[256];
    __shared__ float red[256];
    const float* qrow = g_q + ((size_t)(b*Tt + t))*Ee + hh*DH;
    if (tid < 64) sq[tid] = qrow[tid];
    __syncthreads();
    float lmax = -3.4e38f;
    for (int j = tid; j <= t; j += 256) {
        const float* krow = g_k + ((size_t)(b*Tt + j))*Ee + hh*DH;
        float d = 0.f;
#pragma unroll
        for (int e = 0; e < 64; e++) d += sq[e]*krow[e];
        d *= 0.125f;
        ss[j] = d;
        lmax = fmaxf(lmax, d);
    }
    red[tid] = lmax;
    __syncthreads();
    for (int s = 128; s > 0; s >>= 1) { if (tid < s) red[tid] = fmaxf(red[tid], red[tid+s]); __syncthreads(); }
    float mx = red[0];
    __syncthreads();
    float lsum = 0.f;
    for (int j = tid; j <= t; j += 256) { float p = expf(ss[j]-mx); ss[j] = p; lsum += p; }
    red[tid] = lsum;
    __syncthreads();
    for (int s = 128; s > 0; s >>= 1) { if (tid < s) red[tid] += red[tid+s]; __syncthreads(); }
    float inv = 1.f / red[0];
    __syncthreads();
    if (tid < 64) {
        float acc = 0.f;
        for (int j = 0; j <= t; j++)
            acc += ss[j] * g_v[((size_t)(b*Tt + j))*Ee + hh*DH + tid];
        g_attno[((size_t)(b*Tt + t))*Ee + hh*DH + tid] = acc * inv;
    }
}

// ---------------- W_lg fp16 convert + transpose ----------------
__global__ void k_convW(const float* __restrict__ Wh, const float* __restrict__ Wr) {
    __shared__ float tile[32][33];
    int nt = blockIdx.x*32, kt = blockIdx.y*32;
    int tx = threadIdx.x, ty = threadIdx.y;
#pragma unroll
    for (int r = 0; r < 32; r += 8) {
        int k = kt + ty + r, n = nt + tx;
        float v = (k < 512) ? Wh[(size_t)k*Vv + n] : Wr[(size_t)(k-512)*Vv + n];
        tile[ty+r][tx] = v;
    }
    __syncthreads();
#pragma unroll
    for (int r = 0; r < 32; r += 8) {
        int n = nt + ty + r, k = kt + tx;
        g_W16[(size_t)n*KTOT + k] = __float2half(tile[tx][ty+r]);
    }
}

// ---------------- A fp16 convert (h_f part) ----------------
__global__ void k_convA1() {
    int stride = gridDim.x*blockDim.x;
    for (int idx = blockIdx.x*blockDim.x + threadIdx.x; idx < Mrows*512; idx += stride) {
        int m = idx >> 9, k = idx & 511;
        g_A16[(size_t)m*KTOT + k] = __float2half(g_hf[(size_t)m*Ee + k]);
    }
}

// ---------------- transpose W_if_r ----------------
__global__ void k_twifr(const float* __restrict__ W) {
    __shared__ float tile[32][33];
    int ct = blockIdx.x*32, dt = blockIdx.y*32;
    int tx = threadIdx.x, ty = threadIdx.y;
#pragma unroll
    for (int r = 0; r < 32; r += 8) {
        int d = dt + ty + r, c = ct + tx;
        tile[ty+r][tx] = (c < IFc) ? W[(size_t)d*IFc + c] : 0.f;
    }
    __syncthreads();
#pragma unroll
    for (int r = 0; r < 32; r += 8) {
        int c = ct + ty + r, d = dt + tx;
        if (c < IFc) g_wifrT[(size_t)c*Dd + d] = tile[tx][ty+r];
    }
}

// ---------------- fp16 mma.sync + ldmatrix ----------------
__device__ __forceinline__ void mma16816(float* c, const uint32_t* a, const uint32_t* b) {
    asm volatile(
        "mma.sync.aligned.m16n8k16.row.col.f32.f16.f16.f32 "
        "{%0,%1,%2,%3}, {%4,%5,%6,%7}, {%8,%9}, {%0,%1,%2,%3};"
        : "+f"(c[0]), "+f"(c[1]), "+f"(c[2]), "+f"(c[3])
        : "r"(a[0]), "r"(a[1]), "r"(a[2]), "r"(a[3]), "r"(b[0]), "r"(b[1]));
}
__device__ __forceinline__ void ldmat_x4(uint32_t* r, uint32_t saddr) {
    asm volatile("ldmatrix.sync.aligned.m8n8.x4.shared.b16 {%0,%1,%2,%3}, [%4];"
        : "=r"(r[0]), "=r"(r[1]), "=r"(r[2]), "=r"(r[3]) : "r"(saddr));
}

// ---------------- shared layouts ----------------
struct GemmSm {
    __half As[2][128][40];
    __half Bs[2][128][40];
};
struct ScanSm {
    float ssim2[2][Nn];
    float skr[64], skw[64];
    float kq[128];
    float wtop[2][4][8]; int witop[2][4][8];
    float lw2[2][48]; int li2[2][48];
    int cnt[2];
    float scal2[2][4];
    float s_scal[4];
    float rvred[4][64];
};

// ---------------- one 128x128 logits tile (single fp16 pass) ----------------
__device__ void lgemm_tile(GemmSm* sm, int m0, int n0, int kb, int nchunks,
                           const float* __restrict__ bias, float* __restrict__ C, int accum) {
    const int tid = threadIdx.x, wid = tid >> 5, lane = tid & 31;
    const int wm = (wid & 1) * 64, wn = (wid >> 1) * 32;

    const uint32_t aBase0 = (uint32_t)__cvta_generic_to_shared(&sm->As[0][0][0]);
    const uint32_t bBase0 = (uint32_t)__cvta_generic_to_shared(&sm->Bs[0][0][0]);
    const uint32_t aLane = (uint32_t)((wm + (lane & 15)) * 80 + ((lane >> 4) * 8) * 2);
    const uint32_t bLane = (uint32_t)((wn + ((lane >> 4) & 1) * 8 + (lane & 7)) * 80
                                      + (((lane >> 3) & 1) * 8) * 2);

    float acc[4][4][4];
#pragma unroll
    for (int mi = 0; mi < 4; mi++)
#pragma unroll
        for (int ni = 0; ni < 4; ni++)
#pragma unroll
            for (int j = 0; j < 4; j++) acc[mi][ni][j] = 0.f;

    uint4 aR[2], bR[2];
    auto ldg = [&](int c) {
        int kin = kb + c*32;
#pragma unroll
        for (int v = 0; v < 2; v++) {
            int i = tid + v*256;
            int row = i >> 2, cg = i & 3;
            aR[v] = *(const uint4*)(g_A16 + (size_t)(m0+row)*KTOT + kin + cg*8);
            bR[v] = *(const uint4*)(g_W16 + (size_t)(n0+row)*KTOT + kin + cg*8);
        }
    };
    auto sts = [&](int buf) {
#pragma unroll
        for (int v = 0; v < 2; v++) {
            int i = tid + v*256;
            int row = i >> 2, cg = i & 3;
            *(uint4*)&sm->As[buf][row][cg*8] = aR[v];
            *(uint4*)&sm->Bs[buf][row][cg*8] = bR[v];
        }
    };
    auto comp = [&](int buf) {
        uint32_t aB = aBase0 + (uint32_t)buf*10240u + aLane;
        uint32_t bB = bBase0 + (uint32_t)buf*10240u + bLane;
#pragma unroll
        for (int kt = 0; kt < 32; kt += 16) {
            uint32_t af[4][4], bq[2][4];
#pragma unroll
            for (int mi = 0; mi < 4; mi++)
                ldmat_x4(af[mi], aB + (uint32_t)(mi*16*80) + (uint32_t)(kt*2));
#pragma unroll
            for (int p = 0; p < 2; p++)
                ldmat_x4(bq[p], bB + (uint32_t)(p*16*80) + (uint32_t)(kt*2));
#pragma unroll
            for (int mi = 0; mi < 4; mi++)
#pragma unroll
                for (int ni = 0; ni < 4; ni++)
                    mma16816(acc[mi][ni], af[mi], &bq[ni >> 1][(ni & 1) * 2]);
        }
    };

    ldg(0); sts(0); __syncthreads();
    int cur = 0;
    for (int c = 1; c < nchunks; c++) {
        ldg(c);
        comp(cur);
        sts(cur^1);
        __syncthreads();
        cur ^= 1;
    }
    comp(cur);

    const int r = lane >> 2, c2 = (lane & 3) * 2;
#pragma unroll
    for (int mi = 0; mi < 4; mi++) {
        int row0 = m0 + wm + mi*16 + r;
#pragma unroll
        for (int ni = 0; ni < 4; ni++) {
            int col = n0 + wn + ni*8 + c2;
            float2 v0, v1;
            if (accum) {
                float2 o0 = *(const float2*)&C[(size_t)row0*Vv + col];
                float2 o1 = *(const float2*)&C[(size_t)(row0+8)*Vv + col];
                v0.x = acc[mi][ni][0] + o0.x; v0.y = acc[mi][ni][1] + o0.y;
                v1.x = acc[mi][ni][2] + o1.x; v1.y = acc[mi][ni][3] + o1.y;
            } else {
                v0.x = acc[mi][ni][0] + bias[col]; v0.y = acc[mi][ni][1] + bias[col+1];
                v1.x = acc[mi][ni][2] + bias[col]; v1.y = acc[mi][ni][3] + bias[col+1];
            }
            *(float2*)&C[(size_t)row0*Vv + col]     = v0;
            *(float2*)&C[(size_t)(row0+8)*Vv + col] = v1;
        }
    }
}

// ---------------- worker loop ----------------
__device__ void worker_loop(GemmSm* gsm, volatile int* s_tile,
                            const float* __restrict__ bias, float* __restrict__ out) {
    const int tid = threadIdx.x;
    volatile unsigned* vgen = &g_gen;
    for (;;) {
        if (tid == 0) *s_tile = (int)atomicAdd(&g_tile, 1u);
        __syncthreads();
        int tl = *s_tile;
        if (tl >= NT_TOT) break;
        if (tl < NT_P1) {
            lgemm_tile(gsm, (tl/250)*128, (tl%250)*128, 0, 16, bias, out, 0);
        } else {
            int id = tl - NT_P1;
            int grp = id / 250, nt = id % 250;
            int mt = (grp < 8) ? (2*grp) : (2*(grp-8)+1);
            unsigned need = (mt & 1) ? 510u : 254u;
            if (tid == 0) { while (*vgen < need) __nanosleep(128); }
            __syncthreads();
            __threadfence();
            lgemm_tile(gsm, mt*128, nt*128, 512, 8, nullptr, out, 1);
        }
        __syncthreads();
    }
}

// ---------------- scan init ----------------
__global__ void k_scan_init(const float* __restrict__ mem_init, const float* __restrict__ iface,
                            const float* __restrict__ b_if) {
    int stride = gridDim.x*blockDim.x;
    int tid0 = blockIdx.x*blockDim.x + threadIdx.x;
    for (int idx = tid0; idx < Bb*Nn*Dd; idx += stride)
        g_mem[idx] = mem_init[idx % (Nn*Dd)];
    for (int idx = tid0; idx < 32*64*Nn; idx += stride) {
        int n = idx & (Nn-1);
        int rest = idx >> 11;
        int d = rest & 63;
        int bh = rest >> 6;
        int h = bh & 3;
        g_memT[idx] = mem_init[(size_t)n*Dd + h*64 + d];
    }
    for (int idx = tid0; idx < 32*Nn; idx += stride) {
        int n = idx & (Nn-1);
        int bh = idx >> 11;
        int h = bh & 3;
        const float* r = mem_init + (size_t)n*Dd + h*HD;
        float s = 0.f;
#pragma unroll
        for (int d = 0; d < HD; d++) s += r[d]*r[d];
        g_sumsq[idx] = s;
    }
    for (int idx = tid0; idx < Bb*IFc; idx += stride) {
        int b = idx / IFc, c = idx - b*IFc;
        g_ibuf[0][idx] = iface[((size_t)(b*Tt))*IFc + c] + b_if[c];
    }
    for (int idx = tid0; idx < Bb*Dd; idx += stride) {
        g_rv[idx] = 0.f;
        int b = idx / Dd, kk = idx % Dd;
        g_A16[(size_t)(b*Tt)*KTOT + 512 + kk] = __float2half(0.f);
    }
    if (tid0 == 0) { g_cnt = 0u; g_gen = 0u; g_tile = 0u; g_rvflag = 0u; }
}

// ---------------- software grid barrier ----------------
__device__ __forceinline__ void gridbar() {
    __syncthreads();
    if (threadIdx.x == 0) {
        volatile unsigned* vgen = &g_gen;
        __threadfence();
        unsigned gen = *vgen;
        if (atomicAdd(&g_cnt, 1u) == GRIDB - 1u) {
            atomicExch(&g_cnt, 0u);
            __threadfence();
            atomicExch(&g_gen, gen + 1u);
        } else {
            while (*vgen == gen) { }
        }
    }
    __syncthreads();
}

__device__ __forceinline__ float sigmoidf_(float x) { return 1.f/(1.f + expf(-x)); }

// ---------------- persistent scan + fused logits workers ----------------
__global__ void __launch_bounds__(256, 2) k_scan(const float* __restrict__ iface,
                                                 const float* __restrict__ b_if,
                                                 const float* __restrict__ brp,
                                                 const float* __restrict__ bwp,
                                                 const float* __restrict__ bias,
                                                 float* __restrict__ out) {
    __shared__ __align__(16) char smraw[sizeof(ScanSm) > sizeof(GemmSm) ? sizeof(ScanSm) : sizeof(GemmSm)];
    __shared__ int s_tile;
    const int blk = blockIdx.x, tid = threadIdx.x;
    GemmSm* gsm = reinterpret_cast<GemmSm*>(smraw);

    if (blk >= GRIDB) {
        worker_loop(gsm, &s_tile, bias, out);
        return;
    }

    ScanSm& S = *reinterpret_cast<ScanSm*>(smraw);
    const int warp = tid >> 5, lane = tid & 31;

    float beta_r, beta_w;
    {
        float b0 = *brp; b0 = log1pf(expf(b0)); beta_r = fminf(fmaxf(b0, 1.f), 20.f);
        float b1 = *bwp; b1 = log1pf(expf(b1)); beta_w = fminf(fmaxf(b1, 1.f), 20.f);
    }
    const int s_bh = blk >> 2, s_sub = blk & 3;
    const int s_b = s_bh >> 2, s_h = s_bh & 3;
    const int c_b = blk >> 2, c_h = blk & 3;
    const int c_bh = blk;

    for (int t = 0; t < Tt; t++) {
        const float* ib = g_ibuf[t & 1];
        // ---------- SIM ----------
        {
            if (tid < 128) {
                int rw = tid >> 6, d = tid & 63;
                float kx = ib[s_b*IFc + rw*Dd + s_h*64 + d];
                if (rw) S.skw[d] = kx; else S.skr[d] = kx;
                S.kq[tid] = kx*kx;
            }
            __syncthreads();
            if (tid < 2) {
                float s = 0.f;
                for (int d2 = 0; d2 < 64; d2++) s += S.kq[tid*64 + d2];
                S.s_scal[tid] = rsqrtf(s + 1e-8f);
            }
            __syncthreads();
            if (tid < 128) {
                int rw = tid >> 6, d = tid & 63;
                if (rw) S.skw[d] *= S.s_scal[1]; else S.skr[d] *= S.s_scal[0];
            }
            __syncthreads();
            int nbase = s_sub*512;
            const float* mt = g_memT + (size_t)s_bh*64*Nn + nbase;
            float ar0 = 0.f, aw0 = 0.f, ar1 = 0.f, aw1 = 0.f;
#pragma unroll 8
            for (int d = 0; d < 64; d++) {
                float kr = S.skr[d], kw = S.skw[d];
                float m0 = mt[(size_t)d*Nn + tid];
                float m1 = mt[(size_t)d*Nn + tid + 256];
                ar0 += m0*kr; aw0 += m0*kw;
                ar1 += m1*kr; aw1 += m1*kw;
            }
            int n1 = nbase + tid, n2 = n1 + 256;
            float i1 = rsqrtf(g_sumsq[s_bh*Nn + n1] + 1e-8f);
            float i2 = rsqrtf(g_sumsq[s_bh*Nn + n2] + 1e-8f);
            g_sim[(size_t)s_bh*Nn + n1]        = ar0 * i1;
            g_sim[(size_t)s_bh*Nn + n2]        = ar1 * i2;
            g_sim[(size_t)(32 + s_bh)*Nn + n1] = aw0 * i1;
            g_sim[(size_t)(32 + s_bh)*Nn + n2] = aw1 * i2;
        }
        gridbar();   // bar A
        // ---------- phase C (blocks 0..31)  ||  iface t+1 (blocks 32..127) ----------
        if (blk < 32) {
            const int half = warp >> 2;
            const int hw = warp & 3;
            const float beta = half ? beta_w : beta_r;
            const float* s0 = g_sim + ((size_t)(half*32 + blk))*Nn;
            float v[16];
#pragma unroll
            for (int j = 0; j < 16; j++) {
                int n = hw*512 + j*32 + lane;
                v[j] = s0[n];
                S.ssim2[half][n] = v[j];
            }
            if (tid < 2) S.cnt[tid] = 0;
            float wt8[8]; int wi8[8];
#pragma unroll
            for (int k = 0; k < TOPK; k++) {
                float bv = -3.4e38f; int bj = 0;
#pragma unroll
                for (int j = 0; j < 16; j++) if (v[j] > bv) { bv = v[j]; bj = j; }
                int bi = hw*512 + bj*32 + lane;
#pragma unroll
                for (int off = 16; off > 0; off >>= 1) {
                    float ov = __shfl_xor_sync(0xffffffffu, bv, off);
                    int   oi = __shfl_xor_sync(0xffffffffu, bi, off);
                    if (ov > bv || (ov == bv && oi < bi)) { bv = ov; bi = oi; }
                }
                wt8[k] = bv; wi8[k] = bi;
                if (lane == (bi & 31)) v[(bi >> 5) & 15] = -3.4e38f;
            }
            if (lane < 8) { S.wtop[half][hw][lane] = wt8[lane]; S.witop[half][hw][lane] = wi8[lane]; }
            __syncthreads();
            if (hw == 0) {
                float cv = S.wtop[half][lane >> 3][lane & 7];
                int   ci = S.witop[half][lane >> 3][lane & 7];
#pragma unroll
                for (int k = 0; k < TOPK; k++) {
                    float bv = cv; int bi = ci;
#pragma unroll
                    for (int off = 16; off > 0; off >>= 1) {
                        float ov = __shfl_xor_sync(0xffffffffu, bv, off);
                        int   oi = __shfl_xor_sync(0xffffffffu, bi, off);
                        if (ov > bv || (ov == bv && oi < bi)) { bv = ov; bi = oi; }
                    }
                    if (lane == 0) {
                        if (k == 0)       S.scal2[half][0] = bv;
                        if (k == TOPK-1)  S.scal2[half][1] = bv;
                    }
                    if (ci == bi) cv = -3.4e38f;
                }
            }
            __syncthreads();
            float smax = S.scal2[half][0], kth = S.scal2[half][1];
#pragma unroll
            for (int j = 0; j < 16; j++) {
                int n = hw*512 + j*32 + lane;
                float sv = S.ssim2[half][n];
                if (sv >= kth) {
                    int p = atomicAdd(&S.cnt[half], 1);
                    if (p < 48) { S.li2[half][p] = n; S.lw2[half][p] = expf(beta*(sv - smax)); }
                }
            }
            __syncthreads();
            if (tid == 0 || tid == 128) {
                int hh = tid >> 7;
                int ln = S.cnt[hh] < 48 ? S.cnt[hh] : 48;
                for (int a2 = 1; a2 < ln; a2++) {
                    int key = S.li2[hh][a2]; float kw2 = S.lw2[hh][a2]; int c2s = a2 - 1;
                    while (c2s >= 0 && S.li2[hh][c2s] > key) {
                        S.li2[hh][c2s+1] = S.li2[hh][c2s]; S.lw2[hh][c2s+1] = S.lw2[hh][c2s]; c2s--;
                    }
                    S.li2[hh][c2s+1] = key; S.lw2[hh][c2s+1] = kw2;
                }
                float s = 0.f;
                for (int j = 0; j < ln; j++) s += S.lw2[hh][j];
                S.scal2[hh][2] = 1.f / s;
                S.cnt[hh] = ln;
            }
            __syncthreads();
            // rv gather
            {
                int ln0 = S.cnt[0];
                float inv0 = S.scal2[0][2];
                int d = tid & 63, jj = tid >> 6;
                float part = 0.f;
                for (int j = jj; j < ln0; j += 4)
                    part += (S.lw2[0][j]*inv0) * g_mem[((size_t)(c_b*Nn + S.li2[0][j]))*Dd + c_h*64 + d];
                S.rvred[jj][d] = part;
            }
            __syncthreads();
            if (tid < 64) {
                float acc = S.rvred[0][tid] + S.rvred[1][tid] + S.rvred[2][tid] + S.rvred[3][tid];
                g_rv[c_b*Dd + c_h*64 + tid] = acc;
                if (t + 1 < Tt)
                    g_A16[(size_t)(c_b*Tt + t + 1)*KTOT + 512 + c_h*64 + tid] = __float2half(acc);
            }
            __syncthreads();
            if (tid == 0) { __threadfence(); atomicAdd(&g_rvflag, 1u); }
            // mem update
            {
                int ln1 = S.cnt[1];
                float inv1 = S.scal2[1][2];
                float gh   = sigmoidf_(ib[c_b*IFc + 4*Dd + c_h]);
                float er0  = sigmoidf_(ib[c_b*IFc + 3*Dd + c_h*64 + lane]);
                float er1  = sigmoidf_(ib[c_b*IFc + 3*Dd + c_h*64 + lane + 32]);
                float val0 = ib[c_b*IFc + 2*Dd + c_h*64 + lane];
                float val1 = ib[c_b*IFc + 2*Dd + c_h*64 + lane + 32];
                for (int j = warp; j < ln1; j += 8) {
                    int n = S.li2[1][j]; float w = S.lw2[1][j]*inv1;
                    size_t base = ((size_t)(c_b*Nn + n))*Dd + c_h*64;
                    float m0 = g_mem[base + lane], m1 = g_mem[base + lane + 32];
                    float nm0 = m0*(1.f - w*er0) + w*(gh*val0);
                    float nm1 = m1*(1.f - w*er1) + w*(gh*val1);
                    g_mem[base + lane] = nm0;
                    g_mem[base + lane + 32] = nm1;
                    g_memT[((size_t)c_bh*64 + lane)*Nn + n]      = nm0;
                    g_memT[((size_t)c_bh*64 + lane + 32)*Nn + n] = nm1;
                    float ss2 = nm0*nm0 + nm1*nm1;
#pragma unroll
                    for (int off = 16; off > 0; off >>= 1) ss2 += __shfl_down_sync(0xffffffffu, ss2, off);
                    if (lane == 0) g_sumsq[c_bh*Nn + n] = ss2;
                }
            }
        } else if (t + 1 < Tt) {
            if (tid == 0) {
                volatile unsigned* vf = &g_rvflag;
                unsigned target = 32u*(unsigned)(t + 1);
                while (*vf < target) { }
            }
            __syncthreads();
            __threadfence();
            for (int idx = (blk-32)*256 + tid; idx < Bb*IFc; idx += 96*256) {
                int b2 = idx / IFc, c = idx - b2*IFc;
                float acc = iface[((size_t)(b2*Tt + t + 1))*IFc + c] + b_if[c];
                const float4* wp = (const float4*)(g_wifrT + (size_t)c*Dd);
                const float4* rp = (const float4*)(g_rv + b2*Dd);
#pragma unroll 8
                for (int d4 = 0; d4 < Dd/4; d4++) {
                    float4 w4 = wp[d4], r4 = rp[d4];
                    acc += r4.x*w4.x + r4.y*w4.y + r4.z*w4.z + r4.w*w4.w;
                }
                g_ibuf[(t + 1) & 1][idx] = acc;
            }
        }
        gridbar();   // bar B
    }

    worker_loop(gsm, &s_tile, bias, out);
}

static float* addr_of(const void* symbol) {
    void* p = nullptr;
    cudaGetSymbolAddress(&p, symbol);
    return (float*)p;
}

extern "C" void kernel_launch(void* const* d_in, const int* in_sizes, int n_in,
                              void* d_out, int out_size) {
    const int*   input_seq = (const int*)  d_in[0];
    const float* emb       = (const float*)d_in[1];
    const float* pos       = (const float*)d_in[2];
    const float* ln1_g     = (const float*)d_in[3];
    const float* ln1_b     = (const float*)d_in[4];
    const float* ln2_g     = (const float*)d_in[5];
    const float* ln2_b     = (const float*)d_in[6];
    const float* Wq        = (const float*)d_in[7];
    const float* Wk        = (const float*)d_in[8];
    const float* Wv        = (const float*)d_in[9];
    const float* Wo        = (const float*)d_in[10];
    const float* W1        = (const float*)d_in[11];
    const float* b1        = (const float*)d_in[12];
    const float* W2        = (const float*)d_in[13];
    const float* b2        = (const float*)d_in[14];
    const float* lnf_g     = (const float*)d_in[15];
    const float* lnf_b     = (const float*)d_in[16];
    const float* W_if_h    = (const float*)d_in[17];
    const float* W_if_r    = (const float*)d_in[18];
    const float* b_if      = (const float*)d_in[19];
    const float* W_lg_h    = (const float*)d_in[20];
    const float* W_lg_r    = (const float*)d_in[21];
    const float* b_lg      = (const float*)d_in[22];
    const float* beta_read = (const float*)d_in[23];
    const float* beta_write= (const float*)d_in[24];
    const float* mem_init  = (const float*)d_in[25];
    float* out = (float*)d_out;

    static float* p_x = nullptr, *p_h, *p_q, *p_k, *p_v, *p_attno, *p_hf, *p_ffn, *p_iface;
    if (!p_x) {
        p_x      = addr_of(g_x);      p_h     = addr_of(g_h);
        p_q      = addr_of(g_q);      p_k     = addr_of(g_k);
        p_v      = addr_of(g_v);      p_attno = addr_of(g_attno);
        p_hf     = addr_of(g_hf);     p_ffn   = addr_of(g_ffn);
        p_iface  = addr_of(g_iface);
    }

    k_embed<<<2048, 256>>>(input_seq, emb, pos);
    k_convW<<<dim3(Vv/32, KTOT/32), dim3(32,8)>>>(W_lg_h, W_lg_r);
    k_twifr<<<dim3((IFc+31)/32, Dd/32), dim3(32,8)>>>(W_if_r);

    dim3 gE(4, 32);
    dim3 gF(16, 16);
    for (int l = 0; l < Ll; l++) {
        k_ln<<<Mrows, 256>>>(p_x, p_h, ln1_g + l*Ee, ln1_b + l*Ee);
        k_gemm<64,4><<<gE, 256>>>(p_h, Wq + (size_t)l*Ee*Ee, nullptr, nullptr, p_q, Mrows, Ee, Ee, 0);
        k_gemm<64,4><<<gE, 256>>>(p_h, Wk + (size_t)l*Ee*Ee, nullptr, nullptr, p_k, Mrows, Ee, Ee, 0);
        k_gemm<64,4><<<gE, 256>>>(p_h, Wv + (size_t)l*Ee*Ee, nullptr, nullptr, p_v, Mrows, Ee, Ee, 0);
        k_attn<<<dim3(Tt, HA, Bb), 256>>>();
        k_gemm<64,4><<<gE, 256>>>(p_attno, Wo + (size_t)l*Ee*Ee, nullptr, p_x, p_x, Mrows, Ee, Ee, 0);
        k_ln<<<Mrows, 256>>>(p_x, p_h, ln2_g + l*Ee, ln2_b + l*Ee);
        k_gemm<128,8><<<gF, 256>>>(p_h, W1 + (size_t)l*Ee*Ff, b1 + l*Ff, nullptr, p_ffn, Mrows, Ee, Ff, 1);
        k_gemm<64,4><<<gE, 256>>>(p_ffn, W2 + (size_t)l*Ff*Ee, b2 + l*Ee, p_x, p_x, Mrows, Ff, Ee, 0);
    }

    k_ln<<<Mrows, 256>>>(p_x, p_hf, lnf_g, lnf_b);
    k_gemm<128,8><<<dim3(9, 16), 256>>>(p_hf, W_if_h, nullptr, nullptr, p_iface, Mrows, Ee, IFc, 0);

    k_convA1<<<2048, 256>>>();

    k_scan_init<<<2048, 256>>>(mem_init, p_iface, b_if);
    k_scan<<<GRIDB + WORKERS, 256>>>(p_iface, b_if, beta_read, beta_write, b_lg, out);
}

// round 15
// speedup vs baseline: 1.9214x; 1.0234x over previous
#include <cuda_runtime.h>
#include <cuda_bf16.h>
#include <cuda_fp16.h>
#include <math.h>
#include <stdint.h>

// ---------------- problem constants ----------------
#define Vv 32000
#define Ee 512
#define Ff 2048
#define Dd 256
#define Nn 2048
#define Ll 2
#define Bb 8
#define Tt 256
#define HM 4
#define TOPK 8
#define HA 8
#define HD 64
#define DH 64
#define IFc 1028
#define Mrows (Bb*Tt)
#define GRIDB 128
#define WORKERS 168
#define KTOT 768
#define NT_P1 4000
#define NT_TOT 8000

// ---------------- scratch ----------------
__device__ float g_x[Mrows*Ee];
__device__ float g_h[Mrows*Ee];
__device__ float g_q[Mrows*Ee];
__device__ float g_k[Mrows*Ee];
__device__ float g_v[Mrows*Ee];
__device__ float g_attno[Mrows*Ee];
__device__ float g_hf[Mrows*Ee];
__device__ float g_ffn[Mrows*Ff];
__device__ float g_iface[Mrows*IFc];
__device__ float g_mem[Bb*Nn*Dd];
__device__ float g_memT[32*64*Nn];
__device__ float g_sumsq[32*Nn];
__device__ float g_rv[Bb*Dd];
__device__ float g_ibuf[2][Bb*IFc];
__device__ float g_sim[2*Bb*HM*Nn];
__device__ float g_wifrT[IFc*Dd];
__device__ __half g_W16[(size_t)Vv*KTOT];   // [n][k] fp16
__device__ __half g_A16[(size_t)Mrows*KTOT]; // [m][hf(512) | rv(256)] fp16
__device__ unsigned g_cnt;
__device__ unsigned g_gen;
__device__ unsigned g_tile;
__device__ unsigned g_rvflag;

// ---------------- embedding ----------------
__global__ void k_embed(const int* __restrict__ seq, const float* __restrict__ emb,
                        const float* __restrict__ pos) {
    int stride = gridDim.x * blockDim.x;
    for (int idx = blockIdx.x*blockDim.x + threadIdx.x; idx < Mrows*Ee; idx += stride) {
        int e  = idx % Ee;
        int bt = idx / Ee;
        int t  = bt % Tt;
        g_x[idx] = emb[(size_t)seq[bt]*Ee + e] + pos[t*Ee + e];
    }
}

// ---------------- layernorm ----------------
__global__ void k_ln(const float* __restrict__ in, float* __restrict__ outp,
                     const float* __restrict__ g, const float* __restrict__ b) {
    int row = blockIdx.x;
    int tid = threadIdx.x;
    const float* x = in + (size_t)row*Ee;
    __shared__ float red[256];
    float v0 = x[tid], v1 = x[tid+256];
    red[tid] = v0 + v1;
    __syncthreads();
    for (int s = 128; s > 0; s >>= 1) { if (tid < s) red[tid] += red[tid+s]; __syncthreads(); }
    float mean = red[0] * (1.f/Ee);
    __syncthreads();
    float d0 = v0 - mean, d1 = v1 - mean;
    red[tid] = d0*d0 + d1*d1;
    __syncthreads();
    for (int s = 128; s > 0; s >>= 1) { if (tid < s) red[tid] += red[tid+s]; __syncthreads(); }
    float inv = rsqrtf(red[0] * (1.f/Ee) + 1e-5f);
    outp[(size_t)row*Ee + tid]       = d0*inv*g[tid]     + b[tid];
    outp[(size_t)row*Ee + tid + 256] = d1*inv*g[tid+256] + b[tid+256];
}

__device__ __forceinline__ float geluf_(float xx) {
    float tt = tanhf(0.7978845608028654f * (xx + 0.044715f*xx*xx*xx));
    return 0.5f * xx * (1.f + tt);
}

// ---------------- SIMT GEMM (transformer-sized, fp32) ----------------
template<int BM, int TM>
__global__ void __launch_bounds__(256) k_gemm(const float* __restrict__ A, const float* __restrict__ W,
                       const float* __restrict__ bias, const float* __restrict__ res,
                       float* __restrict__ C, int M, int K, int N, int act) {
    __shared__ float As[2][16][BM];
    __shared__ float Bs[2][16][128];
    const int tid = threadIdx.x;
    const int bm = blockIdx.y * BM, bn = blockIdx.x * 128;
    const int tx = tid & 15, ty = tid >> 4;
    constexpr int AV = BM/64;
    float4 aR[AV], bR[2];
    float acc[TM][8];
#pragma unroll
    for (int i = 0; i < TM; i++)
#pragma unroll
        for (int j = 0; j < 8; j++) acc[i][j] = 0.f;

    auto ldg = [&](int k0) {
#pragma unroll
        for (int v = 0; v < AV; v++) {
            int i = tid + v*256;
            int row = i >> 2, cg = i & 3;
            aR[v] = *(const float4*)(A + (size_t)(bm+row)*K + k0 + cg*4);
        }
#pragma unroll
        for (int v = 0; v < 2; v++) {
            int i = tid + v*256;
            int row = i >> 5, cg = i & 31;
            int col = bn + cg*4;
            if (col < N) bR[v] = *(const float4*)(W + (size_t)(k0+row)*N + col);
            else { bR[v].x = bR[v].y = bR[v].z = bR[v].w = 0.f; }
        }
    };
    auto sts = [&](int buf) {
#pragma unroll
        for (int v = 0; v < AV; v++) {
            int i = tid + v*256;
            int row = i >> 2, cg = i & 3;
            As[buf][cg*4+0][row] = aR[v].x; As[buf][cg*4+1][row] = aR[v].y;
            As[buf][cg*4+2][row] = aR[v].z; As[buf][cg*4+3][row] = aR[v].w;
        }
#pragma unroll
        for (int v = 0; v < 2; v++) {
            int i = tid + v*256;
            int row = i >> 5, cg = i & 31;
            *(float4*)&Bs[buf][row][cg*4] = bR[v];
        }
    };
    auto comp = [&](int buf) {
#pragma unroll
        for (int kk = 0; kk < 16; kk++) {
            float a[TM], bfr[8];
#pragma unroll
            for (int v = 0; v < TM/4; v++)
                *(float4*)&a[v*4] = *(const float4*)&As[buf][kk][ty*TM + v*4];
            *(float4*)&bfr[0] = *(const float4*)&Bs[buf][kk][tx*8];
            *(float4*)&bfr[4] = *(const float4*)&Bs[buf][kk][tx*8+4];
#pragma unroll
            for (int i = 0; i < TM; i++)
#pragma unroll
                for (int j = 0; j < 8; j++) acc[i][j] += a[i]*bfr[j];
        }
    };

    ldg(0); sts(0); __syncthreads();
    int cur = 0;
    for (int k0 = 16; k0 < K; k0 += 16) {
        ldg(k0);
        comp(cur);
        sts(cur^1);
        __syncthreads();
        cur ^= 1;
    }
    comp(cur);

#pragma unroll
    for (int i = 0; i < TM; i++) {
        int row = bm + ty*TM + i;
#pragma unroll
        for (int jv = 0; jv < 2; jv++) {
            int col = bn + tx*8 + jv*4;
            if (col < N) {
                float4 v4;
                v4.x = acc[i][jv*4+0]; v4.y = acc[i][jv*4+1];
                v4.z = acc[i][jv*4+2]; v4.w = acc[i][jv*4+3];
                if (bias) { v4.x += bias[col]; v4.y += bias[col+1]; v4.z += bias[col+2]; v4.w += bias[col+3]; }
                if (act == 1) { v4.x = geluf_(v4.x); v4.y = geluf_(v4.y); v4.z = geluf_(v4.z); v4.w = geluf_(v4.w); }
                if (res) {
                    float4 r4 = *(const float4*)&res[(size_t)row*N + col];
                    v4.x += r4.x; v4.y += r4.y; v4.z += r4.z; v4.w += r4.w;
                }
                *(float4*)&C[(size_t)row*N + col] = v4;
            }
        }
    }
}

// ---------------- attention ----------------
__global__ void k_attn() {
    int t = blockIdx.x, hh = blockIdx.y, b = blockIdx.z;
    int tid = threadIdx.x;
    __shared__ float sq[64];
    __shared__ float ss[256];
    __shared__ float red[256];
    const float* qrow = g_q + ((size_t)(b*Tt + t))*Ee + hh*DH;
    if (tid < 64) sq[tid] = qrow[tid];
    __syncthreads();
    float lmax = -3.4e38f;
    for (int j = tid; j <= t; j += 256) {
        const float* krow = g_k + ((size_t)(b*Tt + j))*Ee + hh*DH;
        float d = 0.f;
#pragma unroll
        for (int e = 0; e < 64; e++) d += sq[e]*krow[e];
        d *= 0.125f;
        ss[j] = d;
        lmax = fmaxf(lmax, d);
    }
    red[tid] = lmax;
    __syncthreads();
    for (int s = 128; s > 0; s >>= 1) { if (tid < s) red[tid] = fmaxf(red[tid], red[tid+s]); __syncthreads(); }
    float mx = red[0];
    __syncthreads();
    float lsum = 0.f;
    for (int j = tid; j <= t; j += 256) { float p = expf(ss[j]-mx); ss[j] = p; lsum += p; }
    red[tid] = lsum;
    __syncthreads();
    for (int s = 128; s > 0; s >>= 1) { if (tid < s) red[tid] += red[tid+s]; __syncthreads(); }
    float inv = 1.f / red[0];
    __syncthreads();
    if (tid < 64) {
        float acc = 0.f;
        for (int j = 0; j <= t; j++)
            acc += ss[j] * g_v[((size_t)(b*Tt + j))*Ee + hh*DH + tid];
        g_attno[((size_t)(b*Tt + t))*Ee + hh*DH + tid] = acc * inv;
    }
}

// ---------------- W_lg fp16 convert + transpose ----------------
__global__ void k_convW(const float* __restrict__ Wh, const float* __restrict__ Wr) {
    __shared__ float tile[32][33];
    int nt = blockIdx.x*32, kt = blockIdx.y*32;
    int tx = threadIdx.x, ty = threadIdx.y;
#pragma unroll
    for (int r = 0; r < 32; r += 8) {
        int k = kt + ty + r, n = nt + tx;
        float v = (k < 512) ? Wh[(size_t)k*Vv + n] : Wr[(size_t)(k-512)*Vv + n];
        tile[ty+r][tx] = v;
    }
    __syncthreads();
#pragma unroll
    for (int r = 0; r < 32; r += 8) {
        int n = nt + ty + r, k = kt + tx;
        g_W16[(size_t)n*KTOT + k] = __float2half(tile[tx][ty+r]);
    }
}

// ---------------- A fp16 convert (h_f part) ----------------
__global__ void k_convA1() {
    int stride = gridDim.x*blockDim.x;
    for (int idx = blockIdx.x*blockDim.x + threadIdx.x; idx < Mrows*512; idx += stride) {
        int m = idx >> 9, k = idx & 511;
        g_A16[(size_t)m*KTOT + k] = __float2half(g_hf[(size_t)m*Ee + k]);
    }
}

// ---------------- transpose W_if_r ----------------
__global__ void k_twifr(const float* __restrict__ W) {
    __shared__ float tile[32][33];
    int ct = blockIdx.x*32, dt = blockIdx.y*32;
    int tx = threadIdx.x, ty = threadIdx.y;
#pragma unroll
    for (int r = 0; r < 32; r += 8) {
        int d = dt + ty + r, c = ct + tx;
        tile[ty+r][tx] = (c < IFc) ? W[(size_t)d*IFc + c] : 0.f;
    }
    __syncthreads();
#pragma unroll
    for (int r = 0; r < 32; r += 8) {
        int c = ct + ty + r, d = dt + tx;
        if (c < IFc) g_wifrT[(size_t)c*Dd + d] = tile[tx][ty+r];
    }
}

// ---------------- fp16 mma.sync + ldmatrix ----------------
__device__ __forceinline__ void mma16816(float* c, const uint32_t* a, const uint32_t* b) {
    asm volatile(
        "mma.sync.aligned.m16n8k16.row.col.f32.f16.f16.f32 "
        "{%0,%1,%2,%3}, {%4,%5,%6,%7}, {%8,%9}, {%0,%1,%2,%3};"
        : "+f"(c[0]), "+f"(c[1]), "+f"(c[2]), "+f"(c[3])
        : "r"(a[0]), "r"(a[1]), "r"(a[2]), "r"(a[3]), "r"(b[0]), "r"(b[1]));
}
__device__ __forceinline__ void ldmat_x4(uint32_t* r, uint32_t saddr) {
    asm volatile("ldmatrix.sync.aligned.m8n8.x4.shared.b16 {%0,%1,%2,%3}, [%4];"
        : "=r"(r[0]), "=r"(r[1]), "=r"(r[2]), "=r"(r[3]) : "r"(saddr));
}

// ---------------- shared layouts ----------------
struct GemmSm {
    __half As[2][128][40];
    __half Bs[2][128][40];
};
struct ScanSm {
    float ssim2[2][Nn];
    float skr[64], skw[64];
    float kq[128];
    float wtop[2][4][8]; int witop[2][4][8];
    float lw2[2][48]; int li2[2][48];
    int cnt[2];
    int wcnt[2][4];
    float scal2[2][4];
    float s_scal[4];
    float rvred[4][64];
};

// ---------------- one 128x128 logits tile (single fp16 pass) ----------------
__device__ void lgemm_tile(GemmSm* sm, int m0, int n0, int kb, int nchunks,
                           const float* __restrict__ bias, float* __restrict__ C, int accum) {
    const int tid = threadIdx.x, wid = tid >> 5, lane = tid & 31;
    const int wm = (wid & 1) * 64, wn = (wid >> 1) * 32;

    const uint32_t aBase0 = (uint32_t)__cvta_generic_to_shared(&sm->As[0][0][0]);
    const uint32_t bBase0 = (uint32_t)__cvta_generic_to_shared(&sm->Bs[0][0][0]);
    const uint32_t aLane = (uint32_t)((wm + (lane & 15)) * 80 + ((lane >> 4) * 8) * 2);
    const uint32_t bLane = (uint32_t)((wn + ((lane >> 4) & 1) * 8 + (lane & 7)) * 80
                                      + (((lane >> 3) & 1) * 8) * 2);

    float acc[4][4][4];
#pragma unroll
    for (int mi = 0; mi < 4; mi++)
#pragma unroll
        for (int ni = 0; ni < 4; ni++)
#pragma unroll
            for (int j = 0; j < 4; j++) acc[mi][ni][j] = 0.f;

    uint4 aR[2], bR[2];
    auto ldg = [&](int c) {
        int kin = kb + c*32;
#pragma unroll
        for (int v = 0; v < 2; v++) {
            int i = tid + v*256;
            int row = i >> 2, cg = i & 3;
            aR[v] = *(const uint4*)(g_A16 + (size_t)(m0+row)*KTOT + kin + cg*8);
            bR[v] = *(const uint4*)(g_W16 + (size_t)(n0+row)*KTOT + kin + cg*8);
        }
    };
    auto sts = [&](int buf) {
#pragma unroll
        for (int v = 0; v < 2; v++) {
            int i = tid + v*256;
            int row = i >> 2, cg = i & 3;
            *(uint4*)&sm->As[buf][row][cg*8] = aR[v];
            *(uint4*)&sm->Bs[buf][row][cg*8] = bR[v];
        }
    };
    auto comp = [&](int buf) {
        uint32_t aB = aBase0 + (uint32_t)buf*10240u + aLane;
        uint32_t bB = bBase0 + (uint32_t)buf*10240u + bLane;
#pragma unroll
        for (int kt = 0; kt < 32; kt += 16) {
            uint32_t af[4][4], bq[2][4];
#pragma unroll
            for (int mi = 0; mi < 4; mi++)
                ldmat_x4(af[mi], aB + (uint32_t)(mi*16*80) + (uint32_t)(kt*2));
#pragma unroll
            for (int p = 0; p < 2; p++)
                ldmat_x4(bq[p], bB + (uint32_t)(p*16*80) + (uint32_t)(kt*2));
#pragma unroll
            for (int mi = 0; mi < 4; mi++)
#pragma unroll
                for (int ni = 0; ni < 4; ni++)
                    mma16816(acc[mi][ni], af[mi], &bq[ni >> 1][(ni & 1) * 2]);
        }
    };

    ldg(0); sts(0); __syncthreads();
    int cur = 0;
    for (int c = 1; c < nchunks; c++) {
        ldg(c);
        comp(cur);
        sts(cur^1);
        __syncthreads();
        cur ^= 1;
    }
    comp(cur);

    const int r = lane >> 2, c2 = (lane & 3) * 2;
#pragma unroll
    for (int mi = 0; mi < 4; mi++) {
        int row0 = m0 + wm + mi*16 + r;
#pragma unroll
        for (int ni = 0; ni < 4; ni++) {
            int col = n0 + wn + ni*8 + c2;
            float2 v0, v1;
            if (accum) {
                float2 o0 = *(const float2*)&C[(size_t)row0*Vv + col];
                float2 o1 = *(const float2*)&C[(size_t)(row0+8)*Vv + col];
                v0.x = acc[mi][ni][0] + o0.x; v0.y = acc[mi][ni][1] + o0.y;
                v1.x = acc[mi][ni][2] + o1.x; v1.y = acc[mi][ni][3] + o1.y;
            } else {
                v0.x = acc[mi][ni][0] + bias[col]; v0.y = acc[mi][ni][1] + bias[col+1];
                v1.x = acc[mi][ni][2] + bias[col]; v1.y = acc[mi][ni][3] + bias[col+1];
            }
            *(float2*)&C[(size_t)row0*Vv + col]     = v0;
            *(float2*)&C[(size_t)(row0+8)*Vv + col] = v1;
        }
    }
}

// ---------------- worker loop ----------------
__device__ void worker_loop(GemmSm* gsm, volatile int* s_tile,
                            const float* __restrict__ bias, float* __restrict__ out) {
    const int tid = threadIdx.x;
    volatile unsigned* vgen = &g_gen;
    for (;;) {
        if (tid == 0) *s_tile = (int)atomicAdd(&g_tile, 1u);
        __syncthreads();
        int tl = *s_tile;
        if (tl >= NT_TOT) break;
        if (tl < NT_P1) {
            lgemm_tile(gsm, (tl/250)*128, (tl%250)*128, 0, 16, bias, out, 0);
        } else {
            int id = tl - NT_P1;
            int grp = id / 250, nt = id % 250;
            int mt = (grp < 8) ? (2*grp) : (2*(grp-8)+1);
            unsigned need = (mt & 1) ? 510u : 254u;
            if (tid == 0) { while (*vgen < need) __nanosleep(128); }
            __syncthreads();
            __threadfence();
            lgemm_tile(gsm, mt*128, nt*128, 512, 8, nullptr, out, 1);
        }
        __syncthreads();
    }
}

// ---------------- scan init ----------------
__global__ void k_scan_init(const float* __restrict__ mem_init, const float* __restrict__ iface,
                            const float* __restrict__ b_if) {
    int stride = gridDim.x*blockDim.x;
    int tid0 = blockIdx.x*blockDim.x + threadIdx.x;
    for (int idx = tid0; idx < Bb*Nn*Dd; idx += stride)
        g_mem[idx] = mem_init[idx % (Nn*Dd)];
    for (int idx = tid0; idx < 32*64*Nn; idx += stride) {
        int n = idx & (Nn-1);
        int rest = idx >> 11;
        int d = rest & 63;
        int bh = rest >> 6;
        int h = bh & 3;
        g_memT[idx] = mem_init[(size_t)n*Dd + h*64 + d];
    }
    for (int idx = tid0; idx < 32*Nn; idx += stride) {
        int n = idx & (Nn-1);
        int bh = idx >> 11;
        int h = bh & 3;
        const float* r = mem_init + (size_t)n*Dd + h*HD;
        float s = 0.f;
#pragma unroll
        for (int d = 0; d < HD; d++) s += r[d]*r[d];
        g_sumsq[idx] = s;
    }
    for (int idx = tid0; idx < Bb*IFc; idx += stride) {
        int b = idx / IFc, c = idx - b*IFc;
        g_ibuf[0][idx] = iface[((size_t)(b*Tt))*IFc + c] + b_if[c];
    }
    for (int idx = tid0; idx < Bb*Dd; idx += stride) {
        g_rv[idx] = 0.f;
        int b = idx / Dd, kk = idx % Dd;
        g_A16[(size_t)(b*Tt)*KTOT + 512 + kk] = __float2half(0.f);
    }
    if (tid0 == 0) { g_cnt = 0u; g_gen = 0u; g_tile = 0u; g_rvflag = 0u; }
}

// ---------------- software grid barrier ----------------
__device__ __forceinline__ void gridbar() {
    __syncthreads();
    if (threadIdx.x == 0) {
        volatile unsigned* vgen = &g_gen;
        __threadfence();
        unsigned gen = *vgen;
        if (atomicAdd(&g_cnt, 1u) == GRIDB - 1u) {
            atomicExch(&g_cnt, 0u);
            __threadfence();
            atomicExch(&g_gen, gen + 1u);
        } else {
            while (*vgen == gen) { }
        }
    }
    __syncthreads();
}

__device__ __forceinline__ float sigmoidf_(float x) { return 1.f/(1.f + expf(-x)); }

// ---------------- persistent scan + fused logits workers ----------------
__global__ void __launch_bounds__(256, 2) k_scan(const float* __restrict__ iface,
                                                 const float* __restrict__ b_if,
                                                 const float* __restrict__ brp,
                                                 const float* __restrict__ bwp,
                                                 const float* __restrict__ bias,
                                                 float* __restrict__ out) {
    __shared__ __align__(16) char smraw[sizeof(ScanSm) > sizeof(GemmSm) ? sizeof(ScanSm) : sizeof(GemmSm)];
    __shared__ int s_tile;
    const int blk = blockIdx.x, tid = threadIdx.x;
    GemmSm* gsm = reinterpret_cast<GemmSm*>(smraw);

    if (blk >= GRIDB) {
        worker_loop(gsm, &s_tile, bias, out);
        return;
    }

    ScanSm& S = *reinterpret_cast<ScanSm*>(smraw);
    const int warp = tid >> 5, lane = tid & 31;

    float beta_r, beta_w;
    {
        float b0 = *brp; b0 = log1pf(expf(b0)); beta_r = fminf(fmaxf(b0, 1.f), 20.f);
        float b1 = *bwp; b1 = log1pf(expf(b1)); beta_w = fminf(fmaxf(b1, 1.f), 20.f);
    }
    const int s_bh = blk >> 2, s_sub = blk & 3;
    const int s_b = s_bh >> 2, s_h = s_bh & 3;
    const int c_b = blk >> 2, c_h = blk & 3;
    const int c_bh = blk;

    for (int t = 0; t < Tt; t++) {
        const float* ib = g_ibuf[t & 1];
        // ---------- SIM ----------
        {
            if (tid < 128) {
                int rw = tid >> 6, d = tid & 63;
                float kx = ib[s_b*IFc + rw*Dd + s_h*64 + d];
                if (rw) S.skw[d] = kx; else S.skr[d] = kx;
                S.kq[tid] = kx*kx;
            }
            __syncthreads();
            if (tid < 2) {
                float s = 0.f;
                for (int d2 = 0; d2 < 64; d2++) s += S.kq[tid*64 + d2];
                S.s_scal[tid] = rsqrtf(s + 1e-8f);
            }
            __syncthreads();
            if (tid < 128) {
                int rw = tid >> 6, d = tid & 63;
                if (rw) S.skw[d] *= S.s_scal[1]; else S.skr[d] *= S.s_scal[0];
            }
            __syncthreads();
            int nbase = s_sub*512;
            const float* mt = g_memT + (size_t)s_bh*64*Nn + nbase;
            float ar0 = 0.f, aw0 = 0.f, ar1 = 0.f, aw1 = 0.f;
#pragma unroll 8
            for (int d = 0; d < 64; d++) {
                float kr = S.skr[d], kw = S.skw[d];
                float m0 = mt[(size_t)d*Nn + tid];
                float m1 = mt[(size_t)d*Nn + tid + 256];
                ar0 += m0*kr; aw0 += m0*kw;
                ar1 += m1*kr; aw1 += m1*kw;
            }
            int n1 = nbase + tid, n2 = n1 + 256;
            float i1 = rsqrtf(g_sumsq[s_bh*Nn + n1] + 1e-8f);
            float i2 = rsqrtf(g_sumsq[s_bh*Nn + n2] + 1e-8f);
            g_sim[(size_t)s_bh*Nn + n1]        = ar0 * i1;
            g_sim[(size_t)s_bh*Nn + n2]        = ar1 * i2;
            g_sim[(size_t)(32 + s_bh)*Nn + n1] = aw0 * i1;
            g_sim[(size_t)(32 + s_bh)*Nn + n2] = aw1 * i2;
        }
        gridbar();   // bar A
        // ---------- phase C (blocks 0..31)  ||  iface t+1 (blocks 32..127) ----------
        if (blk < 32) {
            const int half = warp >> 2;
            const int hw = warp & 3;
            const float beta = half ? beta_w : beta_r;
            const float* s0 = g_sim + ((size_t)(half*32 + blk))*Nn;
            float v[16];
#pragma unroll
            for (int j = 0; j < 16; j++) {
                int n = hw*512 + j*32 + lane;
                v[j] = s0[n];
                S.ssim2[half][n] = v[j];
            }
            float wt8[8]; int wi8[8];
#pragma unroll
            for (int k = 0; k < TOPK; k++) {
                float bv = -3.4e38f; int bj = 0;
#pragma unroll
                for (int j = 0; j < 16; j++) if (v[j] > bv) { bv = v[j]; bj = j; }
                int bi = hw*512 + bj*32 + lane;
#pragma unroll
                for (int off = 16; off > 0; off >>= 1) {
                    float ov = __shfl_xor_sync(0xffffffffu, bv, off);
                    int   oi = __shfl_xor_sync(0xffffffffu, bi, off);
                    if (ov > bv || (ov == bv && oi < bi)) { bv = ov; bi = oi; }
                }
                wt8[k] = bv; wi8[k] = bi;
                if (lane == (bi & 31)) v[(bi >> 5) & 15] = -3.4e38f;
            }
            if (lane < 8) { S.wtop[half][hw][lane] = wt8[lane]; S.witop[half][hw][lane] = wi8[lane]; }
            __syncthreads();
            if (hw == 0) {
                float cv = S.wtop[half][lane >> 3][lane & 7];
                int   ci = S.witop[half][lane >> 3][lane & 7];
#pragma unroll
                for (int k = 0; k < TOPK; k++) {
                    float bv = cv; int bi = ci;
#pragma unroll
                    for (int off = 16; off > 0; off >>= 1) {
                        float ov = __shfl_xor_sync(0xffffffffu, bv, off);
                        int   oi = __shfl_xor_sync(0xffffffffu, bi, off);
                        if (ov > bv || (ov == bv && oi < bi)) { bv = ov; bi = oi; }
                    }
                    if (lane == 0) {
                        if (k == 0)       S.scal2[half][0] = bv;
                        if (k == TOPK-1)  S.scal2[half][1] = bv;
                    }
                    if (ci == bi) cv = -3.4e38f;
                }
            }
            __syncthreads();
            float smax = S.scal2[half][0], kth = S.scal2[half][1];
            // ---- deterministic ballot-based survivor collection (n-ascending) ----
            unsigned masks[16];
            int mycnt = 0;
#pragma unroll
            for (int j = 0; j < 16; j++) {
                int n = hw*512 + j*32 + lane;
                unsigned m = __ballot_sync(0xffffffffu, S.ssim2[half][n] >= kth);
                masks[j] = m;
                mycnt += __popc(m);
            }
            if (lane == 0) S.wcnt[half][hw] = mycnt;
            __syncthreads();
            int base = 0;
            for (int w2 = 0; w2 < hw; w2++) base += S.wcnt[half][w2];
            int off2 = base;
#pragma unroll
            for (int j = 0; j < 16; j++) {
                unsigned m = masks[j];
                int n = hw*512 + j*32 + lane;
                if ((m >> lane) & 1u) {
                    int pos = off2 + __popc(m & ((1u << lane) - 1u));
                    if (pos < 48) {
                        S.li2[half][pos] = n;
                        S.lw2[half][pos] = expf(beta*(S.ssim2[half][n] - smax));
                    }
                }
                off2 += __popc(m);
            }
            __syncthreads();
            if (tid == 0 || tid == 128) {
                int hh = tid >> 7;
                int tot = S.wcnt[hh][0] + S.wcnt[hh][1] + S.wcnt[hh][2] + S.wcnt[hh][3];
                int ln = tot < 48 ? tot : 48;
                float s = 0.f;
                for (int j = 0; j < ln; j++) s += S.lw2[hh][j];
                S.scal2[hh][2] = 1.f / s;
                S.cnt[hh] = ln;
            }
            __syncthreads();
            // rv gather
            {
                int ln0 = S.cnt[0];
                float inv0 = S.scal2[0][2];
                int d = tid & 63, jj = tid >> 6;
                float part = 0.f;
                for (int j = jj; j < ln0; j += 4)
                    part += (S.lw2[0][j]*inv0) * g_mem[((size_t)(c_b*Nn + S.li2[0][j]))*Dd + c_h*64 + d];
                S.rvred[jj][d] = part;
            }
            __syncthreads();
            if (tid < 64) {
                float acc = S.rvred[0][tid] + S.rvred[1][tid] + S.rvred[2][tid] + S.rvred[3][tid];
                g_rv[c_b*Dd + c_h*64 + tid] = acc;
                if (t + 1 < Tt)
                    g_A16[(size_t)(c_b*Tt + t + 1)*KTOT + 512 + c_h*64 + tid] = __float2half(acc);
            }
            __syncthreads();
            if (tid == 0) { __threadfence(); atomicAdd(&g_rvflag, 1u); }
            // mem update
            {
                int ln1 = S.cnt[1];
                float inv1 = S.scal2[1][2];
                float gh   = sigmoidf_(ib[c_b*IFc + 4*Dd + c_h]);
                float er0  = sigmoidf_(ib[c_b*IFc + 3*Dd + c_h*64 + lane]);
                float er1  = sigmoidf_(ib[c_b*IFc + 3*Dd + c_h*64 + lane + 32]);
                float val0 = ib[c_b*IFc + 2*Dd + c_h*64 + lane];
                float val1 = ib[c_b*IFc + 2*Dd + c_h*64 + lane + 32];
                for (int j = warp; j < ln1; j += 8) {
                    int n = S.li2[1][j]; float w = S.lw2[1][j]*inv1;
                    size_t base2 = ((size_t)(c_b*Nn + n))*Dd + c_h*64;
                    float m0 = g_mem[base2 + lane], m1 = g_mem[base2 + lane + 32];
                    float nm0 = m0*(1.f - w*er0) + w*(gh*val0);
                    float nm1 = m1*(1.f - w*er1) + w*(gh*val1);
                    g_mem[base2 + lane] = nm0;
                    g_mem[base2 + lane + 32] = nm1;
                    g_memT[((size_t)c_bh*64 + lane)*Nn + n]      = nm0;
                    g_memT[((size_t)c_bh*64 + lane + 32)*Nn + n] = nm1;
                    float ss2 = nm0*nm0 + nm1*nm1;
#pragma unroll
                    for (int off = 16; off > 0; off >>= 1) ss2 += __shfl_down_sync(0xffffffffu, ss2, off);
                    if (lane == 0) g_sumsq[c_bh*Nn + n] = ss2;
                }
            }
        } else if (t + 1 < Tt) {
            if (tid == 0) {
                volatile unsigned* vf = &g_rvflag;
                unsigned target = 32u*(unsigned)(t + 1);
                while (*vf < target) { }
            }
            __syncthreads();
            __threadfence();
            for (int idx = (blk-32)*256 + tid; idx < Bb*IFc; idx += 96*256) {
                int b2 = idx / IFc, c = idx - b2*IFc;
                float acc = iface[((size_t)(b2*Tt + t + 1))*IFc + c] + b_if[c];
                const float4* wp = (const float4*)(g_wifrT + (size_t)c*Dd);
                const float4* rp = (const float4*)(g_rv + b2*Dd);
#pragma unroll 8
                for (int d4 = 0; d4 < Dd/4; d4++) {
                    float4 w4 = wp[d4], r4 = rp[d4];
                    acc += r4.x*w4.x + r4.y*w4.y + r4.z*w4.z + r4.w*w4.w;
                }
                g_ibuf[(t + 1) & 1][idx] = acc;
            }
        }
        gridbar();   // bar B
    }

    worker_loop(gsm, &s_tile, bias, out);
}

static float* addr_of(const void* symbol) {
    void* p = nullptr;
    cudaGetSymbolAddress(&p, symbol);
    return (float*)p;
}

extern "C" void kernel_launch(void* const* d_in, const int* in_sizes, int n_in,
                              void* d_out, int out_size) {
    const int*   input_seq = (const int*)  d_in[0];
    const float* emb       = (const float*)d_in[1];
    const float* pos       = (const float*)d_in[2];
    const float* ln1_g     = (const float*)d_in[3];
    const float* ln1_b     = (const float*)d_in[4];
    const float* ln2_g     = (const float*)d_in[5];
    const float* ln2_b     = (const float*)d_in[6];
    const float* Wq        = (const float*)d_in[7];
    const float* Wk        = (const float*)d_in[8];
    const float* Wv        = (const float*)d_in[9];
    const float* Wo        = (const float*)d_in[10];
    const float* W1        = (const float*)d_in[11];
    const float* b1        = (const float*)d_in[12];
    const float* W2        = (const float*)d_in[13];
    const float* b2        = (const float*)d_in[14];
    const float* lnf_g     = (const float*)d_in[15];
    const float* lnf_b     = (const float*)d_in[16];
    const float* W_if_h    = (const float*)d_in[17];
    const float* W_if_r    = (const float*)d_in[18];
    const float* b_if      = (const float*)d_in[19];
    const float* W_lg_h    = (const float*)d_in[20];
    const float* W_lg_r    = (const float*)d_in[21];
    const float* b_lg      = (const float*)d_in[22];
    const float* beta_read = (const float*)d_in[23];
    const float* beta_write= (const float*)d_in[24];
    const float* mem_init  = (const float*)d_in[25];
    float* out = (float*)d_out;

    static float* p_x = nullptr, *p_h, *p_q, *p_k, *p_v, *p_attno, *p_hf, *p_ffn, *p_iface;
    if (!p_x) {
        p_x      = addr_of(g_x);      p_h     = addr_of(g_h);
        p_q      = addr_of(g_q);      p_k     = addr_of(g_k);
        p_v      = addr_of(g_v);      p_attno = addr_of(g_attno);
        p_hf     = addr_of(g_hf);     p_ffn   = addr_of(g_ffn);
        p_iface  = addr_of(g_iface);
    }

    k_embed<<<2048, 256>>>(input_seq, emb, pos);
    k_convW<<<dim3(Vv/32, KTOT/32), dim3(32,8)>>>(W_lg_h, W_lg_r);
    k_twifr<<<dim3((IFc+31)/32, Dd/32), dim3(32,8)>>>(W_if_r);

    dim3 gE(4, 32);
    dim3 gF(16, 16);
    for (int l = 0; l < Ll; l++) {
        k_ln<<<Mrows, 256>>>(p_x, p_h, ln1_g + l*Ee, ln1_b + l*Ee);
        k_gemm<64,4><<<gE, 256>>>(p_h, Wq + (size_t)l*Ee*Ee, nullptr, nullptr, p_q, Mrows, Ee, Ee, 0);
        k_gemm<64,4><<<gE, 256>>>(p_h, Wk + (size_t)l*Ee*Ee, nullptr, nullptr, p_k, Mrows, Ee, Ee, 0);
        k_gemm<64,4><<<gE, 256>>>(p_h, Wv + (size_t)l*Ee*Ee, nullptr, nullptr, p_v, Mrows, Ee, Ee, 0);
        k_attn<<<dim3(Tt, HA, Bb), 256>>>();
        k_gemm<64,4><<<gE, 256>>>(p_attno, Wo + (size_t)l*Ee*Ee, nullptr, p_x, p_x, Mrows, Ee, Ee, 0);
        k_ln<<<Mrows, 256>>>(p_x, p_h, ln2_g + l*Ee, ln2_b + l*Ee);
        k_gemm<128,8><<<gF, 256>>>(p_h, W1 + (size_t)l*Ee*Ff, b1 + l*Ff, nullptr, p_ffn, Mrows, Ee, Ff, 1);
        k_gemm<64,4><<<gE, 256>>>(p_ffn, W2 + (size_t)l*Ff*Ee, b2 + l*Ee, p_x, p_x, Mrows, Ff, Ee, 0);
    }

    k_ln<<<Mrows, 256>>>(p_x, p_hf, lnf_g, lnf_b);
    k_gemm<128,8><<<dim3(9, 16), 256>>>(p_hf, W_if_h, nullptr, nullptr, p_iface, Mrows, Ee, IFc, 0);

    k_convA1<<<2048, 256>>>();

    k_scan_init<<<2048, 256>>>(mem_init, p_iface, b_if);
    k_scan<<<GRIDB + WORKERS, 256>>>(p_iface, b_if, beta_read, beta_write, b_lg, out);
}